// round 10
// baseline (speedup 1.0000x reference)
#include <cuda_runtime.h>
#include <cuda_bf16.h>
#include <math.h>
#include <stdint.h>

#define B   2
#define T   1024
#define H   2048
#define NH  32
#define NKV 8
#define HD  64
#define IM  8192
#define M   (B*T)

typedef __nv_bfloat16  bf16;
typedef __nv_bfloat162 bf162;

// ---------------- scratch (device globals; no allocation) ----------------
__device__ __align__(16) float g_q  [M * NH * HD];
__device__ __align__(16) float g_k  [M * NKV * HD];
__device__ __align__(16) float g_v  [M * NKV * HD];
__device__ __align__(16) float g_h2 [M * H];
// bf16 hi/lo split weights
__device__ __align__(16) bf16 s_wq_h[NH*HD*H],  s_wq_l[NH*HD*H];
__device__ __align__(16) bf16 s_wk_h[NKV*HD*H], s_wk_l[NKV*HD*H];
__device__ __align__(16) bf16 s_wv_h[NKV*HD*H], s_wv_l[NKV*HD*H];
__device__ __align__(16) bf16 s_wo_h[H*NH*HD],  s_wo_l[H*NH*HD];
__device__ __align__(16) bf16 s_wg_h[(size_t)IM*H], s_wg_l[(size_t)IM*H];
__device__ __align__(16) bf16 s_wu_h[(size_t)IM*H], s_wu_l[(size_t)IM*H];
__device__ __align__(16) bf16 s_wd_h[(size_t)H*IM], s_wd_l[(size_t)H*IM];
// bf16 hi/lo split activations
__device__ __align__(16) bf16 s_xn_h [M*H],        s_xn_l [M*H];
__device__ __align__(16) bf16 s_at_h [M*NH*HD],    s_at_l [M*NH*HD];
__device__ __align__(16) bf16 s_xn2_h[M*H],        s_xn2_l[M*H];
__device__ __align__(16) bf16 s_g_h  [(size_t)M*IM], s_g_l[(size_t)M*IM];
// bf16 hi/lo split q/k/v for attention (head-major; v transposed)
__device__ __align__(16) bf16 s_q_h [M*NH*HD],  s_q_l [M*NH*HD];
__device__ __align__(16) bf16 s_k_h [M*NKV*HD], s_k_l [M*NKV*HD];
__device__ __align__(16) bf16 s_vt_h[M*NKV*HD], s_vt_l[M*NKV*HD];

// ---------------- helpers ----------------
__device__ __forceinline__ uint32_t smem_u32(const void* p) {
    uint32_t a;
    asm("{ .reg .u64 t; cvta.to.shared.u64 t, %1; cvt.u32.u64 %0, t; }"
        : "=r"(a) : "l"(p));
    return a;
}
__device__ __forceinline__ void cp_async16(uint32_t dst, const void* src) {
    asm volatile("cp.async.cg.shared.global [%0], [%1], 16;"
                 :: "r"(dst), "l"(src));
}
#define CP_ASYNC_COMMIT() asm volatile("cp.async.commit_group;" ::: "memory")
#define CP_ASYNC_WAIT0()  asm volatile("cp.async.wait_group 0;" ::: "memory")
#define CP_ASYNC_WAIT1()  asm volatile("cp.async.wait_group 1;" ::: "memory")

#define LDMX4(r0, r1, r2, r3, addr) \
    asm volatile("ldmatrix.sync.aligned.m8n8.x4.shared.b16 {%0,%1,%2,%3}, [%4];" \
        : "=r"(r0), "=r"(r1), "=r"(r2), "=r"(r3) : "r"(addr))

__device__ __forceinline__ void mma_bf16(float& c0, float& c1, float& c2, float& c3,
                                         uint32_t a0, uint32_t a1, uint32_t a2, uint32_t a3,
                                         uint32_t b0, uint32_t b1) {
    asm volatile(
        "mma.sync.aligned.m16n8k16.row.col.f32.bf16.bf16.f32 "
        "{%0,%1,%2,%3}, {%4,%5,%6,%7}, {%8,%9}, {%0,%1,%2,%3};"
        : "+f"(c0), "+f"(c1), "+f"(c2), "+f"(c3)
        : "r"(a0), "r"(a1), "r"(a2), "r"(a3), "r"(b0), "r"(b1));
}

// split-store helpers (fp32 -> hi/lo bf16)
__device__ __forceinline__ void split_store4(bf16* __restrict__ h, bf16* __restrict__ l,
                                             size_t idx, float x, float y, float z, float w) {
    bf162 h0 = __floats2bfloat162_rn(x, y);
    bf162 h1 = __floats2bfloat162_rn(z, w);
    float lx = x - __bfloat162float(__low2bfloat16(h0));
    float ly = y - __bfloat162float(__high2bfloat16(h0));
    float lz = z - __bfloat162float(__low2bfloat16(h1));
    float lw = w - __bfloat162float(__high2bfloat16(h1));
    *(bf162*)(h + idx)     = h0;
    *(bf162*)(h + idx + 2) = h1;
    *(bf162*)(l + idx)     = __floats2bfloat162_rn(lx, ly);
    *(bf162*)(l + idx + 2) = __floats2bfloat162_rn(lz, lw);
}
__device__ __forceinline__ void split_store2(bf16* __restrict__ h, bf16* __restrict__ l,
                                             size_t idx, float x, float y) {
    bf162 h0 = __floats2bfloat162_rn(x, y);
    float lx = x - __bfloat162float(__low2bfloat16(h0));
    float ly = y - __bfloat162float(__high2bfloat16(h0));
    *(bf162*)(h + idx) = h0;
    *(bf162*)(l + idx) = __floats2bfloat162_rn(lx, ly);
}
__device__ __forceinline__ void pack_split2(float x, float y, uint32_t& hi, uint32_t& lo) {
    bf162 h0 = __floats2bfloat162_rn(x, y);
    float lx = x - __bfloat162float(__low2bfloat16(h0));
    float ly = y - __bfloat162float(__high2bfloat16(h0));
    bf162 l0 = __floats2bfloat162_rn(lx, ly);
    hi = *(uint32_t*)&h0;
    lo = *(uint32_t*)&l0;
}

// ---------------- weight split kernel ----------------
__global__ void split_kernel(const float* __restrict__ x,
                             bf16* __restrict__ h, bf16* __restrict__ l, int n4) {
    int i = blockIdx.x * blockDim.x + threadIdx.x;
    if (i >= n4) return;
    float4 v = ((const float4*)x)[i];
    split_store4(h, l, (size_t)i * 4, v.x, v.y, v.z, v.w);
}

// ---------------- 3xBF16 GEMM core (ldmatrix, 3-stage cp.async) -------------
#define RPAD 20
#define ATILE_U (64 * RPAD)                       // 1280
#define BTILE_U (128 * RPAD)                      // 2560
#define STAGE_U (2 * ATILE_U + 2 * BTILE_U)       // 7680 uints
#define GEMM_DSMEM (3 * STAGE_U * 4)              // 92160 B

__device__ __forceinline__ void gemm_tile(float* sm,
                                          const bf16* __restrict__ Ah, const bf16* __restrict__ Al,
                                          const bf16* __restrict__ Bh, const bf16* __restrict__ Bl,
                                          const float* __restrict__ res, float* __restrict__ C,
                                          int N, int K, int bm, int bn) {
    const uint32_t smem_base = smem_u32(sm);
    const int tid  = threadIdx.x;
    const int wid  = tid >> 5;
    const int lane = tid & 31;
    const int wm   = wid >> 2;
    const int wn   = wid & 3;
    const int gid  = lane >> 2;
    const int tig  = lane & 3;
    const int KC   = K >> 5;
    const int lrow = tid >> 2;
    const int lch  = tid & 3;

    const int sub  = lane >> 3;
    const int r8   = lane & 7;
    const int arow = ((sub & 1) << 3) + r8;
    const int akof = (sub >> 1) << 4;
    const int brow = ((sub >> 1) << 3) + r8;
    const int bkof = (sub & 1) << 4;

    uint32_t aaddr[2][2], baddr[2][2];
    #pragma unroll
    for (int mt = 0; mt < 2; mt++) {
        uint32_t base = smem_base + (uint32_t)((wm * 32 + mt * 16 + arow) * RPAD) * 4 + akof;
        aaddr[mt][0] = base;
        aaddr[mt][1] = base + ATILE_U * 4;
    }
    #pragma unroll
    for (int np = 0; np < 2; np++) {
        uint32_t base = smem_base + (uint32_t)(2 * ATILE_U + (wn * 32 + np * 16 + brow) * RPAD) * 4 + bkof;
        baddr[np][0] = base;
        baddr[np][1] = base + BTILE_U * 4;
    }

    float acc[2][4][4];
    #pragma unroll
    for (int i = 0; i < 2; i++)
        #pragma unroll
        for (int j = 0; j < 4; j++)
            #pragma unroll
            for (int k = 0; k < 4; k++) acc[i][j][k] = 0.f;

    auto issue_load = [&](int c, int buf) {
        const int k0 = c << 5;
        uint32_t st = smem_base + buf * (STAGE_U * 4);
        cp_async16(st + (lrow * RPAD + lch * 4) * 4,
                   Ah + (size_t)(bm + lrow) * K + k0 + lch * 8);
        cp_async16(st + (ATILE_U + lrow * RPAD + lch * 4) * 4,
                   Al + (size_t)(bm + lrow) * K + k0 + lch * 8);
        #pragma unroll
        for (int it = 0; it < 2; it++) {
            int br = it * 64 + lrow;
            cp_async16(st + (2 * ATILE_U + br * RPAD + lch * 4) * 4,
                       Bh + (size_t)(bn + br) * K + k0 + lch * 8);
            cp_async16(st + (2 * ATILE_U + BTILE_U + br * RPAD + lch * 4) * 4,
                       Bl + (size_t)(bn + br) * K + k0 + lch * 8);
        }
        CP_ASYNC_COMMIT();
    };

    issue_load(0, 0);
    issue_load(1, 1);

    for (int c = 0; c < KC; c++) {
        const int buf = c % 3;
        if (c + 2 < KC) {
            CP_ASYNC_WAIT1();
            __syncthreads();
            issue_load(c + 2, (c + 2) % 3);
        } else {
            CP_ASYNC_WAIT0();
            __syncthreads();
        }

        const uint32_t boff = (uint32_t)buf * (STAGE_U * 4);

        #pragma unroll
        for (int ks = 0; ks < 2; ks++) {
            const uint32_t koff = boff + ks * 32;
            uint32_t ahf[2][4], alf[2][4], bhf[4][2], blf[4][2];
            #pragma unroll
            for (int mt = 0; mt < 2; mt++) {
                LDMX4(ahf[mt][0], ahf[mt][1], ahf[mt][2], ahf[mt][3], aaddr[mt][0] + koff);
                LDMX4(alf[mt][0], alf[mt][1], alf[mt][2], alf[mt][3], aaddr[mt][1] + koff);
            }
            #pragma unroll
            for (int np = 0; np < 2; np++) {
                LDMX4(bhf[2*np][0], bhf[2*np][1], bhf[2*np+1][0], bhf[2*np+1][1],
                      baddr[np][0] + koff);
                LDMX4(blf[2*np][0], blf[2*np][1], blf[2*np+1][0], blf[2*np+1][1],
                      baddr[np][1] + koff);
            }
            #pragma unroll
            for (int mt = 0; mt < 2; mt++)
                #pragma unroll
                for (int nt = 0; nt < 4; nt++) {
                    mma_bf16(acc[mt][nt][0], acc[mt][nt][1],
                             acc[mt][nt][2], acc[mt][nt][3],
                             ahf[mt][0], ahf[mt][1], ahf[mt][2], ahf[mt][3],
                             blf[nt][0], blf[nt][1]);
                    mma_bf16(acc[mt][nt][0], acc[mt][nt][1],
                             acc[mt][nt][2], acc[mt][nt][3],
                             alf[mt][0], alf[mt][1], alf[mt][2], alf[mt][3],
                             bhf[nt][0], bhf[nt][1]);
                    mma_bf16(acc[mt][nt][0], acc[mt][nt][1],
                             acc[mt][nt][2], acc[mt][nt][3],
                             ahf[mt][0], ahf[mt][1], ahf[mt][2], ahf[mt][3],
                             bhf[nt][0], bhf[nt][1]);
                }
        }
        __syncthreads();
    }

    #pragma unroll
    for (int mt = 0; mt < 2; mt++) {
        int r0 = bm + wm * 32 + mt * 16 + gid;
        #pragma unroll
        for (int nt = 0; nt < 4; nt++) {
            int col = bn + wn * 32 + nt * 8 + tig * 2;
            size_t o0 = (size_t)r0 * N + col;
            size_t o1 = (size_t)(r0 + 8) * N + col;
            float2 v0 = make_float2(acc[mt][nt][0], acc[mt][nt][1]);
            float2 v1 = make_float2(acc[mt][nt][2], acc[mt][nt][3]);
            if (res) {
                float2 r0v = *(const float2*)(res + o0);
                float2 r1v = *(const float2*)(res + o1);
                v0.x += r0v.x; v0.y += r0v.y;
                v1.x += r1v.x; v1.y += r1v.y;
            }
            *(float2*)(C + o0) = v0;
            *(float2*)(C + o1) = v1;
        }
    }
}

// ---- generic GEMM (o-proj, down-proj); grid: x = M-block (fast), y = N-block
__global__ void __launch_bounds__(256, 2)
gemm_mma_kernel(const bf16* __restrict__ Ah, const bf16* __restrict__ Al,
                const bf16* __restrict__ Bh, const bf16* __restrict__ Bl,
                const float* __restrict__ res, float* __restrict__ C,
                int N, int K) {
    extern __shared__ float sm[];
    gemm_tile(sm, Ah, Al, Bh, Bl, res, C, N, K, blockIdx.x * 64, blockIdx.y * 128);
}

// ---- fused QKV; grid: x = M-block, y = ct (0..15 Q, 16..19 K, 20..23 V)
__global__ void __launch_bounds__(256, 2)
gemm_qkv_kernel(const bf16* __restrict__ Ah, const bf16* __restrict__ Al,
                float* __restrict__ q, float* __restrict__ k, float* __restrict__ v) {
    extern __shared__ float sm[];
    const int ct = blockIdx.y;
    const bf16 *Bh, *Bl; float* C; int N, bn;
    if (ct < 16)      { Bh = s_wq_h; Bl = s_wq_l; C = q; N = NH  * HD; bn = ct * 128; }
    else if (ct < 20) { Bh = s_wk_h; Bl = s_wk_l; C = k; N = NKV * HD; bn = (ct - 16) * 128; }
    else              { Bh = s_wv_h; Bl = s_wv_l; C = v; N = NKV * HD; bn = (ct - 20) * 128; }
    gemm_tile(sm, Ah, Al, Bh, Bl, nullptr, C, N, H, blockIdx.x * 64, bn);
}

// ---- fused gate/up + SwiGLU: CTA computes 64x64 gate AND up tiles, applies
//      silu(g)*u in epilogue, split-stores bf16. grid: x = M-block, y = N64-block
__global__ void __launch_bounds__(256, 2)
gemm_gu_silu_kernel(const bf16* __restrict__ Ah, const bf16* __restrict__ Al,
                    bf16* __restrict__ gh, bf16* __restrict__ gl) {
    extern __shared__ float sm[];
    const uint32_t smem_base = smem_u32(sm);
    const int bm = blockIdx.x * 64;
    const int bn = blockIdx.y * 64;
    const int K  = H, KC = K >> 5;

    const int tid  = threadIdx.x;
    const int wid  = tid >> 5;
    const int lane = tid & 31;
    const int wsel = wid >> 2;           // 0 = gate, 1 = up
    const int wq   = wid & 3;
    const int wm   = wq >> 1;            // 0..1 -> 32-row band
    const int wn   = wq & 1;             // 0..1 -> 32-col band
    const int gid  = lane >> 2;
    const int tig  = lane & 3;
    const int lrow = tid >> 2;           // 0..63
    const int lch  = tid & 3;

    const int sub  = lane >> 3;
    const int r8   = lane & 7;
    const int arow = ((sub & 1) << 3) + r8;
    const int akof = (sub >> 1) << 4;
    const int brow = ((sub >> 1) << 3) + r8;
    const int bkof = (sub & 1) << 4;

    // stage layout: tiles of 1280 uints: A_h, A_l, Bg_h, Bg_l, Bu_h, Bu_l
    uint32_t aaddr[2][2], baddr[2][2];
    #pragma unroll
    for (int mt = 0; mt < 2; mt++) {
        uint32_t base = smem_base + (uint32_t)((wm * 32 + mt * 16 + arow) * RPAD) * 4 + akof;
        aaddr[mt][0] = base;
        aaddr[mt][1] = base + ATILE_U * 4;
    }
    #pragma unroll
    for (int np = 0; np < 2; np++) {
        uint32_t base = smem_base +
            (uint32_t)((2 + 2 * wsel) * ATILE_U + (wn * 32 + np * 16 + brow) * RPAD) * 4 + bkof;
        baddr[np][0] = base;
        baddr[np][1] = base + ATILE_U * 4;
    }

    const bf16* Bgh = s_wg_h; const bf16* Bgl = s_wg_l;
    const bf16* Buh = s_wu_h; const bf16* Bul = s_wu_l;

    float acc[2][4][4];
    #pragma unroll
    for (int i = 0; i < 2; i++)
        #pragma unroll
        for (int j = 0; j < 4; j++)
            #pragma unroll
            for (int k = 0; k < 4; k++) acc[i][j][k] = 0.f;

    auto issue_load = [&](int c, int buf) {
        const int k0 = c << 5;
        uint32_t st = smem_base + buf * (STAGE_U * 4);
        cp_async16(st + (0 * ATILE_U + lrow * RPAD + lch * 4) * 4,
                   Ah + (size_t)(bm + lrow) * K + k0 + lch * 8);
        cp_async16(st + (1 * ATILE_U + lrow * RPAD + lch * 4) * 4,
                   Al + (size_t)(bm + lrow) * K + k0 + lch * 8);
        cp_async16(st + (2 * ATILE_U + lrow * RPAD + lch * 4) * 4,
                   Bgh + (size_t)(bn + lrow) * K + k0 + lch * 8);
        cp_async16(st + (3 * ATILE_U + lrow * RPAD + lch * 4) * 4,
                   Bgl + (size_t)(bn + lrow) * K + k0 + lch * 8);
        cp_async16(st + (4 * ATILE_U + lrow * RPAD + lch * 4) * 4,
                   Buh + (size_t)(bn + lrow) * K + k0 + lch * 8);
        cp_async16(st + (5 * ATILE_U + lrow * RPAD + lch * 4) * 4,
                   Bul + (size_t)(bn + lrow) * K + k0 + lch * 8);
        CP_ASYNC_COMMIT();
    };

    issue_load(0, 0);
    issue_load(1, 1);

    for (int c = 0; c < KC; c++) {
        const int buf = c % 3;
        if (c + 2 < KC) {
            CP_ASYNC_WAIT1();
            __syncthreads();
            issue_load(c + 2, (c + 2) % 3);
        } else {
            CP_ASYNC_WAIT0();
            __syncthreads();
        }
        const uint32_t boff = (uint32_t)buf * (STAGE_U * 4);

        #pragma unroll
        for (int ks = 0; ks < 2; ks++) {
            const uint32_t koff = boff + ks * 32;
            uint32_t ahf[2][4], alf[2][4], bhf[4][2], blf[4][2];
            #pragma unroll
            for (int mt = 0; mt < 2; mt++) {
                LDMX4(ahf[mt][0], ahf[mt][1], ahf[mt][2], ahf[mt][3], aaddr[mt][0] + koff);
                LDMX4(alf[mt][0], alf[mt][1], alf[mt][2], alf[mt][3], aaddr[mt][1] + koff);
            }
            #pragma unroll
            for (int np = 0; np < 2; np++) {
                LDMX4(bhf[2*np][0], bhf[2*np][1], bhf[2*np+1][0], bhf[2*np+1][1],
                      baddr[np][0] + koff);
                LDMX4(blf[2*np][0], blf[2*np][1], blf[2*np+1][0], blf[2*np+1][1],
                      baddr[np][1] + koff);
            }
            #pragma unroll
            for (int mt = 0; mt < 2; mt++)
                #pragma unroll
                for (int nt = 0; nt < 4; nt++) {
                    mma_bf16(acc[mt][nt][0], acc[mt][nt][1],
                             acc[mt][nt][2], acc[mt][nt][3],
                             ahf[mt][0], ahf[mt][1], ahf[mt][2], ahf[mt][3],
                             blf[nt][0], blf[nt][1]);
                    mma_bf16(acc[mt][nt][0], acc[mt][nt][1],
                             acc[mt][nt][2], acc[mt][nt][3],
                             alf[mt][0], alf[mt][1], alf[mt][2], alf[mt][3],
                             bhf[nt][0], bhf[nt][1]);
                    mma_bf16(acc[mt][nt][0], acc[mt][nt][1],
                             acc[mt][nt][2], acc[mt][nt][3],
                             ahf[mt][0], ahf[mt][1], ahf[mt][2], ahf[mt][3],
                             bhf[nt][0], bhf[nt][1]);
                }
        }
        __syncthreads();
    }

    // ---- epilogue: exchange gate accs via smem, apply silu*up, split-store --
    float (*sx)[66] = (float (*)[66])sm;
    __syncthreads();
    if (wsel == 0) {
        #pragma unroll
        for (int mt = 0; mt < 2; mt++) {
            int lr = wm * 32 + mt * 16 + gid;
            #pragma unroll
            for (int nt = 0; nt < 4; nt++) {
                int lc = wn * 32 + nt * 8 + tig * 2;
                sx[lr][lc]     = acc[mt][nt][0];
                sx[lr][lc + 1] = acc[mt][nt][1];
                sx[lr + 8][lc]     = acc[mt][nt][2];
                sx[lr + 8][lc + 1] = acc[mt][nt][3];
            }
        }
    }
    __syncthreads();
    if (wsel == 1) {
        #pragma unroll
        for (int mt = 0; mt < 2; mt++) {
            int lr = wm * 32 + mt * 16 + gid;
            #pragma unroll
            for (int nt = 0; nt < 4; nt++) {
                int lc = wn * 32 + nt * 8 + tig * 2;
                float g0 = sx[lr][lc],     g1 = sx[lr][lc + 1];
                float g2 = sx[lr + 8][lc], g3 = sx[lr + 8][lc + 1];
                float r0 = g0 / (1.f + __expf(-g0)) * acc[mt][nt][0];
                float r1 = g1 / (1.f + __expf(-g1)) * acc[mt][nt][1];
                float r2 = g2 / (1.f + __expf(-g2)) * acc[mt][nt][2];
                float r3 = g3 / (1.f + __expf(-g3)) * acc[mt][nt][3];
                size_t o0 = (size_t)(bm + lr)     * IM + bn + lc;
                size_t o1 = (size_t)(bm + lr + 8) * IM + bn + lc;
                split_store2(gh, gl, o0, r0, r1);
                split_store2(gh, gl, o1, r2, r3);
            }
        }
    }
}

// ---------------- RMSNorm with split output ----------------
__global__ void rmsnorm_split_kernel(const float* __restrict__ x,
                                     const float* __restrict__ w,
                                     bf16* __restrict__ oh, bf16* __restrict__ ol) {
    int row = blockIdx.x;
    const float* xr = x + (size_t)row * H;
    float ss = 0.f;
    for (int i = threadIdx.x; i < H / 4; i += blockDim.x) {
        float4 v = ((const float4*)xr)[i];
        ss += v.x * v.x + v.y * v.y + v.z * v.z + v.w * v.w;
    }
    __shared__ float red[32];
    #pragma unroll
    for (int o = 16; o; o >>= 1) ss += __shfl_xor_sync(0xffffffffu, ss, o);
    if ((threadIdx.x & 31) == 0) red[threadIdx.x >> 5] = ss;
    __syncthreads();
    if (threadIdx.x < 32) {
        float v = (threadIdx.x < (blockDim.x >> 5)) ? red[threadIdx.x] : 0.f;
        #pragma unroll
        for (int o = 16; o; o >>= 1) v += __shfl_xor_sync(0xffffffffu, v, o);
        if (threadIdx.x == 0) red[0] = v;
    }
    __syncthreads();
    float r = rsqrtf(red[0] / (float)H + 1e-6f);
    for (int i = threadIdx.x; i < H / 4; i += blockDim.x) {
        float4 v = ((const float4*)xr)[i];
        float4 wv = ((const float4*)w)[i];
        split_store4(oh, ol, (size_t)row * H + 4 * i,
                     v.x * r * wv.x, v.y * r * wv.y, v.z * r * wv.z, v.w * r * wv.w);
    }
}

// ---------------- RoPE (writes bf16 hi/lo, head-major) ----------------
__global__ void rope_q_kernel(const float* __restrict__ q,
                              const float* __restrict__ cosp,
                              const float* __restrict__ sinp,
                              const int* __restrict__ pos,
                              bf16* __restrict__ qh, bf16* __restrict__ ql) {
    int idx = blockIdx.x * blockDim.x + threadIdx.x;
    int d2 = idx & 31;
    int h  = (idx >> 5) & (NH - 1);
    int bt = idx >> 10;
    int t  = bt & (T - 1);
    int b  = bt >> 10;
    int p  = pos[bt];
    float c = cosp[p * 32 + d2], s = sinp[p * 32 + d2];
    size_t base = (size_t)bt * (NH * HD) + h * HD + 2 * d2;
    float x1 = q[base], x2 = q[base + 1];
    float r1 = x1 * c - x2 * s;
    float r2 = x1 * s + x2 * c;
    size_t ob = ((size_t)(b * NH + h) * T + t) * HD + 2 * d2;
    split_store2(qh, ql, ob, r1, r2);
}

__global__ void rope_kv_kernel(const float* __restrict__ k, const float* __restrict__ v,
                               const float* __restrict__ cosp,
                               const float* __restrict__ sinp,
                               const int* __restrict__ pos,
                               float* __restrict__ outk, float* __restrict__ outv,
                               bf16* __restrict__ kh, bf16* __restrict__ kl,
                               bf16* __restrict__ vth, bf16* __restrict__ vtl) {
    int idx = blockIdx.x * blockDim.x + threadIdx.x;
    int d2 = idx & 31;
    int h  = (idx >> 5) & (NKV - 1);
    int bt = idx >> 8;
    int t  = bt & (T - 1);
    int b  = bt >> 10;
    int p  = pos[bt];
    float c = cosp[p * 32 + d2], s = sinp[p * 32 + d2];
    size_t base = (size_t)bt * (NKV * HD) + h * HD + 2 * d2;
    float x1 = k[base], x2 = k[base + 1];
    float r1 = x1 * c - x2 * s;
    float r2 = x1 * s + x2 * c;
    size_t ob = ((size_t)(b * NKV + h) * T + t) * HD + 2 * d2;
    outk[ob] = r1;       outk[ob + 1] = r2;
    split_store2(kh, kl, ob, r1, r2);
    float v1 = v[base], v2 = v[base + 1];
    outv[ob] = v1;       outv[ob + 1] = v2;
    size_t vb = ((size_t)(b * NKV + h) * HD + 2 * d2) * T + t;
    bf16 vh1 = __float2bfloat16(v1);
    bf16 vh2 = __float2bfloat16(v2);
    vth[vb]     = vh1; vtl[vb]     = __float2bfloat16(v1 - __bfloat162float(vh1));
    vth[vb + T] = vh2; vtl[vb + T] = __float2bfloat16(v2 - __bfloat162float(vh2));
}

// ---------------- Flash attention (3xBF16 mma, 64 q rows/CTA, 4 warps) ------
#define AT_RPAD 36
#define AT_TILE_U (64 * AT_RPAD)
#define ATTN_DSMEM (6 * AT_TILE_U * 4)

__global__ void __launch_bounds__(128)
attn_kernel(const bf16* __restrict__ Qh_g, const bf16* __restrict__ Ql_g,
            const bf16* __restrict__ Kh_g, const bf16* __restrict__ Kl_g,
            const bf16* __restrict__ Vth_g, const bf16* __restrict__ Vtl_g,
            bf16* __restrict__ Oh, bf16* __restrict__ Ol) {
    extern __shared__ uint32_t smu[];
    const int qt = blockIdx.x, h = blockIdx.y, b = blockIdx.z;
    const int kvh = h >> 2;
    const int tid = threadIdx.x, wid = tid >> 5, lane = tid & 31;
    const int gid = lane >> 2, tig = lane & 3;
    const int sub = lane >> 3, r8 = lane & 7;
    const int arow = ((sub & 1) << 3) + r8;
    const int akof = (sub >> 1) << 4;
    const int brow = ((sub >> 1) << 3) + r8;
    const int bkof = (sub & 1) << 4;

    const uint32_t smem_base = smem_u32(smu);
    const uint32_t Qh_s = smem_base;
    const uint32_t Ql_s = Qh_s + AT_TILE_U * 4;
    const uint32_t Kh_s = Ql_s + AT_TILE_U * 4;
    const uint32_t Kl_s = Kh_s + AT_TILE_U * 4;
    const uint32_t Vh_s = Kl_s + AT_TILE_U * 4;
    const uint32_t Vl_s = Vh_s + AT_TILE_U * 4;

    {
        const bf16* qh = Qh_g + ((size_t)(b * NH + h) * T + qt * 64) * HD;
        const bf16* ql = Ql_g + ((size_t)(b * NH + h) * T + qt * 64) * HD;
        #pragma unroll
        for (int it = 0; it < 4; it++) {
            int idx = tid + it * 128;
            int row = idx >> 3, ch = idx & 7;
            cp_async16(Qh_s + (row * AT_RPAD + ch * 4) * 4, qh + (size_t)row * HD + ch * 8);
            cp_async16(Ql_s + (row * AT_RPAD + ch * 4) * 4, ql + (size_t)row * HD + ch * 8);
        }
        CP_ASYNC_COMMIT();
        CP_ASYNC_WAIT0();
        __syncthreads();
    }
    uint32_t qfh[4][4], qfl[4][4];
    {
        uint32_t qa = (uint32_t)((wid * 16 + arow) * AT_RPAD) * 4 + akof;
        #pragma unroll
        for (int ks = 0; ks < 4; ks++) {
            LDMX4(qfh[ks][0], qfh[ks][1], qfh[ks][2], qfh[ks][3], Qh_s + qa + ks * 32);
            LDMX4(qfl[ks][0], qfl[ks][1], qfl[ks][2], qfl[ks][3], Ql_s + qa + ks * 32);
        }
    }

    float oacc[8][4];
    #pragma unroll
    for (int i = 0; i < 8; i++)
        #pragma unroll
        for (int j = 0; j < 4; j++) oacc[i][j] = 0.f;
    float rm0 = -1e30f, rm1 = -1e30f, rs0 = 0.f, rs1 = 0.f;

    for (int kt = 0; kt <= qt; kt++) {
        __syncthreads();
        {
            const bf16* kh  = Kh_g  + ((size_t)(b * NKV + kvh) * T + kt * 64) * HD;
            const bf16* kl  = Kl_g  + ((size_t)(b * NKV + kvh) * T + kt * 64) * HD;
            const bf16* vth = Vth_g + (size_t)(b * NKV + kvh) * HD * T;
            const bf16* vtl = Vtl_g + (size_t)(b * NKV + kvh) * HD * T;
            #pragma unroll
            for (int it = 0; it < 4; it++) {
                int idx = tid + it * 128;
                int row = idx >> 3, ch = idx & 7;
                uint32_t soff = (row * AT_RPAD + ch * 4) * 4;
                cp_async16(Kh_s + soff, kh + (size_t)row * HD + ch * 8);
                cp_async16(Kl_s + soff, kl + (size_t)row * HD + ch * 8);
                cp_async16(Vh_s + soff, vth + (size_t)row * T + kt * 64 + ch * 8);
                cp_async16(Vl_s + soff, vtl + (size_t)row * T + kt * 64 + ch * 8);
            }
            CP_ASYNC_COMMIT();
            CP_ASYNC_WAIT0();
            __syncthreads();
        }

        float sacc[8][4];
        #pragma unroll
        for (int i = 0; i < 8; i++)
            #pragma unroll
            for (int j = 0; j < 4; j++) sacc[i][j] = 0.f;

        #pragma unroll
        for (int ks = 0; ks < 4; ks++) {
            uint32_t kfh[8][2], kfl[8][2];
            #pragma unroll
            for (int np = 0; np < 4; np++) {
                uint32_t ka = (uint32_t)((np * 16 + brow) * AT_RPAD) * 4 + bkof + ks * 32;
                LDMX4(kfh[2*np][0], kfh[2*np][1], kfh[2*np+1][0], kfh[2*np+1][1], Kh_s + ka);
                LDMX4(kfl[2*np][0], kfl[2*np][1], kfl[2*np+1][0], kfl[2*np+1][1], Kl_s + ka);
            }
            #pragma unroll
            for (int nt = 0; nt < 8; nt++) {
                mma_bf16(sacc[nt][0], sacc[nt][1], sacc[nt][2], sacc[nt][3],
                         qfh[ks][0], qfh[ks][1], qfh[ks][2], qfh[ks][3],
                         kfl[nt][0], kfl[nt][1]);
                mma_bf16(sacc[nt][0], sacc[nt][1], sacc[nt][2], sacc[nt][3],
                         qfl[ks][0], qfl[ks][1], qfl[ks][2], qfl[ks][3],
                         kfh[nt][0], kfh[nt][1]);
                mma_bf16(sacc[nt][0], sacc[nt][1], sacc[nt][2], sacc[nt][3],
                         qfh[ks][0], qfh[ks][1], qfh[ks][2], qfh[ks][3],
                         kfh[nt][0], kfh[nt][1]);
            }
        }

        const float scale = 0.125f;
        if (kt == qt) {
            #pragma unroll
            for (int nt = 0; nt < 8; nt++)
                #pragma unroll
                for (int c = 0; c < 4; c++) {
                    int col = 8 * nt + 2 * tig + (c & 1);
                    int row = wid * 16 + gid + ((c >> 1) << 3);
                    sacc[nt][c] = (col <= row) ? sacc[nt][c] * scale : -1e30f;
                }
        } else {
            #pragma unroll
            for (int nt = 0; nt < 8; nt++)
                #pragma unroll
                for (int c = 0; c < 4; c++) sacc[nt][c] *= scale;
        }

        float mx0 = -1e30f, mx1 = -1e30f;
        #pragma unroll
        for (int nt = 0; nt < 8; nt++) {
            mx0 = fmaxf(mx0, fmaxf(sacc[nt][0], sacc[nt][1]));
            mx1 = fmaxf(mx1, fmaxf(sacc[nt][2], sacc[nt][3]));
        }
        mx0 = fmaxf(mx0, __shfl_xor_sync(0xffffffffu, mx0, 1));
        mx0 = fmaxf(mx0, __shfl_xor_sync(0xffffffffu, mx0, 2));
        mx1 = fmaxf(mx1, __shfl_xor_sync(0xffffffffu, mx1, 1));
        mx1 = fmaxf(mx1, __shfl_xor_sync(0xffffffffu, mx1, 2));
        float nrm0 = fmaxf(rm0, mx0), nrm1 = fmaxf(rm1, mx1);
        float al0 = __expf(rm0 - nrm0), al1 = __expf(rm1 - nrm1);
        rm0 = nrm0; rm1 = nrm1;

        float p[8][4];
        float sum0 = 0.f, sum1 = 0.f;
        #pragma unroll
        for (int nt = 0; nt < 8; nt++) {
            p[nt][0] = __expf(sacc[nt][0] - nrm0); sum0 += p[nt][0];
            p[nt][1] = __expf(sacc[nt][1] - nrm0); sum0 += p[nt][1];
            p[nt][2] = __expf(sacc[nt][2] - nrm1); sum1 += p[nt][2];
            p[nt][3] = __expf(sacc[nt][3] - nrm1); sum1 += p[nt][3];
        }
        sum0 += __shfl_xor_sync(0xffffffffu, sum0, 1);
        sum0 += __shfl_xor_sync(0xffffffffu, sum0, 2);
        sum1 += __shfl_xor_sync(0xffffffffu, sum1, 1);
        sum1 += __shfl_xor_sync(0xffffffffu, sum1, 2);
        rs0 = rs0 * al0 + sum0;
        rs1 = rs1 * al1 + sum1;
        #pragma unroll
        for (int nt = 0; nt < 8; nt++) {
            oacc[nt][0] *= al0; oacc[nt][1] *= al0;
            oacc[nt][2] *= al1; oacc[nt][3] *= al1;
        }

        uint32_t ph[4][4], pl[4][4];
        #pragma unroll
        for (int ks = 0; ks < 4; ks++) {
            pack_split2(p[2*ks][0],   p[2*ks][1],   ph[ks][0], pl[ks][0]);
            pack_split2(p[2*ks][2],   p[2*ks][3],   ph[ks][1], pl[ks][1]);
            pack_split2(p[2*ks+1][0], p[2*ks+1][1], ph[ks][2], pl[ks][2]);
            pack_split2(p[2*ks+1][2], p[2*ks+1][3], ph[ks][3], pl[ks][3]);
        }

        #pragma unroll
        for (int ks = 0; ks < 4; ks++) {
            uint32_t vfh[8][2], vfl[8][2];
            #pragma unroll
            for (int np = 0; np < 4; np++) {
                uint32_t va = (uint32_t)((np * 16 + brow) * AT_RPAD) * 4 + bkof + ks * 32;
                LDMX4(vfh[2*np][0], vfh[2*np][1], vfh[2*np+1][0], vfh[2*np+1][1], Vh_s + va);
                LDMX4(vfl[2*np][0], vfl[2*np][1], vfl[2*np+1][0], vfl[2*np+1][1], Vl_s + va);
            }
            #pragma unroll
            for (int nt = 0; nt < 8; nt++) {
                mma_bf16(oacc[nt][0], oacc[nt][1], oacc[nt][2], oacc[nt][3],
                         ph[ks][0], ph[ks][1], ph[ks][2], ph[ks][3],
                         vfl[nt][0], vfl[nt][1]);
                mma_bf16(oacc[nt][0], oacc[nt][1], oacc[nt][2], oacc[nt][3],
                         pl[ks][0], pl[ks][1], pl[ks][2], pl[ks][3],
                         vfh[nt][0], vfh[nt][1]);
                mma_bf16(oacc[nt][0], oacc[nt][1], oacc[nt][2], oacc[nt][3],
                         ph[ks][0], ph[ks][1], ph[ks][2], ph[ks][3],
                         vfh[nt][0], vfh[nt][1]);
            }
        }
    }

    float inv0 = 1.f / rs0, inv1 = 1.f / rs1;
    int trow0 = qt * 64 + wid * 16 + gid;
    #pragma unroll
    for (int nt = 0; nt < 8; nt++) {
        int col = 8 * nt + 2 * tig;
        size_t o0 = ((size_t)(b * T + trow0))     * (NH * HD) + h * HD + col;
        size_t o1 = ((size_t)(b * T + trow0 + 8)) * (NH * HD) + h * HD + col;
        split_store2(Oh, Ol, o0, oacc[nt][0] * inv0, oacc[nt][1] * inv0);
        split_store2(Oh, Ol, o1, oacc[nt][2] * inv1, oacc[nt][3] * inv1);
    }
}

// ---------------- launch ----------------
extern "C" void kernel_launch(void* const* d_in, const int* in_sizes, int n_in,
                              void* d_out, int out_size) {
    const float* hs   = (const float*)d_in[0];
    const float* cosp = (const float*)d_in[1];
    const float* sinp = (const float*)d_in[2];
    const int*   pos  = (const int*)  d_in[3];
    const float* n1w  = (const float*)d_in[5];
    const float* wq   = (const float*)d_in[6];
    const float* wk   = (const float*)d_in[7];
    const float* wv   = (const float*)d_in[8];
    const float* wo   = (const float*)d_in[9];
    const float* n2w  = (const float*)d_in[10];
    const float* wg   = (const float*)d_in[11];
    const float* wu   = (const float*)d_in[12];
    const float* wd   = (const float*)d_in[13];

    float *q, *k, *v, *h2;
    cudaGetSymbolAddress((void**)&q,  g_q);
    cudaGetSymbolAddress((void**)&k,  g_k);
    cudaGetSymbolAddress((void**)&v,  g_v);
    cudaGetSymbolAddress((void**)&h2, g_h2);

    bf16 *wqh,*wql,*wkh,*wkl,*wvh,*wvl,*woh,*wol,*wgh,*wgl,*wuh,*wul,*wdh,*wdl;
    bf16 *xnh,*xnl,*ath,*atl,*xn2h,*xn2l,*gh,*gl;
    bf16 *qh,*ql,*kh,*kl,*vth,*vtl;
    cudaGetSymbolAddress((void**)&wqh, s_wq_h);  cudaGetSymbolAddress((void**)&wql, s_wq_l);
    cudaGetSymbolAddress((void**)&wkh, s_wk_h);  cudaGetSymbolAddress((void**)&wkl, s_wk_l);
    cudaGetSymbolAddress((void**)&wvh, s_wv_h);  cudaGetSymbolAddress((void**)&wvl, s_wv_l);
    cudaGetSymbolAddress((void**)&woh, s_wo_h);  cudaGetSymbolAddress((void**)&wol, s_wo_l);
    cudaGetSymbolAddress((void**)&wgh, s_wg_h);  cudaGetSymbolAddress((void**)&wgl, s_wg_l);
    cudaGetSymbolAddress((void**)&wuh, s_wu_h);  cudaGetSymbolAddress((void**)&wul, s_wu_l);
    cudaGetSymbolAddress((void**)&wdh, s_wd_h);  cudaGetSymbolAddress((void**)&wdl, s_wd_l);
    cudaGetSymbolAddress((void**)&xnh, s_xn_h);  cudaGetSymbolAddress((void**)&xnl, s_xn_l);
    cudaGetSymbolAddress((void**)&ath, s_at_h);  cudaGetSymbolAddress((void**)&atl, s_at_l);
    cudaGetSymbolAddress((void**)&xn2h, s_xn2_h);cudaGetSymbolAddress((void**)&xn2l, s_xn2_l);
    cudaGetSymbolAddress((void**)&gh,  s_g_h);   cudaGetSymbolAddress((void**)&gl,  s_g_l);
    cudaGetSymbolAddress((void**)&qh,  s_q_h);   cudaGetSymbolAddress((void**)&ql,  s_q_l);
    cudaGetSymbolAddress((void**)&kh,  s_k_h);   cudaGetSymbolAddress((void**)&kl,  s_k_l);
    cudaGetSymbolAddress((void**)&vth, s_vt_h);  cudaGetSymbolAddress((void**)&vtl, s_vt_l);

    float* out_x = (float*)d_out;
    float* out_k = out_x + (size_t)M * H;
    float* out_v = out_k + (size_t)B * NKV * T * HD;

    cudaFuncSetAttribute(gemm_mma_kernel,
                         cudaFuncAttributeMaxDynamicSharedMemorySize, GEMM_DSMEM);
    cudaFuncSetAttribute(gemm_qkv_kernel,
                         cudaFuncAttributeMaxDynamicSharedMemorySize, GEMM_DSMEM);
    cudaFuncSetAttribute(gemm_gu_silu_kernel,
                         cudaFuncAttributeMaxDynamicSharedMemorySize, GEMM_DSMEM);
    cudaFuncSetAttribute(attn_kernel,
                         cudaFuncAttributeMaxDynamicSharedMemorySize, ATTN_DSMEM);

    // 0. split weights
    split_kernel<<<(NH*HD*H/4 + 255)/256, 256>>>(wq, wqh, wql, NH*HD*H/4);
    split_kernel<<<(NKV*HD*H/4 + 255)/256, 256>>>(wk, wkh, wkl, NKV*HD*H/4);
    split_kernel<<<(NKV*HD*H/4 + 255)/256, 256>>>(wv, wvh, wvl, NKV*HD*H/4);
    split_kernel<<<(H*NH*HD/4 + 255)/256, 256>>>(wo, woh, wol, H*NH*HD/4);
    split_kernel<<<(IM*H/4 + 255)/256, 256>>>(wg, wgh, wgl, IM*H/4);
    split_kernel<<<(IM*H/4 + 255)/256, 256>>>(wu, wuh, wul, IM*H/4);
    split_kernel<<<(H*IM/4 + 255)/256, 256>>>(wd, wdh, wdl, H*IM/4);

    // 1. RMSNorm 1
    rmsnorm_split_kernel<<<M, 256>>>(hs, n1w, xnh, xnl);
    // 2. fused Q/K/V projections (grid: M-block fast for B-stripe L2 reuse)
    gemm_qkv_kernel<<<dim3(M / 64, 24), 256, GEMM_DSMEM>>>(xnh, xnl, q, k, v);
    // 3. RoPE + KV-cache writeout + bf16 splits
    rope_q_kernel <<<(B * T * NH  * (HD / 2)) / 256, 256>>>(q, cosp, sinp, pos, qh, ql);
    rope_kv_kernel<<<(B * T * NKV * (HD / 2)) / 256, 256>>>(k, v, cosp, sinp, pos,
                                                            out_k, out_v, kh, kl, vth, vtl);
    // 4. Attention (tensor-core, 3xBF16)
    attn_kernel<<<dim3(T / 64, NH, B), 128, ATTN_DSMEM>>>(qh, ql, kh, kl, vth, vtl, ath, atl);
    // 5. O-projection + residual
    gemm_mma_kernel<<<dim3(M / 64, H / 128), 256, GEMM_DSMEM>>>(ath, atl, woh, wol,
                                                                hs, h2, H, NH * HD);
    // 6. RMSNorm 2
    rmsnorm_split_kernel<<<M, 256>>>(h2, n2w, xn2h, xn2l);
    // 7. fused MLP gate/up + SwiGLU (split bf16 output directly)
    gemm_gu_silu_kernel<<<dim3(M / 64, IM / 64), 256, GEMM_DSMEM>>>(xn2h, xn2l, gh, gl);
    // 8. Down projection + residual -> x output
    gemm_mma_kernel<<<dim3(M / 64, H / 128), 256, GEMM_DSMEM>>>(gh, gl, wdh, wdl,
                                                                h2, out_x, H, IM);
}

// round 11
// speedup vs baseline: 1.0162x; 1.0162x over previous
#include <cuda_runtime.h>
#include <cuda_bf16.h>
#include <math.h>
#include <stdint.h>

#define B   2
#define T   1024
#define H   2048
#define NH  32
#define NKV 8
#define HD  64
#define IM  8192
#define M   (B*T)

typedef __nv_bfloat16  bf16;
typedef __nv_bfloat162 bf162;

// ---------------- scratch (device globals; no allocation) ----------------
__device__ __align__(16) float g_q  [M * NH * HD];
__device__ __align__(16) float g_k  [M * NKV * HD];
__device__ __align__(16) float g_v  [M * NKV * HD];
__device__ __align__(16) float g_h2 [M * H];
// bf16 hi/lo split weights
__device__ __align__(16) bf16 s_wq_h[NH*HD*H],  s_wq_l[NH*HD*H];
__device__ __align__(16) bf16 s_wk_h[NKV*HD*H], s_wk_l[NKV*HD*H];
__device__ __align__(16) bf16 s_wv_h[NKV*HD*H], s_wv_l[NKV*HD*H];
__device__ __align__(16) bf16 s_wo_h[H*NH*HD],  s_wo_l[H*NH*HD];
__device__ __align__(16) bf16 s_wg_h[(size_t)IM*H], s_wg_l[(size_t)IM*H];
__device__ __align__(16) bf16 s_wu_h[(size_t)IM*H], s_wu_l[(size_t)IM*H];
__device__ __align__(16) bf16 s_wd_h[(size_t)H*IM], s_wd_l[(size_t)H*IM];
// bf16 hi/lo split activations
__device__ __align__(16) bf16 s_xn_h [M*H],        s_xn_l [M*H];
__device__ __align__(16) bf16 s_at_h [M*NH*HD],    s_at_l [M*NH*HD];
__device__ __align__(16) bf16 s_xn2_h[M*H],        s_xn2_l[M*H];
__device__ __align__(16) bf16 s_g_h  [(size_t)M*IM], s_g_l[(size_t)M*IM];
// bf16 hi/lo split q/k/v for attention (head-major; v transposed)
__device__ __align__(16) bf16 s_q_h [M*NH*HD],  s_q_l [M*NH*HD];
__device__ __align__(16) bf16 s_k_h [M*NKV*HD], s_k_l [M*NKV*HD];
__device__ __align__(16) bf16 s_vt_h[M*NKV*HD], s_vt_l[M*NKV*HD];

// ---------------- helpers ----------------
__device__ __forceinline__ uint32_t smem_u32(const void* p) {
    uint32_t a;
    asm("{ .reg .u64 t; cvta.to.shared.u64 t, %1; cvt.u32.u64 %0, t; }"
        : "=r"(a) : "l"(p));
    return a;
}
__device__ __forceinline__ void cp_async16(uint32_t dst, const void* src) {
    asm volatile("cp.async.cg.shared.global [%0], [%1], 16;"
                 :: "r"(dst), "l"(src));
}
#define CP_ASYNC_COMMIT() asm volatile("cp.async.commit_group;" ::: "memory")
#define CP_ASYNC_WAIT0()  asm volatile("cp.async.wait_group 0;" ::: "memory")

#define LDMX4(r0, r1, r2, r3, addr) \
    asm volatile("ldmatrix.sync.aligned.m8n8.x4.shared.b16 {%0,%1,%2,%3}, [%4];" \
        : "=r"(r0), "=r"(r1), "=r"(r2), "=r"(r3) : "r"(addr))

__device__ __forceinline__ void mma_bf16(float& c0, float& c1, float& c2, float& c3,
                                         uint32_t a0, uint32_t a1, uint32_t a2, uint32_t a3,
                                         uint32_t b0, uint32_t b1) {
    asm volatile(
        "mma.sync.aligned.m16n8k16.row.col.f32.bf16.bf16.f32 "
        "{%0,%1,%2,%3}, {%4,%5,%6,%7}, {%8,%9}, {%0,%1,%2,%3};"
        : "+f"(c0), "+f"(c1), "+f"(c2), "+f"(c3)
        : "r"(a0), "r"(a1), "r"(a2), "r"(a3), "r"(b0), "r"(b1));
}

// split-store helpers (fp32 -> hi/lo bf16)
__device__ __forceinline__ void split_store4(bf16* __restrict__ h, bf16* __restrict__ l,
                                             size_t idx, float x, float y, float z, float w) {
    bf162 h0 = __floats2bfloat162_rn(x, y);
    bf162 h1 = __floats2bfloat162_rn(z, w);
    float lx = x - __bfloat162float(__low2bfloat16(h0));
    float ly = y - __bfloat162float(__high2bfloat16(h0));
    float lz = z - __bfloat162float(__low2bfloat16(h1));
    float lw = w - __bfloat162float(__high2bfloat16(h1));
    *(bf162*)(h + idx)     = h0;
    *(bf162*)(h + idx + 2) = h1;
    *(bf162*)(l + idx)     = __floats2bfloat162_rn(lx, ly);
    *(bf162*)(l + idx + 2) = __floats2bfloat162_rn(lz, lw);
}
__device__ __forceinline__ void split_store2(bf16* __restrict__ h, bf16* __restrict__ l,
                                             size_t idx, float x, float y) {
    bf162 h0 = __floats2bfloat162_rn(x, y);
    float lx = x - __bfloat162float(__low2bfloat16(h0));
    float ly = y - __bfloat162float(__high2bfloat16(h0));
    *(bf162*)(h + idx) = h0;
    *(bf162*)(l + idx) = __floats2bfloat162_rn(lx, ly);
}
__device__ __forceinline__ void pack_split2(float x, float y, uint32_t& hi, uint32_t& lo) {
    bf162 h0 = __floats2bfloat162_rn(x, y);
    float lx = x - __bfloat162float(__low2bfloat16(h0));
    float ly = y - __bfloat162float(__high2bfloat16(h0));
    bf162 l0 = __floats2bfloat162_rn(lx, ly);
    hi = *(uint32_t*)&h0;
    lo = *(uint32_t*)&l0;
}

// ---------------- weight split kernel (8 elems/thread, 16B stores) ----------
__global__ void split_kernel(const float* __restrict__ x,
                             bf16* __restrict__ h, bf16* __restrict__ l, int n8) {
    int i = blockIdx.x * blockDim.x + threadIdx.x;
    if (i >= n8) return;
    float4 a = ((const float4*)x)[2 * i];
    float4 b = ((const float4*)x)[2 * i + 1];
    uint32_t h0, h1, h2, h3, l0, l1, l2, l3;
    pack_split2(a.x, a.y, h0, l0);
    pack_split2(a.z, a.w, h1, l1);
    pack_split2(b.x, b.y, h2, l2);
    pack_split2(b.z, b.w, h3, l3);
    ((uint4*)h)[i] = make_uint4(h0, h1, h2, h3);
    ((uint4*)l)[i] = make_uint4(l0, l1, l2, l3);
}

// ---------------- 3xBF16 GEMM core (ldmatrix, 2-stage cp.async) -------------
#define RPAD 20
#define ATILE_U (64 * RPAD)                       // 1280
#define BTILE_U (128 * RPAD)                      // 2560
#define STAGE_U (2 * ATILE_U + 2 * BTILE_U)       // 7680 uints
#define GEMM_DSMEM (2 * STAGE_U * 4)              // 61440 B

__device__ __forceinline__ void gemm_tile(float* sm,
                                          const bf16* __restrict__ Ah, const bf16* __restrict__ Al,
                                          const bf16* __restrict__ Bh, const bf16* __restrict__ Bl,
                                          const float* __restrict__ res, float* __restrict__ C,
                                          int N, int K, int bm, int bn) {
    const uint32_t smem_base = smem_u32(sm);
    const int tid  = threadIdx.x;
    const int wid  = tid >> 5;
    const int lane = tid & 31;
    const int wm   = wid >> 2;
    const int wn   = wid & 3;
    const int gid  = lane >> 2;
    const int tig  = lane & 3;
    const int KC   = K >> 5;
    const int lrow = tid >> 2;
    const int lch  = tid & 3;

    const int sub  = lane >> 3;
    const int r8   = lane & 7;
    const int arow = ((sub & 1) << 3) + r8;
    const int akof = (sub >> 1) << 4;
    const int brow = ((sub >> 1) << 3) + r8;
    const int bkof = (sub & 1) << 4;

    uint32_t aaddr[2][2], baddr[2][2];
    #pragma unroll
    for (int mt = 0; mt < 2; mt++) {
        uint32_t base = smem_base + (uint32_t)((wm * 32 + mt * 16 + arow) * RPAD) * 4 + akof;
        aaddr[mt][0] = base;
        aaddr[mt][1] = base + ATILE_U * 4;
    }
    #pragma unroll
    for (int np = 0; np < 2; np++) {
        uint32_t base = smem_base + (uint32_t)(2 * ATILE_U + (wn * 32 + np * 16 + brow) * RPAD) * 4 + bkof;
        baddr[np][0] = base;
        baddr[np][1] = base + BTILE_U * 4;
    }

    float acc[2][4][4];
    #pragma unroll
    for (int i = 0; i < 2; i++)
        #pragma unroll
        for (int j = 0; j < 4; j++)
            #pragma unroll
            for (int k = 0; k < 4; k++) acc[i][j][k] = 0.f;

    auto issue_load = [&](int c, int buf) {
        const int k0 = c << 5;
        uint32_t st = smem_base + buf * (STAGE_U * 4);
        cp_async16(st + (lrow * RPAD + lch * 4) * 4,
                   Ah + (size_t)(bm + lrow) * K + k0 + lch * 8);
        cp_async16(st + (ATILE_U + lrow * RPAD + lch * 4) * 4,
                   Al + (size_t)(bm + lrow) * K + k0 + lch * 8);
        #pragma unroll
        for (int it = 0; it < 2; it++) {
            int br = it * 64 + lrow;
            cp_async16(st + (2 * ATILE_U + br * RPAD + lch * 4) * 4,
                       Bh + (size_t)(bn + br) * K + k0 + lch * 8);
            cp_async16(st + (2 * ATILE_U + BTILE_U + br * RPAD + lch * 4) * 4,
                       Bl + (size_t)(bn + br) * K + k0 + lch * 8);
        }
        CP_ASYNC_COMMIT();
    };

    issue_load(0, 0);

    for (int c = 0; c < KC; c++) {
        const int buf = c & 1;
        CP_ASYNC_WAIT0();
        __syncthreads();
        if (c + 1 < KC) issue_load(c + 1, buf ^ 1);

        const uint32_t boff = (uint32_t)buf * (STAGE_U * 4);

        #pragma unroll
        for (int ks = 0; ks < 2; ks++) {
            const uint32_t koff = boff + ks * 32;
            uint32_t ahf[2][4], alf[2][4], bhf[4][2], blf[4][2];
            #pragma unroll
            for (int mt = 0; mt < 2; mt++) {
                LDMX4(ahf[mt][0], ahf[mt][1], ahf[mt][2], ahf[mt][3], aaddr[mt][0] + koff);
                LDMX4(alf[mt][0], alf[mt][1], alf[mt][2], alf[mt][3], aaddr[mt][1] + koff);
            }
            #pragma unroll
            for (int np = 0; np < 2; np++) {
                LDMX4(bhf[2*np][0], bhf[2*np][1], bhf[2*np+1][0], bhf[2*np+1][1],
                      baddr[np][0] + koff);
                LDMX4(blf[2*np][0], blf[2*np][1], blf[2*np+1][0], blf[2*np+1][1],
                      baddr[np][1] + koff);
            }
            #pragma unroll
            for (int mt = 0; mt < 2; mt++)
                #pragma unroll
                for (int nt = 0; nt < 4; nt++) {
                    mma_bf16(acc[mt][nt][0], acc[mt][nt][1],
                             acc[mt][nt][2], acc[mt][nt][3],
                             ahf[mt][0], ahf[mt][1], ahf[mt][2], ahf[mt][3],
                             blf[nt][0], blf[nt][1]);
                    mma_bf16(acc[mt][nt][0], acc[mt][nt][1],
                             acc[mt][nt][2], acc[mt][nt][3],
                             alf[mt][0], alf[mt][1], alf[mt][2], alf[mt][3],
                             bhf[nt][0], bhf[nt][1]);
                    mma_bf16(acc[mt][nt][0], acc[mt][nt][1],
                             acc[mt][nt][2], acc[mt][nt][3],
                             ahf[mt][0], ahf[mt][1], ahf[mt][2], ahf[mt][3],
                             bhf[nt][0], bhf[nt][1]);
                }
        }
        __syncthreads();
    }

    #pragma unroll
    for (int mt = 0; mt < 2; mt++) {
        int r0 = bm + wm * 32 + mt * 16 + gid;
        #pragma unroll
        for (int nt = 0; nt < 4; nt++) {
            int col = bn + wn * 32 + nt * 8 + tig * 2;
            size_t o0 = (size_t)r0 * N + col;
            size_t o1 = (size_t)(r0 + 8) * N + col;
            float2 v0 = make_float2(acc[mt][nt][0], acc[mt][nt][1]);
            float2 v1 = make_float2(acc[mt][nt][2], acc[mt][nt][3]);
            if (res) {
                float2 r0v = *(const float2*)(res + o0);
                float2 r1v = *(const float2*)(res + o1);
                v0.x += r0v.x; v0.y += r0v.y;
                v1.x += r1v.x; v1.y += r1v.y;
            }
            *(float2*)(C + o0) = v0;
            *(float2*)(C + o1) = v1;
        }
    }
}

__global__ void __launch_bounds__(256, 2)
gemm_mma_kernel(const bf16* __restrict__ Ah, const bf16* __restrict__ Al,
                const bf16* __restrict__ Bh, const bf16* __restrict__ Bl,
                const float* __restrict__ res, float* __restrict__ C,
                int N, int K) {
    extern __shared__ float sm[];
    gemm_tile(sm, Ah, Al, Bh, Bl, res, C, N, K, blockIdx.y * 64, blockIdx.x * 128);
}

__global__ void __launch_bounds__(256, 2)
gemm_qkv_kernel(const bf16* __restrict__ Ah, const bf16* __restrict__ Al,
                float* __restrict__ q, float* __restrict__ k, float* __restrict__ v) {
    extern __shared__ float sm[];
    const int ct = blockIdx.x;
    const bf16 *Bh, *Bl; float* C; int N, bn;
    if (ct < 16)      { Bh = s_wq_h; Bl = s_wq_l; C = q; N = NH  * HD; bn = ct * 128; }
    else if (ct < 20) { Bh = s_wk_h; Bl = s_wk_l; C = k; N = NKV * HD; bn = (ct - 16) * 128; }
    else              { Bh = s_wv_h; Bl = s_wv_l; C = v; N = NKV * HD; bn = (ct - 20) * 128; }
    gemm_tile(sm, Ah, Al, Bh, Bl, nullptr, C, N, H, blockIdx.y * 64, bn);
}

// ---- fused gate/up + SwiGLU: CTA computes 64x64 gate AND up tiles, applies
//      silu(g)*u in epilogue, split-stores bf16. grid: x = N64-block, y = M-block
__global__ void __launch_bounds__(256, 2)
gemm_gu_silu_kernel(const bf16* __restrict__ Ah, const bf16* __restrict__ Al,
                    bf16* __restrict__ gh, bf16* __restrict__ gl) {
    extern __shared__ float sm[];
    const uint32_t smem_base = smem_u32(sm);
    const int bn = blockIdx.x * 64;
    const int bm = blockIdx.y * 64;
    const int K  = H, KC = K >> 5;

    const int tid  = threadIdx.x;
    const int wid  = tid >> 5;
    const int lane = tid & 31;
    const int wsel = wid >> 2;           // 0 = gate, 1 = up
    const int wq   = wid & 3;
    const int wm   = wq >> 1;            // 0..1 -> 32-row band
    const int wn   = wq & 1;             // 0..1 -> 32-col band
    const int gid  = lane >> 2;
    const int tig  = lane & 3;
    const int lrow = tid >> 2;           // 0..63
    const int lch  = tid & 3;

    const int sub  = lane >> 3;
    const int r8   = lane & 7;
    const int arow = ((sub & 1) << 3) + r8;
    const int akof = (sub >> 1) << 4;
    const int brow = ((sub >> 1) << 3) + r8;
    const int bkof = (sub & 1) << 4;

    // stage layout: 6 tiles of ATILE_U uints: A_h, A_l, Bg_h, Bg_l, Bu_h, Bu_l
    uint32_t aaddr[2][2], baddr[2][2];
    #pragma unroll
    for (int mt = 0; mt < 2; mt++) {
        uint32_t base = smem_base + (uint32_t)((wm * 32 + mt * 16 + arow) * RPAD) * 4 + akof;
        aaddr[mt][0] = base;
        aaddr[mt][1] = base + ATILE_U * 4;
    }
    #pragma unroll
    for (int np = 0; np < 2; np++) {
        uint32_t base = smem_base +
            (uint32_t)((2 + 2 * wsel) * ATILE_U + (wn * 32 + np * 16 + brow) * RPAD) * 4 + bkof;
        baddr[np][0] = base;
        baddr[np][1] = base + ATILE_U * 4;
    }

    const bf16* Bgh = s_wg_h; const bf16* Bgl = s_wg_l;
    const bf16* Buh = s_wu_h; const bf16* Bul = s_wu_l;

    float acc[2][4][4];
    #pragma unroll
    for (int i = 0; i < 2; i++)
        #pragma unroll
        for (int j = 0; j < 4; j++)
            #pragma unroll
            for (int k = 0; k < 4; k++) acc[i][j][k] = 0.f;

    auto issue_load = [&](int c, int buf) {
        const int k0 = c << 5;
        uint32_t st = smem_base + buf * (STAGE_U * 4);
        cp_async16(st + (0 * ATILE_U + lrow * RPAD + lch * 4) * 4,
                   Ah + (size_t)(bm + lrow) * K + k0 + lch * 8);
        cp_async16(st + (1 * ATILE_U + lrow * RPAD + lch * 4) * 4,
                   Al + (size_t)(bm + lrow) * K + k0 + lch * 8);
        cp_async16(st + (2 * ATILE_U + lrow * RPAD + lch * 4) * 4,
                   Bgh + (size_t)(bn + lrow) * K + k0 + lch * 8);
        cp_async16(st + (3 * ATILE_U + lrow * RPAD + lch * 4) * 4,
                   Bgl + (size_t)(bn + lrow) * K + k0 + lch * 8);
        cp_async16(st + (4 * ATILE_U + lrow * RPAD + lch * 4) * 4,
                   Buh + (size_t)(bn + lrow) * K + k0 + lch * 8);
        cp_async16(st + (5 * ATILE_U + lrow * RPAD + lch * 4) * 4,
                   Bul + (size_t)(bn + lrow) * K + k0 + lch * 8);
        CP_ASYNC_COMMIT();
    };

    issue_load(0, 0);

    for (int c = 0; c < KC; c++) {
        const int buf = c & 1;
        CP_ASYNC_WAIT0();
        __syncthreads();
        if (c + 1 < KC) issue_load(c + 1, buf ^ 1);

        const uint32_t boff = (uint32_t)buf * (STAGE_U * 4);

        #pragma unroll
        for (int ks = 0; ks < 2; ks++) {
            const uint32_t koff = boff + ks * 32;
            uint32_t ahf[2][4], alf[2][4], bhf[4][2], blf[4][2];
            #pragma unroll
            for (int mt = 0; mt < 2; mt++) {
                LDMX4(ahf[mt][0], ahf[mt][1], ahf[mt][2], ahf[mt][3], aaddr[mt][0] + koff);
                LDMX4(alf[mt][0], alf[mt][1], alf[mt][2], alf[mt][3], aaddr[mt][1] + koff);
            }
            #pragma unroll
            for (int np = 0; np < 2; np++) {
                LDMX4(bhf[2*np][0], bhf[2*np][1], bhf[2*np+1][0], bhf[2*np+1][1],
                      baddr[np][0] + koff);
                LDMX4(blf[2*np][0], blf[2*np][1], blf[2*np+1][0], blf[2*np+1][1],
                      baddr[np][1] + koff);
            }
            #pragma unroll
            for (int mt = 0; mt < 2; mt++)
                #pragma unroll
                for (int nt = 0; nt < 4; nt++) {
                    mma_bf16(acc[mt][nt][0], acc[mt][nt][1],
                             acc[mt][nt][2], acc[mt][nt][3],
                             ahf[mt][0], ahf[mt][1], ahf[mt][2], ahf[mt][3],
                             blf[nt][0], blf[nt][1]);
                    mma_bf16(acc[mt][nt][0], acc[mt][nt][1],
                             acc[mt][nt][2], acc[mt][nt][3],
                             alf[mt][0], alf[mt][1], alf[mt][2], alf[mt][3],
                             bhf[nt][0], bhf[nt][1]);
                    mma_bf16(acc[mt][nt][0], acc[mt][nt][1],
                             acc[mt][nt][2], acc[mt][nt][3],
                             ahf[mt][0], ahf[mt][1], ahf[mt][2], ahf[mt][3],
                             bhf[nt][0], bhf[nt][1]);
                }
        }
        __syncthreads();
    }

    // ---- epilogue: exchange gate accs via smem, apply silu*up, split-store --
    float (*sx)[66] = (float (*)[66])sm;
    __syncthreads();
    if (wsel == 0) {
        #pragma unroll
        for (int mt = 0; mt < 2; mt++) {
            int lr = wm * 32 + mt * 16 + gid;
            #pragma unroll
            for (int nt = 0; nt < 4; nt++) {
                int lc = wn * 32 + nt * 8 + tig * 2;
                sx[lr][lc]     = acc[mt][nt][0];
                sx[lr][lc + 1] = acc[mt][nt][1];
                sx[lr + 8][lc]     = acc[mt][nt][2];
                sx[lr + 8][lc + 1] = acc[mt][nt][3];
            }
        }
    }
    __syncthreads();
    if (wsel == 1) {
        #pragma unroll
        for (int mt = 0; mt < 2; mt++) {
            int lr = wm * 32 + mt * 16 + gid;
            #pragma unroll
            for (int nt = 0; nt < 4; nt++) {
                int lc = wn * 32 + nt * 8 + tig * 2;
                float g0 = sx[lr][lc],     g1 = sx[lr][lc + 1];
                float g2 = sx[lr + 8][lc], g3 = sx[lr + 8][lc + 1];
                float r0 = g0 / (1.f + __expf(-g0)) * acc[mt][nt][0];
                float r1 = g1 / (1.f + __expf(-g1)) * acc[mt][nt][1];
                float r2 = g2 / (1.f + __expf(-g2)) * acc[mt][nt][2];
                float r3 = g3 / (1.f + __expf(-g3)) * acc[mt][nt][3];
                size_t o0 = (size_t)(bm + lr)     * IM + bn + lc;
                size_t o1 = (size_t)(bm + lr + 8) * IM + bn + lc;
                split_store2(gh, gl, o0, r0, r1);
                split_store2(gh, gl, o1, r2, r3);
            }
        }
    }
}

// ---------------- RMSNorm with split output ----------------
__global__ void rmsnorm_split_kernel(const float* __restrict__ x,
                                     const float* __restrict__ w,
                                     bf16* __restrict__ oh, bf16* __restrict__ ol) {
    int row = blockIdx.x;
    const float* xr = x + (size_t)row * H;
    float ss = 0.f;
    for (int i = threadIdx.x; i < H / 4; i += blockDim.x) {
        float4 v = ((const float4*)xr)[i];
        ss += v.x * v.x + v.y * v.y + v.z * v.z + v.w * v.w;
    }
    __shared__ float red[32];
    #pragma unroll
    for (int o = 16; o; o >>= 1) ss += __shfl_xor_sync(0xffffffffu, ss, o);
    if ((threadIdx.x & 31) == 0) red[threadIdx.x >> 5] = ss;
    __syncthreads();
    if (threadIdx.x < 32) {
        float v = (threadIdx.x < (blockDim.x >> 5)) ? red[threadIdx.x] : 0.f;
        #pragma unroll
        for (int o = 16; o; o >>= 1) v += __shfl_xor_sync(0xffffffffu, v, o);
        if (threadIdx.x == 0) red[0] = v;
    }
    __syncthreads();
    float r = rsqrtf(red[0] / (float)H + 1e-6f);
    for (int i = threadIdx.x; i < H / 4; i += blockDim.x) {
        float4 v = ((const float4*)xr)[i];
        float4 wv = ((const float4*)w)[i];
        split_store4(oh, ol, (size_t)row * H + 4 * i,
                     v.x * r * wv.x, v.y * r * wv.y, v.z * r * wv.z, v.w * r * wv.w);
    }
}

// ---------------- RoPE (writes bf16 hi/lo, head-major) ----------------
__global__ void rope_q_kernel(const float* __restrict__ q,
                              const float* __restrict__ cosp,
                              const float* __restrict__ sinp,
                              const int* __restrict__ pos,
                              bf16* __restrict__ qh, bf16* __restrict__ ql) {
    int idx = blockIdx.x * blockDim.x + threadIdx.x;
    int d2 = idx & 31;
    int h  = (idx >> 5) & (NH - 1);
    int bt = idx >> 10;
    int t  = bt & (T - 1);
    int b  = bt >> 10;
    int p  = pos[bt];
    float c = cosp[p * 32 + d2], s = sinp[p * 32 + d2];
    size_t base = (size_t)bt * (NH * HD) + h * HD + 2 * d2;
    float x1 = q[base], x2 = q[base + 1];
    float r1 = x1 * c - x2 * s;
    float r2 = x1 * s + x2 * c;
    size_t ob = ((size_t)(b * NH + h) * T + t) * HD + 2 * d2;
    split_store2(qh, ql, ob, r1, r2);
}

__global__ void rope_kv_kernel(const float* __restrict__ k, const float* __restrict__ v,
                               const float* __restrict__ cosp,
                               const float* __restrict__ sinp,
                               const int* __restrict__ pos,
                               float* __restrict__ outk, float* __restrict__ outv,
                               bf16* __restrict__ kh, bf16* __restrict__ kl,
                               bf16* __restrict__ vth, bf16* __restrict__ vtl) {
    int idx = blockIdx.x * blockDim.x + threadIdx.x;
    int d2 = idx & 31;
    int h  = (idx >> 5) & (NKV - 1);
    int bt = idx >> 8;
    int t  = bt & (T - 1);
    int b  = bt >> 10;
    int p  = pos[bt];
    float c = cosp[p * 32 + d2], s = sinp[p * 32 + d2];
    size_t base = (size_t)bt * (NKV * HD) + h * HD + 2 * d2;
    float x1 = k[base], x2 = k[base + 1];
    float r1 = x1 * c - x2 * s;
    float r2 = x1 * s + x2 * c;
    size_t ob = ((size_t)(b * NKV + h) * T + t) * HD + 2 * d2;
    outk[ob] = r1;       outk[ob + 1] = r2;
    split_store2(kh, kl, ob, r1, r2);
    float v1 = v[base], v2 = v[base + 1];
    outv[ob] = v1;       outv[ob + 1] = v2;
    size_t vb = ((size_t)(b * NKV + h) * HD + 2 * d2) * T + t;
    bf16 vh1 = __float2bfloat16(v1);
    bf16 vh2 = __float2bfloat16(v2);
    vth[vb]     = vh1; vtl[vb]     = __float2bfloat16(v1 - __bfloat162float(vh1));
    vth[vb + T] = vh2; vtl[vb + T] = __float2bfloat16(v2 - __bfloat162float(vh2));
}

// ---------------- Flash attention (3xBF16 mma, 64 q rows/CTA, 4 warps) ------
#define AT_RPAD 36
#define AT_TILE_U (64 * AT_RPAD)
#define ATTN_DSMEM (6 * AT_TILE_U * 4)

__global__ void __launch_bounds__(128)
attn_kernel(const bf16* __restrict__ Qh_g, const bf16* __restrict__ Ql_g,
            const bf16* __restrict__ Kh_g, const bf16* __restrict__ Kl_g,
            const bf16* __restrict__ Vth_g, const bf16* __restrict__ Vtl_g,
            bf16* __restrict__ Oh, bf16* __restrict__ Ol) {
    extern __shared__ uint32_t smu[];
    const int qt = blockIdx.x, h = blockIdx.y, b = blockIdx.z;
    const int kvh = h >> 2;
    const int tid = threadIdx.x, wid = tid >> 5, lane = tid & 31;
    const int gid = lane >> 2, tig = lane & 3;
    const int sub = lane >> 3, r8 = lane & 7;
    const int arow = ((sub & 1) << 3) + r8;
    const int akof = (sub >> 1) << 4;
    const int brow = ((sub >> 1) << 3) + r8;
    const int bkof = (sub & 1) << 4;

    const uint32_t smem_base = smem_u32(smu);
    const uint32_t Qh_s = smem_base;
    const uint32_t Ql_s = Qh_s + AT_TILE_U * 4;
    const uint32_t Kh_s = Ql_s + AT_TILE_U * 4;
    const uint32_t Kl_s = Kh_s + AT_TILE_U * 4;
    const uint32_t Vh_s = Kl_s + AT_TILE_U * 4;
    const uint32_t Vl_s = Vh_s + AT_TILE_U * 4;

    {
        const bf16* qh = Qh_g + ((size_t)(b * NH + h) * T + qt * 64) * HD;
        const bf16* ql = Ql_g + ((size_t)(b * NH + h) * T + qt * 64) * HD;
        #pragma unroll
        for (int it = 0; it < 4; it++) {
            int idx = tid + it * 128;
            int row = idx >> 3, ch = idx & 7;
            cp_async16(Qh_s + (row * AT_RPAD + ch * 4) * 4, qh + (size_t)row * HD + ch * 8);
            cp_async16(Ql_s + (row * AT_RPAD + ch * 4) * 4, ql + (size_t)row * HD + ch * 8);
        }
        CP_ASYNC_COMMIT();
        CP_ASYNC_WAIT0();
        __syncthreads();
    }
    uint32_t qfh[4][4], qfl[4][4];
    {
        uint32_t qa = (uint32_t)((wid * 16 + arow) * AT_RPAD) * 4 + akof;
        #pragma unroll
        for (int ks = 0; ks < 4; ks++) {
            LDMX4(qfh[ks][0], qfh[ks][1], qfh[ks][2], qfh[ks][3], Qh_s + qa + ks * 32);
            LDMX4(qfl[ks][0], qfl[ks][1], qfl[ks][2], qfl[ks][3], Ql_s + qa + ks * 32);
        }
    }

    float oacc[8][4];
    #pragma unroll
    for (int i = 0; i < 8; i++)
        #pragma unroll
        for (int j = 0; j < 4; j++) oacc[i][j] = 0.f;
    float rm0 = -1e30f, rm1 = -1e30f, rs0 = 0.f, rs1 = 0.f;

    for (int kt = 0; kt <= qt; kt++) {
        __syncthreads();
        {
            const bf16* kh  = Kh_g  + ((size_t)(b * NKV + kvh) * T + kt * 64) * HD;
            const bf16* kl  = Kl_g  + ((size_t)(b * NKV + kvh) * T + kt * 64) * HD;
            const bf16* vth = Vth_g + (size_t)(b * NKV + kvh) * HD * T;
            const bf16* vtl = Vtl_g + (size_t)(b * NKV + kvh) * HD * T;
            #pragma unroll
            for (int it = 0; it < 4; it++) {
                int idx = tid + it * 128;
                int row = idx >> 3, ch = idx & 7;
                uint32_t soff = (row * AT_RPAD + ch * 4) * 4;
                cp_async16(Kh_s + soff, kh + (size_t)row * HD + ch * 8);
                cp_async16(Kl_s + soff, kl + (size_t)row * HD + ch * 8);
                cp_async16(Vh_s + soff, vth + (size_t)row * T + kt * 64 + ch * 8);
                cp_async16(Vl_s + soff, vtl + (size_t)row * T + kt * 64 + ch * 8);
            }
            CP_ASYNC_COMMIT();
            CP_ASYNC_WAIT0();
            __syncthreads();
        }

        float sacc[8][4];
        #pragma unroll
        for (int i = 0; i < 8; i++)
            #pragma unroll
            for (int j = 0; j < 4; j++) sacc[i][j] = 0.f;

        #pragma unroll
        for (int ks = 0; ks < 4; ks++) {
            uint32_t kfh[8][2], kfl[8][2];
            #pragma unroll
            for (int np = 0; np < 4; np++) {
                uint32_t ka = (uint32_t)((np * 16 + brow) * AT_RPAD) * 4 + bkof + ks * 32;
                LDMX4(kfh[2*np][0], kfh[2*np][1], kfh[2*np+1][0], kfh[2*np+1][1], Kh_s + ka);
                LDMX4(kfl[2*np][0], kfl[2*np][1], kfl[2*np+1][0], kfl[2*np+1][1], Kl_s + ka);
            }
            #pragma unroll
            for (int nt = 0; nt < 8; nt++) {
                mma_bf16(sacc[nt][0], sacc[nt][1], sacc[nt][2], sacc[nt][3],
                         qfh[ks][0], qfh[ks][1], qfh[ks][2], qfh[ks][3],
                         kfl[nt][0], kfl[nt][1]);
                mma_bf16(sacc[nt][0], sacc[nt][1], sacc[nt][2], sacc[nt][3],
                         qfl[ks][0], qfl[ks][1], qfl[ks][2], qfl[ks][3],
                         kfh[nt][0], kfh[nt][1]);
                mma_bf16(sacc[nt][0], sacc[nt][1], sacc[nt][2], sacc[nt][3],
                         qfh[ks][0], qfh[ks][1], qfh[ks][2], qfh[ks][3],
                         kfh[nt][0], kfh[nt][1]);
            }
        }

        const float scale = 0.125f;
        if (kt == qt) {
            #pragma unroll
            for (int nt = 0; nt < 8; nt++)
                #pragma unroll
                for (int c = 0; c < 4; c++) {
                    int col = 8 * nt + 2 * tig + (c & 1);
                    int row = wid * 16 + gid + ((c >> 1) << 3);
                    sacc[nt][c] = (col <= row) ? sacc[nt][c] * scale : -1e30f;
                }
        } else {
            #pragma unroll
            for (int nt = 0; nt < 8; nt++)
                #pragma unroll
                for (int c = 0; c < 4; c++) sacc[nt][c] *= scale;
        }

        float mx0 = -1e30f, mx1 = -1e30f;
        #pragma unroll
        for (int nt = 0; nt < 8; nt++) {
            mx0 = fmaxf(mx0, fmaxf(sacc[nt][0], sacc[nt][1]));
            mx1 = fmaxf(mx1, fmaxf(sacc[nt][2], sacc[nt][3]));
        }
        mx0 = fmaxf(mx0, __shfl_xor_sync(0xffffffffu, mx0, 1));
        mx0 = fmaxf(mx0, __shfl_xor_sync(0xffffffffu, mx0, 2));
        mx1 = fmaxf(mx1, __shfl_xor_sync(0xffffffffu, mx1, 1));
        mx1 = fmaxf(mx1, __shfl_xor_sync(0xffffffffu, mx1, 2));
        float nrm0 = fmaxf(rm0, mx0), nrm1 = fmaxf(rm1, mx1);
        float al0 = __expf(rm0 - nrm0), al1 = __expf(rm1 - nrm1);
        rm0 = nrm0; rm1 = nrm1;

        float p[8][4];
        float sum0 = 0.f, sum1 = 0.f;
        #pragma unroll
        for (int nt = 0; nt < 8; nt++) {
            p[nt][0] = __expf(sacc[nt][0] - nrm0); sum0 += p[nt][0];
            p[nt][1] = __expf(sacc[nt][1] - nrm0); sum0 += p[nt][1];
            p[nt][2] = __expf(sacc[nt][2] - nrm1); sum1 += p[nt][2];
            p[nt][3] = __expf(sacc[nt][3] - nrm1); sum1 += p[nt][3];
        }
        sum0 += __shfl_xor_sync(0xffffffffu, sum0, 1);
        sum0 += __shfl_xor_sync(0xffffffffu, sum0, 2);
        sum1 += __shfl_xor_sync(0xffffffffu, sum1, 1);
        sum1 += __shfl_xor_sync(0xffffffffu, sum1, 2);
        rs0 = rs0 * al0 + sum0;
        rs1 = rs1 * al1 + sum1;
        #pragma unroll
        for (int nt = 0; nt < 8; nt++) {
            oacc[nt][0] *= al0; oacc[nt][1] *= al0;
            oacc[nt][2] *= al1; oacc[nt][3] *= al1;
        }

        uint32_t ph[4][4], pl[4][4];
        #pragma unroll
        for (int ks = 0; ks < 4; ks++) {
            pack_split2(p[2*ks][0],   p[2*ks][1],   ph[ks][0], pl[ks][0]);
            pack_split2(p[2*ks][2],   p[2*ks][3],   ph[ks][1], pl[ks][1]);
            pack_split2(p[2*ks+1][0], p[2*ks+1][1], ph[ks][2], pl[ks][2]);
            pack_split2(p[2*ks+1][2], p[2*ks+1][3], ph[ks][3], pl[ks][3]);
        }

        #pragma unroll
        for (int ks = 0; ks < 4; ks++) {
            uint32_t vfh[8][2], vfl[8][2];
            #pragma unroll
            for (int np = 0; np < 4; np++) {
                uint32_t va = (uint32_t)((np * 16 + brow) * AT_RPAD) * 4 + bkof + ks * 32;
                LDMX4(vfh[2*np][0], vfh[2*np][1], vfh[2*np+1][0], vfh[2*np+1][1], Vh_s + va);
                LDMX4(vfl[2*np][0], vfl[2*np][1], vfl[2*np+1][0], vfl[2*np+1][1], Vl_s + va);
            }
            #pragma unroll
            for (int nt = 0; nt < 8; nt++) {
                mma_bf16(oacc[nt][0], oacc[nt][1], oacc[nt][2], oacc[nt][3],
                         ph[ks][0], ph[ks][1], ph[ks][2], ph[ks][3],
                         vfl[nt][0], vfl[nt][1]);
                mma_bf16(oacc[nt][0], oacc[nt][1], oacc[nt][2], oacc[nt][3],
                         pl[ks][0], pl[ks][1], pl[ks][2], pl[ks][3],
                         vfh[nt][0], vfh[nt][1]);
                mma_bf16(oacc[nt][0], oacc[nt][1], oacc[nt][2], oacc[nt][3],
                         ph[ks][0], ph[ks][1], ph[ks][2], ph[ks][3],
                         vfh[nt][0], vfh[nt][1]);
            }
        }
    }

    float inv0 = 1.f / rs0, inv1 = 1.f / rs1;
    int trow0 = qt * 64 + wid * 16 + gid;
    #pragma unroll
    for (int nt = 0; nt < 8; nt++) {
        int col = 8 * nt + 2 * tig;
        size_t o0 = ((size_t)(b * T + trow0))     * (NH * HD) + h * HD + col;
        size_t o1 = ((size_t)(b * T + trow0 + 8)) * (NH * HD) + h * HD + col;
        split_store2(Oh, Ol, o0, oacc[nt][0] * inv0, oacc[nt][1] * inv0);
        split_store2(Oh, Ol, o1, oacc[nt][2] * inv1, oacc[nt][3] * inv1);
    }
}

// ---------------- launch ----------------
extern "C" void kernel_launch(void* const* d_in, const int* in_sizes, int n_in,
                              void* d_out, int out_size) {
    const float* hs   = (const float*)d_in[0];
    const float* cosp = (const float*)d_in[1];
    const float* sinp = (const float*)d_in[2];
    const int*   pos  = (const int*)  d_in[3];
    const float* n1w  = (const float*)d_in[5];
    const float* wq   = (const float*)d_in[6];
    const float* wk   = (const float*)d_in[7];
    const float* wv   = (const float*)d_in[8];
    const float* wo   = (const float*)d_in[9];
    const float* n2w  = (const float*)d_in[10];
    const float* wg   = (const float*)d_in[11];
    const float* wu   = (const float*)d_in[12];
    const float* wd   = (const float*)d_in[13];

    float *q, *k, *v, *h2;
    cudaGetSymbolAddress((void**)&q,  g_q);
    cudaGetSymbolAddress((void**)&k,  g_k);
    cudaGetSymbolAddress((void**)&v,  g_v);
    cudaGetSymbolAddress((void**)&h2, g_h2);

    bf16 *wqh,*wql,*wkh,*wkl,*wvh,*wvl,*woh,*wol,*wgh,*wgl,*wuh,*wul,*wdh,*wdl;
    bf16 *xnh,*xnl,*ath,*atl,*xn2h,*xn2l,*gh,*gl;
    bf16 *qh,*ql,*kh,*kl,*vth,*vtl;
    cudaGetSymbolAddress((void**)&wqh, s_wq_h);  cudaGetSymbolAddress((void**)&wql, s_wq_l);
    cudaGetSymbolAddress((void**)&wkh, s_wk_h);  cudaGetSymbolAddress((void**)&wkl, s_wk_l);
    cudaGetSymbolAddress((void**)&wvh, s_wv_h);  cudaGetSymbolAddress((void**)&wvl, s_wv_l);
    cudaGetSymbolAddress((void**)&woh, s_wo_h);  cudaGetSymbolAddress((void**)&wol, s_wo_l);
    cudaGetSymbolAddress((void**)&wgh, s_wg_h);  cudaGetSymbolAddress((void**)&wgl, s_wg_l);
    cudaGetSymbolAddress((void**)&wuh, s_wu_h);  cudaGetSymbolAddress((void**)&wul, s_wu_l);
    cudaGetSymbolAddress((void**)&wdh, s_wd_h);  cudaGetSymbolAddress((void**)&wdl, s_wd_l);
    cudaGetSymbolAddress((void**)&xnh, s_xn_h);  cudaGetSymbolAddress((void**)&xnl, s_xn_l);
    cudaGetSymbolAddress((void**)&ath, s_at_h);  cudaGetSymbolAddress((void**)&atl, s_at_l);
    cudaGetSymbolAddress((void**)&xn2h, s_xn2_h);cudaGetSymbolAddress((void**)&xn2l, s_xn2_l);
    cudaGetSymbolAddress((void**)&gh,  s_g_h);   cudaGetSymbolAddress((void**)&gl,  s_g_l);
    cudaGetSymbolAddress((void**)&qh,  s_q_h);   cudaGetSymbolAddress((void**)&ql,  s_q_l);
    cudaGetSymbolAddress((void**)&kh,  s_k_h);   cudaGetSymbolAddress((void**)&kl,  s_k_l);
    cudaGetSymbolAddress((void**)&vth, s_vt_h);  cudaGetSymbolAddress((void**)&vtl, s_vt_l);

    float* out_x = (float*)d_out;
    float* out_k = out_x + (size_t)M * H;
    float* out_v = out_k + (size_t)B * NKV * T * HD;

    cudaFuncSetAttribute(gemm_mma_kernel,
                         cudaFuncAttributeMaxDynamicSharedMemorySize, GEMM_DSMEM);
    cudaFuncSetAttribute(gemm_qkv_kernel,
                         cudaFuncAttributeMaxDynamicSharedMemorySize, GEMM_DSMEM);
    cudaFuncSetAttribute(gemm_gu_silu_kernel,
                         cudaFuncAttributeMaxDynamicSharedMemorySize, GEMM_DSMEM);
    cudaFuncSetAttribute(attn_kernel,
                         cudaFuncAttributeMaxDynamicSharedMemorySize, ATTN_DSMEM);

    // 0. split weights (8 elems per thread)
    split_kernel<<<(NH*HD*H/8 + 255)/256, 256>>>(wq, wqh, wql, NH*HD*H/8);
    split_kernel<<<(NKV*HD*H/8 + 255)/256, 256>>>(wk, wkh, wkl, NKV*HD*H/8);
    split_kernel<<<(NKV*HD*H/8 + 255)/256, 256>>>(wv, wvh, wvl, NKV*HD*H/8);
    split_kernel<<<(H*NH*HD/8 + 255)/256, 256>>>(wo, woh, wol, H*NH*HD/8);
    split_kernel<<<(IM*H/8 + 255)/256, 256>>>(wg, wgh, wgl, IM*H/8);
    split_kernel<<<(IM*H/8 + 255)/256, 256>>>(wu, wuh, wul, IM*H/8);
    split_kernel<<<(H*IM/8 + 255)/256, 256>>>(wd, wdh, wdl, H*IM/8);

    // 1. RMSNorm 1
    rmsnorm_split_kernel<<<M, 256>>>(hs, n1w, xnh, xnl);
    // 2. fused Q/K/V projections (round-9 grid order)
    gemm_qkv_kernel<<<dim3(24, M / 64), 256, GEMM_DSMEM>>>(xnh, xnl, q, k, v);
    // 3. RoPE + KV-cache writeout + bf16 splits
    rope_q_kernel <<<(B * T * NH  * (HD / 2)) / 256, 256>>>(q, cosp, sinp, pos, qh, ql);
    rope_kv_kernel<<<(B * T * NKV * (HD / 2)) / 256, 256>>>(k, v, cosp, sinp, pos,
                                                            out_k, out_v, kh, kl, vth, vtl);
    // 4. Attention (tensor-core, 3xBF16)
    attn_kernel<<<dim3(T / 64, NH, B), 128, ATTN_DSMEM>>>(qh, ql, kh, kl, vth, vtl, ath, atl);
    // 5. O-projection + residual
    gemm_mma_kernel<<<dim3(H / 128, M / 64), 256, GEMM_DSMEM>>>(ath, atl, woh, wol,
                                                                hs, h2, H, NH * HD);
    // 6. RMSNorm 2
    rmsnorm_split_kernel<<<M, 256>>>(h2, n2w, xn2h, xn2l);
    // 7. fused MLP gate/up + SwiGLU (split bf16 output directly)
    gemm_gu_silu_kernel<<<dim3(IM / 64, M / 64), 256, GEMM_DSMEM>>>(xn2h, xn2l, gh, gl);
    // 8. Down projection + residual -> x output
    gemm_mma_kernel<<<dim3(H / 128, M / 64), 256, GEMM_DSMEM>>>(gh, gl, wdh, wdl,
                                                                h2, out_x, H, IM);
}

// round 12
// speedup vs baseline: 1.0191x; 1.0029x over previous
#include <cuda_runtime.h>
#include <cuda_bf16.h>
#include <math.h>
#include <stdint.h>

#define B   2
#define T   1024
#define H   2048
#define NH  32
#define NKV 8
#define HD  64
#define IM  8192
#define M   (B*T)

typedef __nv_bfloat16  bf16;
typedef __nv_bfloat162 bf162;

// ---------------- scratch (device globals; no allocation) ----------------
__device__ __align__(16) float g_q  [M * NH * HD];
__device__ __align__(16) float g_k  [M * NKV * HD];
__device__ __align__(16) float g_v  [M * NKV * HD];
__device__ __align__(16) float g_h2 [M * H];
// bf16 hi/lo split weights
__device__ __align__(16) bf16 s_wq_h[NH*HD*H],  s_wq_l[NH*HD*H];
__device__ __align__(16) bf16 s_wk_h[NKV*HD*H], s_wk_l[NKV*HD*H];
__device__ __align__(16) bf16 s_wv_h[NKV*HD*H], s_wv_l[NKV*HD*H];
__device__ __align__(16) bf16 s_wo_h[H*NH*HD],  s_wo_l[H*NH*HD];
__device__ __align__(16) bf16 s_wg_h[(size_t)IM*H], s_wg_l[(size_t)IM*H];
__device__ __align__(16) bf16 s_wu_h[(size_t)IM*H], s_wu_l[(size_t)IM*H];
__device__ __align__(16) bf16 s_wd_h[(size_t)H*IM], s_wd_l[(size_t)H*IM];
// bf16 hi/lo split activations
__device__ __align__(16) bf16 s_xn_h [M*H],        s_xn_l [M*H];
__device__ __align__(16) bf16 s_at_h [M*NH*HD],    s_at_l [M*NH*HD];
__device__ __align__(16) bf16 s_xn2_h[M*H],        s_xn2_l[M*H];
__device__ __align__(16) bf16 s_g_h  [(size_t)M*IM], s_g_l[(size_t)M*IM];
// bf16 hi/lo split q/k/v for attention (head-major; v transposed)
__device__ __align__(16) bf16 s_q_h [M*NH*HD],  s_q_l [M*NH*HD];
__device__ __align__(16) bf16 s_k_h [M*NKV*HD], s_k_l [M*NKV*HD];
__device__ __align__(16) bf16 s_vt_h[M*NKV*HD], s_vt_l[M*NKV*HD];

// ---------------- helpers ----------------
__device__ __forceinline__ uint32_t smem_u32(const void* p) {
    uint32_t a;
    asm("{ .reg .u64 t; cvta.to.shared.u64 t, %1; cvt.u32.u64 %0, t; }"
        : "=r"(a) : "l"(p));
    return a;
}
__device__ __forceinline__ void cp_async16(uint32_t dst, const void* src) {
    asm volatile("cp.async.cg.shared.global [%0], [%1], 16;"
                 :: "r"(dst), "l"(src));
}
#define CP_ASYNC_COMMIT() asm volatile("cp.async.commit_group;" ::: "memory")
#define CP_ASYNC_WAIT0()  asm volatile("cp.async.wait_group 0;" ::: "memory")

#define LDMX4(r0, r1, r2, r3, addr) \
    asm volatile("ldmatrix.sync.aligned.m8n8.x4.shared.b16 {%0,%1,%2,%3}, [%4];" \
        : "=r"(r0), "=r"(r1), "=r"(r2), "=r"(r3) : "r"(addr))

__device__ __forceinline__ void mma_bf16(float& c0, float& c1, float& c2, float& c3,
                                         uint32_t a0, uint32_t a1, uint32_t a2, uint32_t a3,
                                         uint32_t b0, uint32_t b1) {
    asm volatile(
        "mma.sync.aligned.m16n8k16.row.col.f32.bf16.bf16.f32 "
        "{%0,%1,%2,%3}, {%4,%5,%6,%7}, {%8,%9}, {%0,%1,%2,%3};"
        : "+f"(c0), "+f"(c1), "+f"(c2), "+f"(c3)
        : "r"(a0), "r"(a1), "r"(a2), "r"(a3), "r"(b0), "r"(b1));
}

// split-store helpers (fp32 -> hi/lo bf16)
__device__ __forceinline__ void split_store4(bf16* __restrict__ h, bf16* __restrict__ l,
                                             size_t idx, float x, float y, float z, float w) {
    bf162 h0 = __floats2bfloat162_rn(x, y);
    bf162 h1 = __floats2bfloat162_rn(z, w);
    float lx = x - __bfloat162float(__low2bfloat16(h0));
    float ly = y - __bfloat162float(__high2bfloat16(h0));
    float lz = z - __bfloat162float(__low2bfloat16(h1));
    float lw = w - __bfloat162float(__high2bfloat16(h1));
    *(bf162*)(h + idx)     = h0;
    *(bf162*)(h + idx + 2) = h1;
    *(bf162*)(l + idx)     = __floats2bfloat162_rn(lx, ly);
    *(bf162*)(l + idx + 2) = __floats2bfloat162_rn(lz, lw);
}
__device__ __forceinline__ void split_store2(bf16* __restrict__ h, bf16* __restrict__ l,
                                             size_t idx, float x, float y) {
    bf162 h0 = __floats2bfloat162_rn(x, y);
    float lx = x - __bfloat162float(__low2bfloat16(h0));
    float ly = y - __bfloat162float(__high2bfloat16(h0));
    *(bf162*)(h + idx) = h0;
    *(bf162*)(l + idx) = __floats2bfloat162_rn(lx, ly);
}
__device__ __forceinline__ void pack_split2(float x, float y, uint32_t& hi, uint32_t& lo) {
    bf162 h0 = __floats2bfloat162_rn(x, y);
    float lx = x - __bfloat162float(__low2bfloat16(h0));
    float ly = y - __bfloat162float(__high2bfloat16(h0));
    bf162 l0 = __floats2bfloat162_rn(lx, ly);
    hi = *(uint32_t*)&h0;
    lo = *(uint32_t*)&l0;
}

// ---------------- merged weight-split kernel ----------------
// One launch splits ALL weights. Unit = 16 fp32 elements.
// Segment unit counts (elems/16):
//   wq 262144 | wk 65536 | wv 65536 | wo 262144 | wg 1048576 | wu 1048576 | wd 1048576
#define U_WQ  262144
#define U_WK  (U_WQ + 65536)        // 327680
#define U_WV  (U_WK + 65536)        // 393216
#define U_WO  (U_WV + 262144)       // 655360
#define U_WG  (U_WO + 1048576)      // 1703936
#define U_WU  (U_WG + 1048576)      // 2752512
#define U_WD  (U_WU + 1048576)      // 3801088
#define SPLIT_BLOCKS (U_WD / 256)   // 14848

__global__ void __launch_bounds__(256)
split_all_kernel(const float* __restrict__ wq, const float* __restrict__ wk,
                 const float* __restrict__ wv, const float* __restrict__ wo,
                 const float* __restrict__ wg, const float* __restrict__ wu,
                 const float* __restrict__ wd) {
    uint32_t u = blockIdx.x * 256 + threadIdx.x;
    const float* src; bf16 *h, *l; uint32_t off;
    if (u < U_WQ)      { src = wq; h = s_wq_h; l = s_wq_l; off = u; }
    else if (u < U_WK) { src = wk; h = s_wk_h; l = s_wk_l; off = u - U_WQ; }
    else if (u < U_WV) { src = wv; h = s_wv_h; l = s_wv_l; off = u - U_WK; }
    else if (u < U_WO) { src = wo; h = s_wo_h; l = s_wo_l; off = u - U_WV; }
    else if (u < U_WG) { src = wg; h = s_wg_h; l = s_wg_l; off = u - U_WO; }
    else if (u < U_WU) { src = wu; h = s_wu_h; l = s_wu_l; off = u - U_WG; }
    else               { src = wd; h = s_wd_h; l = s_wd_l; off = u - U_WU; }

    size_t e = (size_t)off * 16;
    // 4 front-batched 16B loads (MLP=4)
    float4 a0 = ((const float4*)(src + e))[0];
    float4 a1 = ((const float4*)(src + e))[1];
    float4 a2 = ((const float4*)(src + e))[2];
    float4 a3 = ((const float4*)(src + e))[3];
    uint32_t hh[8], ll[8];
    pack_split2(a0.x, a0.y, hh[0], ll[0]);
    pack_split2(a0.z, a0.w, hh[1], ll[1]);
    pack_split2(a1.x, a1.y, hh[2], ll[2]);
    pack_split2(a1.z, a1.w, hh[3], ll[3]);
    pack_split2(a2.x, a2.y, hh[4], ll[4]);
    pack_split2(a2.z, a2.w, hh[5], ll[5]);
    pack_split2(a3.x, a3.y, hh[6], ll[6]);
    pack_split2(a3.z, a3.w, hh[7], ll[7]);
    ((uint4*)(h + e))[0] = make_uint4(hh[0], hh[1], hh[2], hh[3]);
    ((uint4*)(h + e))[1] = make_uint4(hh[4], hh[5], hh[6], hh[7]);
    ((uint4*)(l + e))[0] = make_uint4(ll[0], ll[1], ll[2], ll[3]);
    ((uint4*)(l + e))[1] = make_uint4(ll[4], ll[5], ll[6], ll[7]);
}

// ---------------- 3xBF16 GEMM core (ldmatrix, 2-stage cp.async) -------------
#define RPAD 20
#define ATILE_U (64 * RPAD)                       // 1280
#define BTILE_U (128 * RPAD)                      // 2560
#define STAGE_U (2 * ATILE_U + 2 * BTILE_U)       // 7680 uints
#define GEMM_DSMEM (2 * STAGE_U * 4)              // 61440 B

__device__ __forceinline__ void gemm_tile(float* sm,
                                          const bf16* __restrict__ Ah, const bf16* __restrict__ Al,
                                          const bf16* __restrict__ Bh, const bf16* __restrict__ Bl,
                                          const float* __restrict__ res, float* __restrict__ C,
                                          int N, int K, int bm, int bn) {
    const uint32_t smem_base = smem_u32(sm);
    const int tid  = threadIdx.x;
    const int wid  = tid >> 5;
    const int lane = tid & 31;
    const int wm   = wid >> 2;
    const int wn   = wid & 3;
    const int gid  = lane >> 2;
    const int tig  = lane & 3;
    const int KC   = K >> 5;
    const int lrow = tid >> 2;
    const int lch  = tid & 3;

    const int sub  = lane >> 3;
    const int r8   = lane & 7;
    const int arow = ((sub & 1) << 3) + r8;
    const int akof = (sub >> 1) << 4;
    const int brow = ((sub >> 1) << 3) + r8;
    const int bkof = (sub & 1) << 4;

    uint32_t aaddr[2][2], baddr[2][2];
    #pragma unroll
    for (int mt = 0; mt < 2; mt++) {
        uint32_t base = smem_base + (uint32_t)((wm * 32 + mt * 16 + arow) * RPAD) * 4 + akof;
        aaddr[mt][0] = base;
        aaddr[mt][1] = base + ATILE_U * 4;
    }
    #pragma unroll
    for (int np = 0; np < 2; np++) {
        uint32_t base = smem_base + (uint32_t)(2 * ATILE_U + (wn * 32 + np * 16 + brow) * RPAD) * 4 + bkof;
        baddr[np][0] = base;
        baddr[np][1] = base + BTILE_U * 4;
    }

    float acc[2][4][4];
    #pragma unroll
    for (int i = 0; i < 2; i++)
        #pragma unroll
        for (int j = 0; j < 4; j++)
            #pragma unroll
            for (int k = 0; k < 4; k++) acc[i][j][k] = 0.f;

    auto issue_load = [&](int c, int buf) {
        const int k0 = c << 5;
        uint32_t st = smem_base + buf * (STAGE_U * 4);
        cp_async16(st + (lrow * RPAD + lch * 4) * 4,
                   Ah + (size_t)(bm + lrow) * K + k0 + lch * 8);
        cp_async16(st + (ATILE_U + lrow * RPAD + lch * 4) * 4,
                   Al + (size_t)(bm + lrow) * K + k0 + lch * 8);
        #pragma unroll
        for (int it = 0; it < 2; it++) {
            int br = it * 64 + lrow;
            cp_async16(st + (2 * ATILE_U + br * RPAD + lch * 4) * 4,
                       Bh + (size_t)(bn + br) * K + k0 + lch * 8);
            cp_async16(st + (2 * ATILE_U + BTILE_U + br * RPAD + lch * 4) * 4,
                       Bl + (size_t)(bn + br) * K + k0 + lch * 8);
        }
        CP_ASYNC_COMMIT();
    };

    issue_load(0, 0);

    for (int c = 0; c < KC; c++) {
        const int buf = c & 1;
        CP_ASYNC_WAIT0();
        __syncthreads();
        if (c + 1 < KC) issue_load(c + 1, buf ^ 1);

        const uint32_t boff = (uint32_t)buf * (STAGE_U * 4);

        #pragma unroll
        for (int ks = 0; ks < 2; ks++) {
            const uint32_t koff = boff + ks * 32;
            uint32_t ahf[2][4], alf[2][4], bhf[4][2], blf[4][2];
            #pragma unroll
            for (int mt = 0; mt < 2; mt++) {
                LDMX4(ahf[mt][0], ahf[mt][1], ahf[mt][2], ahf[mt][3], aaddr[mt][0] + koff);
                LDMX4(alf[mt][0], alf[mt][1], alf[mt][2], alf[mt][3], aaddr[mt][1] + koff);
            }
            #pragma unroll
            for (int np = 0; np < 2; np++) {
                LDMX4(bhf[2*np][0], bhf[2*np][1], bhf[2*np+1][0], bhf[2*np+1][1],
                      baddr[np][0] + koff);
                LDMX4(blf[2*np][0], blf[2*np][1], blf[2*np+1][0], blf[2*np+1][1],
                      baddr[np][1] + koff);
            }
            #pragma unroll
            for (int mt = 0; mt < 2; mt++)
                #pragma unroll
                for (int nt = 0; nt < 4; nt++) {
                    mma_bf16(acc[mt][nt][0], acc[mt][nt][1],
                             acc[mt][nt][2], acc[mt][nt][3],
                             ahf[mt][0], ahf[mt][1], ahf[mt][2], ahf[mt][3],
                             blf[nt][0], blf[nt][1]);
                    mma_bf16(acc[mt][nt][0], acc[mt][nt][1],
                             acc[mt][nt][2], acc[mt][nt][3],
                             alf[mt][0], alf[mt][1], alf[mt][2], alf[mt][3],
                             bhf[nt][0], bhf[nt][1]);
                    mma_bf16(acc[mt][nt][0], acc[mt][nt][1],
                             acc[mt][nt][2], acc[mt][nt][3],
                             ahf[mt][0], ahf[mt][1], ahf[mt][2], ahf[mt][3],
                             bhf[nt][0], bhf[nt][1]);
                }
        }
        __syncthreads();
    }

    #pragma unroll
    for (int mt = 0; mt < 2; mt++) {
        int r0 = bm + wm * 32 + mt * 16 + gid;
        #pragma unroll
        for (int nt = 0; nt < 4; nt++) {
            int col = bn + wn * 32 + nt * 8 + tig * 2;
            size_t o0 = (size_t)r0 * N + col;
            size_t o1 = (size_t)(r0 + 8) * N + col;
            float2 v0 = make_float2(acc[mt][nt][0], acc[mt][nt][1]);
            float2 v1 = make_float2(acc[mt][nt][2], acc[mt][nt][3]);
            if (res) {
                float2 r0v = *(const float2*)(res + o0);
                float2 r1v = *(const float2*)(res + o1);
                v0.x += r0v.x; v0.y += r0v.y;
                v1.x += r1v.x; v1.y += r1v.y;
            }
            *(float2*)(C + o0) = v0;
            *(float2*)(C + o1) = v1;
        }
    }
}

__global__ void __launch_bounds__(256, 2)
gemm_mma_kernel(const bf16* __restrict__ Ah, const bf16* __restrict__ Al,
                const bf16* __restrict__ Bh, const bf16* __restrict__ Bl,
                const float* __restrict__ res, float* __restrict__ C,
                int N, int K) {
    extern __shared__ float sm[];
    gemm_tile(sm, Ah, Al, Bh, Bl, res, C, N, K, blockIdx.y * 64, blockIdx.x * 128);
}

__global__ void __launch_bounds__(256, 2)
gemm_qkv_kernel(const bf16* __restrict__ Ah, const bf16* __restrict__ Al,
                float* __restrict__ q, float* __restrict__ k, float* __restrict__ v) {
    extern __shared__ float sm[];
    const int ct = blockIdx.x;
    const bf16 *Bh, *Bl; float* C; int N, bn;
    if (ct < 16)      { Bh = s_wq_h; Bl = s_wq_l; C = q; N = NH  * HD; bn = ct * 128; }
    else if (ct < 20) { Bh = s_wk_h; Bl = s_wk_l; C = k; N = NKV * HD; bn = (ct - 16) * 128; }
    else              { Bh = s_wv_h; Bl = s_wv_l; C = v; N = NKV * HD; bn = (ct - 20) * 128; }
    gemm_tile(sm, Ah, Al, Bh, Bl, nullptr, C, N, H, blockIdx.y * 64, bn);
}

// ---- fused gate/up + SwiGLU ----
__global__ void __launch_bounds__(256, 2)
gemm_gu_silu_kernel(const bf16* __restrict__ Ah, const bf16* __restrict__ Al,
                    bf16* __restrict__ gh, bf16* __restrict__ gl) {
    extern __shared__ float sm[];
    const uint32_t smem_base = smem_u32(sm);
    const int bn = blockIdx.x * 64;
    const int bm = blockIdx.y * 64;
    const int K  = H, KC = K >> 5;

    const int tid  = threadIdx.x;
    const int wid  = tid >> 5;
    const int lane = tid & 31;
    const int wsel = wid >> 2;           // 0 = gate, 1 = up
    const int wq   = wid & 3;
    const int wm   = wq >> 1;
    const int wn   = wq & 1;
    const int gid  = lane >> 2;
    const int tig  = lane & 3;
    const int lrow = tid >> 2;
    const int lch  = tid & 3;

    const int sub  = lane >> 3;
    const int r8   = lane & 7;
    const int arow = ((sub & 1) << 3) + r8;
    const int akof = (sub >> 1) << 4;
    const int brow = ((sub >> 1) << 3) + r8;
    const int bkof = (sub & 1) << 4;

    uint32_t aaddr[2][2], baddr[2][2];
    #pragma unroll
    for (int mt = 0; mt < 2; mt++) {
        uint32_t base = smem_base + (uint32_t)((wm * 32 + mt * 16 + arow) * RPAD) * 4 + akof;
        aaddr[mt][0] = base;
        aaddr[mt][1] = base + ATILE_U * 4;
    }
    #pragma unroll
    for (int np = 0; np < 2; np++) {
        uint32_t base = smem_base +
            (uint32_t)((2 + 2 * wsel) * ATILE_U + (wn * 32 + np * 16 + brow) * RPAD) * 4 + bkof;
        baddr[np][0] = base;
        baddr[np][1] = base + ATILE_U * 4;
    }

    const bf16* Bgh = s_wg_h; const bf16* Bgl = s_wg_l;
    const bf16* Buh = s_wu_h; const bf16* Bul = s_wu_l;

    float acc[2][4][4];
    #pragma unroll
    for (int i = 0; i < 2; i++)
        #pragma unroll
        for (int j = 0; j < 4; j++)
            #pragma unroll
            for (int k = 0; k < 4; k++) acc[i][j][k] = 0.f;

    auto issue_load = [&](int c, int buf) {
        const int k0 = c << 5;
        uint32_t st = smem_base + buf * (STAGE_U * 4);
        cp_async16(st + (0 * ATILE_U + lrow * RPAD + lch * 4) * 4,
                   Ah + (size_t)(bm + lrow) * K + k0 + lch * 8);
        cp_async16(st + (1 * ATILE_U + lrow * RPAD + lch * 4) * 4,
                   Al + (size_t)(bm + lrow) * K + k0 + lch * 8);
        cp_async16(st + (2 * ATILE_U + lrow * RPAD + lch * 4) * 4,
                   Bgh + (size_t)(bn + lrow) * K + k0 + lch * 8);
        cp_async16(st + (3 * ATILE_U + lrow * RPAD + lch * 4) * 4,
                   Bgl + (size_t)(bn + lrow) * K + k0 + lch * 8);
        cp_async16(st + (4 * ATILE_U + lrow * RPAD + lch * 4) * 4,
                   Buh + (size_t)(bn + lrow) * K + k0 + lch * 8);
        cp_async16(st + (5 * ATILE_U + lrow * RPAD + lch * 4) * 4,
                   Bul + (size_t)(bn + lrow) * K + k0 + lch * 8);
        CP_ASYNC_COMMIT();
    };

    issue_load(0, 0);

    for (int c = 0; c < KC; c++) {
        const int buf = c & 1;
        CP_ASYNC_WAIT0();
        __syncthreads();
        if (c + 1 < KC) issue_load(c + 1, buf ^ 1);

        const uint32_t boff = (uint32_t)buf * (STAGE_U * 4);

        #pragma unroll
        for (int ks = 0; ks < 2; ks++) {
            const uint32_t koff = boff + ks * 32;
            uint32_t ahf[2][4], alf[2][4], bhf[4][2], blf[4][2];
            #pragma unroll
            for (int mt = 0; mt < 2; mt++) {
                LDMX4(ahf[mt][0], ahf[mt][1], ahf[mt][2], ahf[mt][3], aaddr[mt][0] + koff);
                LDMX4(alf[mt][0], alf[mt][1], alf[mt][2], alf[mt][3], aaddr[mt][1] + koff);
            }
            #pragma unroll
            for (int np = 0; np < 2; np++) {
                LDMX4(bhf[2*np][0], bhf[2*np][1], bhf[2*np+1][0], bhf[2*np+1][1],
                      baddr[np][0] + koff);
                LDMX4(blf[2*np][0], blf[2*np][1], blf[2*np+1][0], blf[2*np+1][1],
                      baddr[np][1] + koff);
            }
            #pragma unroll
            for (int mt = 0; mt < 2; mt++)
                #pragma unroll
                for (int nt = 0; nt < 4; nt++) {
                    mma_bf16(acc[mt][nt][0], acc[mt][nt][1],
                             acc[mt][nt][2], acc[mt][nt][3],
                             ahf[mt][0], ahf[mt][1], ahf[mt][2], ahf[mt][3],
                             blf[nt][0], blf[nt][1]);
                    mma_bf16(acc[mt][nt][0], acc[mt][nt][1],
                             acc[mt][nt][2], acc[mt][nt][3],
                             alf[mt][0], alf[mt][1], alf[mt][2], alf[mt][3],
                             bhf[nt][0], bhf[nt][1]);
                    mma_bf16(acc[mt][nt][0], acc[mt][nt][1],
                             acc[mt][nt][2], acc[mt][nt][3],
                             ahf[mt][0], ahf[mt][1], ahf[mt][2], ahf[mt][3],
                             bhf[nt][0], bhf[nt][1]);
                }
        }
        __syncthreads();
    }

    float (*sx)[66] = (float (*)[66])sm;
    __syncthreads();
    if (wsel == 0) {
        #pragma unroll
        for (int mt = 0; mt < 2; mt++) {
            int lr = wm * 32 + mt * 16 + gid;
            #pragma unroll
            for (int nt = 0; nt < 4; nt++) {
                int lc = wn * 32 + nt * 8 + tig * 2;
                sx[lr][lc]     = acc[mt][nt][0];
                sx[lr][lc + 1] = acc[mt][nt][1];
                sx[lr + 8][lc]     = acc[mt][nt][2];
                sx[lr + 8][lc + 1] = acc[mt][nt][3];
            }
        }
    }
    __syncthreads();
    if (wsel == 1) {
        #pragma unroll
        for (int mt = 0; mt < 2; mt++) {
            int lr = wm * 32 + mt * 16 + gid;
            #pragma unroll
            for (int nt = 0; nt < 4; nt++) {
                int lc = wn * 32 + nt * 8 + tig * 2;
                float g0 = sx[lr][lc],     g1 = sx[lr][lc + 1];
                float g2 = sx[lr + 8][lc], g3 = sx[lr + 8][lc + 1];
                float r0 = g0 / (1.f + __expf(-g0)) * acc[mt][nt][0];
                float r1 = g1 / (1.f + __expf(-g1)) * acc[mt][nt][1];
                float r2 = g2 / (1.f + __expf(-g2)) * acc[mt][nt][2];
                float r3 = g3 / (1.f + __expf(-g3)) * acc[mt][nt][3];
                size_t o0 = (size_t)(bm + lr)     * IM + bn + lc;
                size_t o1 = (size_t)(bm + lr + 8) * IM + bn + lc;
                split_store2(gh, gl, o0, r0, r1);
                split_store2(gh, gl, o1, r2, r3);
            }
        }
    }
}

// ---------------- RMSNorm with split output ----------------
__global__ void rmsnorm_split_kernel(const float* __restrict__ x,
                                     const float* __restrict__ w,
                                     bf16* __restrict__ oh, bf16* __restrict__ ol) {
    int row = blockIdx.x;
    const float* xr = x + (size_t)row * H;
    float ss = 0.f;
    for (int i = threadIdx.x; i < H / 4; i += blockDim.x) {
        float4 v = ((const float4*)xr)[i];
        ss += v.x * v.x + v.y * v.y + v.z * v.z + v.w * v.w;
    }
    __shared__ float red[32];
    #pragma unroll
    for (int o = 16; o; o >>= 1) ss += __shfl_xor_sync(0xffffffffu, ss, o);
    if ((threadIdx.x & 31) == 0) red[threadIdx.x >> 5] = ss;
    __syncthreads();
    if (threadIdx.x < 32) {
        float v = (threadIdx.x < (blockDim.x >> 5)) ? red[threadIdx.x] : 0.f;
        #pragma unroll
        for (int o = 16; o; o >>= 1) v += __shfl_xor_sync(0xffffffffu, v, o);
        if (threadIdx.x == 0) red[0] = v;
    }
    __syncthreads();
    float r = rsqrtf(red[0] / (float)H + 1e-6f);
    for (int i = threadIdx.x; i < H / 4; i += blockDim.x) {
        float4 v = ((const float4*)xr)[i];
        float4 wv = ((const float4*)w)[i];
        split_store4(oh, ol, (size_t)row * H + 4 * i,
                     v.x * r * wv.x, v.y * r * wv.y, v.z * r * wv.z, v.w * r * wv.w);
    }
}

// ---------------- merged RoPE (q part + kv part in one launch) ---------------
#define ROPE_Q_BLOCKS  ((B * T * NH  * (HD / 2)) / 256)   // 8192
#define ROPE_KV_BLOCKS ((B * T * NKV * (HD / 2)) / 256)   // 2048

__global__ void __launch_bounds__(256)
rope_all_kernel(const float* __restrict__ q, const float* __restrict__ k,
                const float* __restrict__ v,
                const float* __restrict__ cosp, const float* __restrict__ sinp,
                const int* __restrict__ pos,
                float* __restrict__ outk, float* __restrict__ outv,
                bf16* __restrict__ qh, bf16* __restrict__ ql,
                bf16* __restrict__ kh, bf16* __restrict__ kl,
                bf16* __restrict__ vth, bf16* __restrict__ vtl) {
    if (blockIdx.x < ROPE_Q_BLOCKS) {
        int idx = blockIdx.x * 256 + threadIdx.x;
        int d2 = idx & 31;
        int h  = (idx >> 5) & (NH - 1);
        int bt = idx >> 10;
        int t  = bt & (T - 1);
        int b  = bt >> 10;
        int p  = pos[bt];
        float c = cosp[p * 32 + d2], s = sinp[p * 32 + d2];
        size_t base = (size_t)bt * (NH * HD) + h * HD + 2 * d2;
        float x1 = q[base], x2 = q[base + 1];
        float r1 = x1 * c - x2 * s;
        float r2 = x1 * s + x2 * c;
        size_t ob = ((size_t)(b * NH + h) * T + t) * HD + 2 * d2;
        split_store2(qh, ql, ob, r1, r2);
    } else {
        int idx = (blockIdx.x - ROPE_Q_BLOCKS) * 256 + threadIdx.x;
        int d2 = idx & 31;
        int h  = (idx >> 5) & (NKV - 1);
        int bt = idx >> 8;
        int t  = bt & (T - 1);
        int b  = bt >> 10;
        int p  = pos[bt];
        float c = cosp[p * 32 + d2], s = sinp[p * 32 + d2];
        size_t base = (size_t)bt * (NKV * HD) + h * HD + 2 * d2;
        float x1 = k[base], x2 = k[base + 1];
        float r1 = x1 * c - x2 * s;
        float r2 = x1 * s + x2 * c;
        size_t ob = ((size_t)(b * NKV + h) * T + t) * HD + 2 * d2;
        outk[ob] = r1;       outk[ob + 1] = r2;
        split_store2(kh, kl, ob, r1, r2);
        float v1 = v[base], v2 = v[base + 1];
        outv[ob] = v1;       outv[ob + 1] = v2;
        size_t vb = ((size_t)(b * NKV + h) * HD + 2 * d2) * T + t;
        bf16 vh1 = __float2bfloat16(v1);
        bf16 vh2 = __float2bfloat16(v2);
        vth[vb]     = vh1; vtl[vb]     = __float2bfloat16(v1 - __bfloat162float(vh1));
        vth[vb + T] = vh2; vtl[vb + T] = __float2bfloat16(v2 - __bfloat162float(vh2));
    }
}

// ---------------- Flash attention (3xBF16 mma, 64 q rows/CTA, 4 warps) ------
#define AT_RPAD 36
#define AT_TILE_U (64 * AT_RPAD)
#define ATTN_DSMEM (6 * AT_TILE_U * 4)

__global__ void __launch_bounds__(128)
attn_kernel(const bf16* __restrict__ Qh_g, const bf16* __restrict__ Ql_g,
            const bf16* __restrict__ Kh_g, const bf16* __restrict__ Kl_g,
            const bf16* __restrict__ Vth_g, const bf16* __restrict__ Vtl_g,
            bf16* __restrict__ Oh, bf16* __restrict__ Ol) {
    extern __shared__ uint32_t smu[];
    const int qt = blockIdx.x, h = blockIdx.y, b = blockIdx.z;
    const int kvh = h >> 2;
    const int tid = threadIdx.x, wid = tid >> 5, lane = tid & 31;
    const int gid = lane >> 2, tig = lane & 3;
    const int sub = lane >> 3, r8 = lane & 7;
    const int arow = ((sub & 1) << 3) + r8;
    const int akof = (sub >> 1) << 4;
    const int brow = ((sub >> 1) << 3) + r8;
    const int bkof = (sub & 1) << 4;

    const uint32_t smem_base = smem_u32(smu);
    const uint32_t Qh_s = smem_base;
    const uint32_t Ql_s = Qh_s + AT_TILE_U * 4;
    const uint32_t Kh_s = Ql_s + AT_TILE_U * 4;
    const uint32_t Kl_s = Kh_s + AT_TILE_U * 4;
    const uint32_t Vh_s = Kl_s + AT_TILE_U * 4;
    const uint32_t Vl_s = Vh_s + AT_TILE_U * 4;

    {
        const bf16* qh = Qh_g + ((size_t)(b * NH + h) * T + qt * 64) * HD;
        const bf16* ql = Ql_g + ((size_t)(b * NH + h) * T + qt * 64) * HD;
        #pragma unroll
        for (int it = 0; it < 4; it++) {
            int idx = tid + it * 128;
            int row = idx >> 3, ch = idx & 7;
            cp_async16(Qh_s + (row * AT_RPAD + ch * 4) * 4, qh + (size_t)row * HD + ch * 8);
            cp_async16(Ql_s + (row * AT_RPAD + ch * 4) * 4, ql + (size_t)row * HD + ch * 8);
        }
        CP_ASYNC_COMMIT();
        CP_ASYNC_WAIT0();
        __syncthreads();
    }
    uint32_t qfh[4][4], qfl[4][4];
    {
        uint32_t qa = (uint32_t)((wid * 16 + arow) * AT_RPAD) * 4 + akof;
        #pragma unroll
        for (int ks = 0; ks < 4; ks++) {
            LDMX4(qfh[ks][0], qfh[ks][1], qfh[ks][2], qfh[ks][3], Qh_s + qa + ks * 32);
            LDMX4(qfl[ks][0], qfl[ks][1], qfl[ks][2], qfl[ks][3], Ql_s + qa + ks * 32);
        }
    }

    float oacc[8][4];
    #pragma unroll
    for (int i = 0; i < 8; i++)
        #pragma unroll
        for (int j = 0; j < 4; j++) oacc[i][j] = 0.f;
    float rm0 = -1e30f, rm1 = -1e30f, rs0 = 0.f, rs1 = 0.f;

    for (int kt = 0; kt <= qt; kt++) {
        __syncthreads();
        {
            const bf16* kh  = Kh_g  + ((size_t)(b * NKV + kvh) * T + kt * 64) * HD;
            const bf16* kl  = Kl_g  + ((size_t)(b * NKV + kvh) * T + kt * 64) * HD;
            const bf16* vth = Vth_g + (size_t)(b * NKV + kvh) * HD * T;
            const bf16* vtl = Vtl_g + (size_t)(b * NKV + kvh) * HD * T;
            #pragma unroll
            for (int it = 0; it < 4; it++) {
                int idx = tid + it * 128;
                int row = idx >> 3, ch = idx & 7;
                uint32_t soff = (row * AT_RPAD + ch * 4) * 4;
                cp_async16(Kh_s + soff, kh + (size_t)row * HD + ch * 8);
                cp_async16(Kl_s + soff, kl + (size_t)row * HD + ch * 8);
                cp_async16(Vh_s + soff, vth + (size_t)row * T + kt * 64 + ch * 8);
                cp_async16(Vl_s + soff, vtl + (size_t)row * T + kt * 64 + ch * 8);
            }
            CP_ASYNC_COMMIT();
            CP_ASYNC_WAIT0();
            __syncthreads();
        }

        float sacc[8][4];
        #pragma unroll
        for (int i = 0; i < 8; i++)
            #pragma unroll
            for (int j = 0; j < 4; j++) sacc[i][j] = 0.f;

        #pragma unroll
        for (int ks = 0; ks < 4; ks++) {
            uint32_t kfh[8][2], kfl[8][2];
            #pragma unroll
            for (int np = 0; np < 4; np++) {
                uint32_t ka = (uint32_t)((np * 16 + brow) * AT_RPAD) * 4 + bkof + ks * 32;
                LDMX4(kfh[2*np][0], kfh[2*np][1], kfh[2*np+1][0], kfh[2*np+1][1], Kh_s + ka);
                LDMX4(kfl[2*np][0], kfl[2*np][1], kfl[2*np+1][0], kfl[2*np+1][1], Kl_s + ka);
            }
            #pragma unroll
            for (int nt = 0; nt < 8; nt++) {
                mma_bf16(sacc[nt][0], sacc[nt][1], sacc[nt][2], sacc[nt][3],
                         qfh[ks][0], qfh[ks][1], qfh[ks][2], qfh[ks][3],
                         kfl[nt][0], kfl[nt][1]);
                mma_bf16(sacc[nt][0], sacc[nt][1], sacc[nt][2], sacc[nt][3],
                         qfl[ks][0], qfl[ks][1], qfl[ks][2], qfl[ks][3],
                         kfh[nt][0], kfh[nt][1]);
                mma_bf16(sacc[nt][0], sacc[nt][1], sacc[nt][2], sacc[nt][3],
                         qfh[ks][0], qfh[ks][1], qfh[ks][2], qfh[ks][3],
                         kfh[nt][0], kfh[nt][1]);
            }
        }

        const float scale = 0.125f;
        if (kt == qt) {
            #pragma unroll
            for (int nt = 0; nt < 8; nt++)
                #pragma unroll
                for (int c = 0; c < 4; c++) {
                    int col = 8 * nt + 2 * tig + (c & 1);
                    int row = wid * 16 + gid + ((c >> 1) << 3);
                    sacc[nt][c] = (col <= row) ? sacc[nt][c] * scale : -1e30f;
                }
        } else {
            #pragma unroll
            for (int nt = 0; nt < 8; nt++)
                #pragma unroll
                for (int c = 0; c < 4; c++) sacc[nt][c] *= scale;
        }

        float mx0 = -1e30f, mx1 = -1e30f;
        #pragma unroll
        for (int nt = 0; nt < 8; nt++) {
            mx0 = fmaxf(mx0, fmaxf(sacc[nt][0], sacc[nt][1]));
            mx1 = fmaxf(mx1, fmaxf(sacc[nt][2], sacc[nt][3]));
        }
        mx0 = fmaxf(mx0, __shfl_xor_sync(0xffffffffu, mx0, 1));
        mx0 = fmaxf(mx0, __shfl_xor_sync(0xffffffffu, mx0, 2));
        mx1 = fmaxf(mx1, __shfl_xor_sync(0xffffffffu, mx1, 1));
        mx1 = fmaxf(mx1, __shfl_xor_sync(0xffffffffu, mx1, 2));
        float nrm0 = fmaxf(rm0, mx0), nrm1 = fmaxf(rm1, mx1);
        float al0 = __expf(rm0 - nrm0), al1 = __expf(rm1 - nrm1);
        rm0 = nrm0; rm1 = nrm1;

        float p[8][4];
        float sum0 = 0.f, sum1 = 0.f;
        #pragma unroll
        for (int nt = 0; nt < 8; nt++) {
            p[nt][0] = __expf(sacc[nt][0] - nrm0); sum0 += p[nt][0];
            p[nt][1] = __expf(sacc[nt][1] - nrm0); sum0 += p[nt][1];
            p[nt][2] = __expf(sacc[nt][2] - nrm1); sum1 += p[nt][2];
            p[nt][3] = __expf(sacc[nt][3] - nrm1); sum1 += p[nt][3];
        }
        sum0 += __shfl_xor_sync(0xffffffffu, sum0, 1);
        sum0 += __shfl_xor_sync(0xffffffffu, sum0, 2);
        sum1 += __shfl_xor_sync(0xffffffffu, sum1, 1);
        sum1 += __shfl_xor_sync(0xffffffffu, sum1, 2);
        rs0 = rs0 * al0 + sum0;
        rs1 = rs1 * al1 + sum1;
        #pragma unroll
        for (int nt = 0; nt < 8; nt++) {
            oacc[nt][0] *= al0; oacc[nt][1] *= al0;
            oacc[nt][2] *= al1; oacc[nt][3] *= al1;
        }

        uint32_t ph[4][4], pl[4][4];
        #pragma unroll
        for (int ks = 0; ks < 4; ks++) {
            pack_split2(p[2*ks][0],   p[2*ks][1],   ph[ks][0], pl[ks][0]);
            pack_split2(p[2*ks][2],   p[2*ks][3],   ph[ks][1], pl[ks][1]);
            pack_split2(p[2*ks+1][0], p[2*ks+1][1], ph[ks][2], pl[ks][2]);
            pack_split2(p[2*ks+1][2], p[2*ks+1][3], ph[ks][3], pl[ks][3]);
        }

        #pragma unroll
        for (int ks = 0; ks < 4; ks++) {
            uint32_t vfh[8][2], vfl[8][2];
            #pragma unroll
            for (int np = 0; np < 4; np++) {
                uint32_t va = (uint32_t)((np * 16 + brow) * AT_RPAD) * 4 + bkof + ks * 32;
                LDMX4(vfh[2*np][0], vfh[2*np][1], vfh[2*np+1][0], vfh[2*np+1][1], Vh_s + va);
                LDMX4(vfl[2*np][0], vfl[2*np][1], vfl[2*np+1][0], vfl[2*np+1][1], Vl_s + va);
            }
            #pragma unroll
            for (int nt = 0; nt < 8; nt++) {
                mma_bf16(oacc[nt][0], oacc[nt][1], oacc[nt][2], oacc[nt][3],
                         ph[ks][0], ph[ks][1], ph[ks][2], ph[ks][3],
                         vfl[nt][0], vfl[nt][1]);
                mma_bf16(oacc[nt][0], oacc[nt][1], oacc[nt][2], oacc[nt][3],
                         pl[ks][0], pl[ks][1], pl[ks][2], pl[ks][3],
                         vfh[nt][0], vfh[nt][1]);
                mma_bf16(oacc[nt][0], oacc[nt][1], oacc[nt][2], oacc[nt][3],
                         ph[ks][0], ph[ks][1], ph[ks][2], ph[ks][3],
                         vfh[nt][0], vfh[nt][1]);
            }
        }
    }

    float inv0 = 1.f / rs0, inv1 = 1.f / rs1;
    int trow0 = qt * 64 + wid * 16 + gid;
    #pragma unroll
    for (int nt = 0; nt < 8; nt++) {
        int col = 8 * nt + 2 * tig;
        size_t o0 = ((size_t)(b * T + trow0))     * (NH * HD) + h * HD + col;
        size_t o1 = ((size_t)(b * T + trow0 + 8)) * (NH * HD) + h * HD + col;
        split_store2(Oh, Ol, o0, oacc[nt][0] * inv0, oacc[nt][1] * inv0);
        split_store2(Oh, Ol, o1, oacc[nt][2] * inv1, oacc[nt][3] * inv1);
    }
}

// ---------------- launch ----------------
extern "C" void kernel_launch(void* const* d_in, const int* in_sizes, int n_in,
                              void* d_out, int out_size) {
    const float* hs   = (const float*)d_in[0];
    const float* cosp = (const float*)d_in[1];
    const float* sinp = (const float*)d_in[2];
    const int*   pos  = (const int*)  d_in[3];
    const float* n1w  = (const float*)d_in[5];
    const float* wq   = (const float*)d_in[6];
    const float* wk   = (const float*)d_in[7];
    const float* wv   = (const float*)d_in[8];
    const float* wo   = (const float*)d_in[9];
    const float* n2w  = (const float*)d_in[10];
    const float* wg   = (const float*)d_in[11];
    const float* wu   = (const float*)d_in[12];
    const float* wd   = (const float*)d_in[13];

    float *q, *k, *v, *h2;
    cudaGetSymbolAddress((void**)&q,  g_q);
    cudaGetSymbolAddress((void**)&k,  g_k);
    cudaGetSymbolAddress((void**)&v,  g_v);
    cudaGetSymbolAddress((void**)&h2, g_h2);

    bf16 *woh,*wol,*wdh,*wdl;
    bf16 *xnh,*xnl,*ath,*atl,*xn2h,*xn2l,*gh,*gl;
    bf16 *qh,*ql,*kh,*kl,*vth,*vtl;
    cudaGetSymbolAddress((void**)&woh, s_wo_h);  cudaGetSymbolAddress((void**)&wol, s_wo_l);
    cudaGetSymbolAddress((void**)&wdh, s_wd_h);  cudaGetSymbolAddress((void**)&wdl, s_wd_l);
    cudaGetSymbolAddress((void**)&xnh, s_xn_h);  cudaGetSymbolAddress((void**)&xnl, s_xn_l);
    cudaGetSymbolAddress((void**)&ath, s_at_h);  cudaGetSymbolAddress((void**)&atl, s_at_l);
    cudaGetSymbolAddress((void**)&xn2h, s_xn2_h);cudaGetSymbolAddress((void**)&xn2l, s_xn2_l);
    cudaGetSymbolAddress((void**)&gh,  s_g_h);   cudaGetSymbolAddress((void**)&gl,  s_g_l);
    cudaGetSymbolAddress((void**)&qh,  s_q_h);   cudaGetSymbolAddress((void**)&ql,  s_q_l);
    cudaGetSymbolAddress((void**)&kh,  s_k_h);   cudaGetSymbolAddress((void**)&kl,  s_k_l);
    cudaGetSymbolAddress((void**)&vth, s_vt_h);  cudaGetSymbolAddress((void**)&vtl, s_vt_l);

    float* out_x = (float*)d_out;
    float* out_k = out_x + (size_t)M * H;
    float* out_v = out_k + (size_t)B * NKV * T * HD;

    cudaFuncSetAttribute(gemm_mma_kernel,
                         cudaFuncAttributeMaxDynamicSharedMemorySize, GEMM_DSMEM);
    cudaFuncSetAttribute(gemm_qkv_kernel,
                         cudaFuncAttributeMaxDynamicSharedMemorySize, GEMM_DSMEM);
    cudaFuncSetAttribute(gemm_gu_silu_kernel,
                         cudaFuncAttributeMaxDynamicSharedMemorySize, GEMM_DSMEM);
    cudaFuncSetAttribute(attn_kernel,
                         cudaFuncAttributeMaxDynamicSharedMemorySize, ATTN_DSMEM);

    // 0. split ALL weights in one launch
    split_all_kernel<<<SPLIT_BLOCKS, 256>>>(wq, wk, wv, wo, wg, wu, wd);
    // 1. RMSNorm 1
    rmsnorm_split_kernel<<<M, 256>>>(hs, n1w, xnh, xnl);
    // 2. fused Q/K/V projections
    gemm_qkv_kernel<<<dim3(24, M / 64), 256, GEMM_DSMEM>>>(xnh, xnl, q, k, v);
    // 3. merged RoPE (q + kv) + KV-cache writeout + bf16 splits
    rope_all_kernel<<<ROPE_Q_BLOCKS + ROPE_KV_BLOCKS, 256>>>(q, k, v, cosp, sinp, pos,
                                                             out_k, out_v,
                                                             qh, ql, kh, kl, vth, vtl);
    // 4. Attention (tensor-core, 3xBF16)
    attn_kernel<<<dim3(T / 64, NH, B), 128, ATTN_DSMEM>>>(qh, ql, kh, kl, vth, vtl, ath, atl);
    // 5. O-projection + residual
    gemm_mma_kernel<<<dim3(H / 128, M / 64), 256, GEMM_DSMEM>>>(ath, atl, woh, wol,
                                                                hs, h2, H, NH * HD);
    // 6. RMSNorm 2
    rmsnorm_split_kernel<<<M, 256>>>(h2, n2w, xn2h, xn2l);
    // 7. fused MLP gate/up + SwiGLU
    gemm_gu_silu_kernel<<<dim3(IM / 64, M / 64), 256, GEMM_DSMEM>>>(xn2h, xn2l, gh, gl);
    // 8. Down projection + residual -> x output
    gemm_mma_kernel<<<dim3(H / 128, M / 64), 256, GEMM_DSMEM>>>(gh, gl, wdh, wdl,
                                                                h2, out_x, H, IM);
}

// round 13
// speedup vs baseline: 1.0267x; 1.0075x over previous
#include <cuda_runtime.h>
#include <cuda_bf16.h>
#include <math.h>
#include <stdint.h>

#define B   2
#define T   1024
#define H   2048
#define NH  32
#define NKV 8
#define HD  64
#define IM  8192
#define M   (B*T)

typedef __nv_bfloat16  bf16;
typedef __nv_bfloat162 bf162;

// ---------------- scratch (device globals; no allocation) ----------------
__device__ __align__(16) float g_h2 [M * H];
// bf16 hi/lo split weights
__device__ __align__(16) bf16 s_wq_h[NH*HD*H],  s_wq_l[NH*HD*H];
__device__ __align__(16) bf16 s_wk_h[NKV*HD*H], s_wk_l[NKV*HD*H];
__device__ __align__(16) bf16 s_wv_h[NKV*HD*H], s_wv_l[NKV*HD*H];
__device__ __align__(16) bf16 s_wo_h[H*NH*HD],  s_wo_l[H*NH*HD];
__device__ __align__(16) bf16 s_wg_h[(size_t)IM*H], s_wg_l[(size_t)IM*H];
__device__ __align__(16) bf16 s_wu_h[(size_t)IM*H], s_wu_l[(size_t)IM*H];
__device__ __align__(16) bf16 s_wd_h[(size_t)H*IM], s_wd_l[(size_t)H*IM];
// bf16 hi/lo split activations
__device__ __align__(16) bf16 s_xn_h [M*H],        s_xn_l [M*H];
__device__ __align__(16) bf16 s_at_h [M*NH*HD],    s_at_l [M*NH*HD];
__device__ __align__(16) bf16 s_xn2_h[M*H],        s_xn2_l[M*H];
__device__ __align__(16) bf16 s_g_h  [(size_t)M*IM], s_g_l[(size_t)M*IM];
// bf16 hi/lo split q/k/v for attention (head-major; v transposed)
__device__ __align__(16) bf16 s_q_h [M*NH*HD],  s_q_l [M*NH*HD];
__device__ __align__(16) bf16 s_k_h [M*NKV*HD], s_k_l [M*NKV*HD];
__device__ __align__(16) bf16 s_vt_h[M*NKV*HD], s_vt_l[M*NKV*HD];

// ---------------- helpers ----------------
__device__ __forceinline__ uint32_t smem_u32(const void* p) {
    uint32_t a;
    asm("{ .reg .u64 t; cvta.to.shared.u64 t, %1; cvt.u32.u64 %0, t; }"
        : "=r"(a) : "l"(p));
    return a;
}
__device__ __forceinline__ void cp_async16(uint32_t dst, const void* src) {
    asm volatile("cp.async.cg.shared.global [%0], [%1], 16;"
                 :: "r"(dst), "l"(src));
}
#define CP_ASYNC_COMMIT() asm volatile("cp.async.commit_group;" ::: "memory")
#define CP_ASYNC_WAIT0()  asm volatile("cp.async.wait_group 0;" ::: "memory")

#define LDMX4(r0, r1, r2, r3, addr) \
    asm volatile("ldmatrix.sync.aligned.m8n8.x4.shared.b16 {%0,%1,%2,%3}, [%4];" \
        : "=r"(r0), "=r"(r1), "=r"(r2), "=r"(r3) : "r"(addr))

__device__ __forceinline__ void mma_bf16(float& c0, float& c1, float& c2, float& c3,
                                         uint32_t a0, uint32_t a1, uint32_t a2, uint32_t a3,
                                         uint32_t b0, uint32_t b1) {
    asm volatile(
        "mma.sync.aligned.m16n8k16.row.col.f32.bf16.bf16.f32 "
        "{%0,%1,%2,%3}, {%4,%5,%6,%7}, {%8,%9}, {%0,%1,%2,%3};"
        : "+f"(c0), "+f"(c1), "+f"(c2), "+f"(c3)
        : "r"(a0), "r"(a1), "r"(a2), "r"(a3), "r"(b0), "r"(b1));
}

// split-store helpers (fp32 -> hi/lo bf16)
__device__ __forceinline__ void split_store4(bf16* __restrict__ h, bf16* __restrict__ l,
                                             size_t idx, float x, float y, float z, float w) {
    bf162 h0 = __floats2bfloat162_rn(x, y);
    bf162 h1 = __floats2bfloat162_rn(z, w);
    float lx = x - __bfloat162float(__low2bfloat16(h0));
    float ly = y - __bfloat162float(__high2bfloat16(h0));
    float lz = z - __bfloat162float(__low2bfloat16(h1));
    float lw = w - __bfloat162float(__high2bfloat16(h1));
    *(bf162*)(h + idx)     = h0;
    *(bf162*)(h + idx + 2) = h1;
    *(bf162*)(l + idx)     = __floats2bfloat162_rn(lx, ly);
    *(bf162*)(l + idx + 2) = __floats2bfloat162_rn(lz, lw);
}
__device__ __forceinline__ void split_store2(bf16* __restrict__ h, bf16* __restrict__ l,
                                             size_t idx, float x, float y) {
    bf162 h0 = __floats2bfloat162_rn(x, y);
    float lx = x - __bfloat162float(__low2bfloat16(h0));
    float ly = y - __bfloat162float(__high2bfloat16(h0));
    *(bf162*)(h + idx) = h0;
    *(bf162*)(l + idx) = __floats2bfloat162_rn(lx, ly);
}
__device__ __forceinline__ void pack_split2(float x, float y, uint32_t& hi, uint32_t& lo) {
    bf162 h0 = __floats2bfloat162_rn(x, y);
    float lx = x - __bfloat162float(__low2bfloat16(h0));
    float ly = y - __bfloat162float(__high2bfloat16(h0));
    bf162 l0 = __floats2bfloat162_rn(lx, ly);
    hi = *(uint32_t*)&h0;
    lo = *(uint32_t*)&l0;
}

// ---------------- merged weight-split kernel ----------------
#define U_WQ  262144
#define U_WK  (U_WQ + 65536)
#define U_WV  (U_WK + 65536)
#define U_WO  (U_WV + 262144)
#define U_WG  (U_WO + 1048576)
#define U_WU  (U_WG + 1048576)
#define U_WD  (U_WU + 1048576)
#define SPLIT_BLOCKS (U_WD / 256)

__global__ void __launch_bounds__(256)
split_all_kernel(const float* __restrict__ wq, const float* __restrict__ wk,
                 const float* __restrict__ wv, const float* __restrict__ wo,
                 const float* __restrict__ wg, const float* __restrict__ wu,
                 const float* __restrict__ wd) {
    uint32_t u = blockIdx.x * 256 + threadIdx.x;
    const float* src; bf16 *h, *l; uint32_t off;
    if (u < U_WQ)      { src = wq; h = s_wq_h; l = s_wq_l; off = u; }
    else if (u < U_WK) { src = wk; h = s_wk_h; l = s_wk_l; off = u - U_WQ; }
    else if (u < U_WV) { src = wv; h = s_wv_h; l = s_wv_l; off = u - U_WK; }
    else if (u < U_WO) { src = wo; h = s_wo_h; l = s_wo_l; off = u - U_WV; }
    else if (u < U_WG) { src = wg; h = s_wg_h; l = s_wg_l; off = u - U_WO; }
    else if (u < U_WU) { src = wu; h = s_wu_h; l = s_wu_l; off = u - U_WG; }
    else               { src = wd; h = s_wd_h; l = s_wd_l; off = u - U_WU; }

    size_t e = (size_t)off * 16;
    float4 a0 = ((const float4*)(src + e))[0];
    float4 a1 = ((const float4*)(src + e))[1];
    float4 a2 = ((const float4*)(src + e))[2];
    float4 a3 = ((const float4*)(src + e))[3];
    uint32_t hh[8], ll[8];
    pack_split2(a0.x, a0.y, hh[0], ll[0]);
    pack_split2(a0.z, a0.w, hh[1], ll[1]);
    pack_split2(a1.x, a1.y, hh[2], ll[2]);
    pack_split2(a1.z, a1.w, hh[3], ll[3]);
    pack_split2(a2.x, a2.y, hh[4], ll[4]);
    pack_split2(a2.z, a2.w, hh[5], ll[5]);
    pack_split2(a3.x, a3.y, hh[6], ll[6]);
    pack_split2(a3.z, a3.w, hh[7], ll[7]);
    ((uint4*)(h + e))[0] = make_uint4(hh[0], hh[1], hh[2], hh[3]);
    ((uint4*)(h + e))[1] = make_uint4(hh[4], hh[5], hh[6], hh[7]);
    ((uint4*)(l + e))[0] = make_uint4(ll[0], ll[1], ll[2], ll[3]);
    ((uint4*)(l + e))[1] = make_uint4(ll[4], ll[5], ll[6], ll[7]);
}

// ---------------- 3xBF16 GEMM mainloop (ldmatrix, 2-stage cp.async) ---------
#define RPAD 20
#define ATILE_U (64 * RPAD)
#define BTILE_U (128 * RPAD)
#define STAGE_U (2 * ATILE_U + 2 * BTILE_U)
#define GEMM_DSMEM (2 * STAGE_U * 4)

__device__ __forceinline__ void gemm_mainloop(float* sm,
                                              const bf16* __restrict__ Ah, const bf16* __restrict__ Al,
                                              const bf16* __restrict__ Bh, const bf16* __restrict__ Bl,
                                              int K, int bm, int bn,
                                              float (&acc)[2][4][4]) {
    const uint32_t smem_base = smem_u32(sm);
    const int tid  = threadIdx.x;
    const int wid  = tid >> 5;
    const int lane = tid & 31;
    const int wm   = wid >> 2;
    const int wn   = wid & 3;
    const int KC   = K >> 5;
    const int lrow = tid >> 2;
    const int lch  = tid & 3;

    const int sub  = lane >> 3;
    const int r8   = lane & 7;
    const int arow = ((sub & 1) << 3) + r8;
    const int akof = (sub >> 1) << 4;
    const int brow = ((sub >> 1) << 3) + r8;
    const int bkof = (sub & 1) << 4;

    uint32_t aaddr[2][2], baddr[2][2];
    #pragma unroll
    for (int mt = 0; mt < 2; mt++) {
        uint32_t base = smem_base + (uint32_t)((wm * 32 + mt * 16 + arow) * RPAD) * 4 + akof;
        aaddr[mt][0] = base;
        aaddr[mt][1] = base + ATILE_U * 4;
    }
    #pragma unroll
    for (int np = 0; np < 2; np++) {
        uint32_t base = smem_base + (uint32_t)(2 * ATILE_U + (wn * 32 + np * 16 + brow) * RPAD) * 4 + bkof;
        baddr[np][0] = base;
        baddr[np][1] = base + BTILE_U * 4;
    }

    #pragma unroll
    for (int i = 0; i < 2; i++)
        #pragma unroll
        for (int j = 0; j < 4; j++)
            #pragma unroll
            for (int k = 0; k < 4; k++) acc[i][j][k] = 0.f;

    auto issue_load = [&](int c, int buf) {
        const int k0 = c << 5;
        uint32_t st = smem_base + buf * (STAGE_U * 4);
        cp_async16(st + (lrow * RPAD + lch * 4) * 4,
                   Ah + (size_t)(bm + lrow) * K + k0 + lch * 8);
        cp_async16(st + (ATILE_U + lrow * RPAD + lch * 4) * 4,
                   Al + (size_t)(bm + lrow) * K + k0 + lch * 8);
        #pragma unroll
        for (int it = 0; it < 2; it++) {
            int br = it * 64 + lrow;
            cp_async16(st + (2 * ATILE_U + br * RPAD + lch * 4) * 4,
                       Bh + (size_t)(bn + br) * K + k0 + lch * 8);
            cp_async16(st + (2 * ATILE_U + BTILE_U + br * RPAD + lch * 4) * 4,
                       Bl + (size_t)(bn + br) * K + k0 + lch * 8);
        }
        CP_ASYNC_COMMIT();
    };

    issue_load(0, 0);

    for (int c = 0; c < KC; c++) {
        const int buf = c & 1;
        CP_ASYNC_WAIT0();
        __syncthreads();
        if (c + 1 < KC) issue_load(c + 1, buf ^ 1);

        const uint32_t boff = (uint32_t)buf * (STAGE_U * 4);

        #pragma unroll
        for (int ks = 0; ks < 2; ks++) {
            const uint32_t koff = boff + ks * 32;
            uint32_t ahf[2][4], alf[2][4], bhf[4][2], blf[4][2];
            #pragma unroll
            for (int mt = 0; mt < 2; mt++) {
                LDMX4(ahf[mt][0], ahf[mt][1], ahf[mt][2], ahf[mt][3], aaddr[mt][0] + koff);
                LDMX4(alf[mt][0], alf[mt][1], alf[mt][2], alf[mt][3], aaddr[mt][1] + koff);
            }
            #pragma unroll
            for (int np = 0; np < 2; np++) {
                LDMX4(bhf[2*np][0], bhf[2*np][1], bhf[2*np+1][0], bhf[2*np+1][1],
                      baddr[np][0] + koff);
                LDMX4(blf[2*np][0], blf[2*np][1], blf[2*np+1][0], blf[2*np+1][1],
                      baddr[np][1] + koff);
            }
            #pragma unroll
            for (int mt = 0; mt < 2; mt++)
                #pragma unroll
                for (int nt = 0; nt < 4; nt++) {
                    mma_bf16(acc[mt][nt][0], acc[mt][nt][1],
                             acc[mt][nt][2], acc[mt][nt][3],
                             ahf[mt][0], ahf[mt][1], ahf[mt][2], ahf[mt][3],
                             blf[nt][0], blf[nt][1]);
                    mma_bf16(acc[mt][nt][0], acc[mt][nt][1],
                             acc[mt][nt][2], acc[mt][nt][3],
                             alf[mt][0], alf[mt][1], alf[mt][2], alf[mt][3],
                             bhf[nt][0], bhf[nt][1]);
                    mma_bf16(acc[mt][nt][0], acc[mt][nt][1],
                             acc[mt][nt][2], acc[mt][nt][3],
                             ahf[mt][0], ahf[mt][1], ahf[mt][2], ahf[mt][3],
                             bhf[nt][0], bhf[nt][1]);
                }
        }
        __syncthreads();
    }
}

// ---- generic GEMM (o-proj, down-proj) ----
__global__ void __launch_bounds__(256, 2)
gemm_mma_kernel(const bf16* __restrict__ Ah, const bf16* __restrict__ Al,
                const bf16* __restrict__ Bh, const bf16* __restrict__ Bl,
                const float* __restrict__ res, float* __restrict__ C,
                int N, int K) {
    extern __shared__ float sm[];
    const int bm = blockIdx.y * 64;
    const int bn = blockIdx.x * 128;
    float acc[2][4][4];
    gemm_mainloop(sm, Ah, Al, Bh, Bl, K, bm, bn, acc);

    const int tid = threadIdx.x, wid = tid >> 5, lane = tid & 31;
    const int wm = wid >> 2, wn = wid & 3;
    const int gid = lane >> 2, tig = lane & 3;
    #pragma unroll
    for (int mt = 0; mt < 2; mt++) {
        int r0 = bm + wm * 32 + mt * 16 + gid;
        #pragma unroll
        for (int nt = 0; nt < 4; nt++) {
            int col = bn + wn * 32 + nt * 8 + tig * 2;
            size_t o0 = (size_t)r0 * N + col;
            size_t o1 = (size_t)(r0 + 8) * N + col;
            float2 v0 = make_float2(acc[mt][nt][0], acc[mt][nt][1]);
            float2 v1 = make_float2(acc[mt][nt][2], acc[mt][nt][3]);
            if (res) {
                float2 r0v = *(const float2*)(res + o0);
                float2 r1v = *(const float2*)(res + o1);
                v0.x += r0v.x; v0.y += r0v.y;
                v1.x += r1v.x; v1.y += r1v.y;
            }
            *(float2*)(C + o0) = v0;
            *(float2*)(C + o1) = v1;
        }
    }
}

// ---- fused QKV projection + RoPE + KV-cache + bf16 splits -----------------
// blockIdx.x: 0..15 Q, 16..19 K, 20..23 V; blockIdx.y: M-block (64 rows)
__global__ void __launch_bounds__(256, 2)
gemm_qkv_rope_kernel(const bf16* __restrict__ Ah, const bf16* __restrict__ Al,
                     const float* __restrict__ cosp, const float* __restrict__ sinp,
                     const int* __restrict__ pos,
                     float* __restrict__ outk, float* __restrict__ outv,
                     bf16* __restrict__ qh, bf16* __restrict__ ql,
                     bf16* __restrict__ kh, bf16* __restrict__ kl,
                     bf16* __restrict__ vth, bf16* __restrict__ vtl) {
    extern __shared__ float sm[];
    const int ct = blockIdx.x;
    const int bm = blockIdx.y * 64;
    const bf16 *Bh, *Bl; int bn;
    if (ct < 16)      { Bh = s_wq_h; Bl = s_wq_l; bn = ct * 128; }
    else if (ct < 20) { Bh = s_wk_h; Bl = s_wk_l; bn = (ct - 16) * 128; }
    else              { Bh = s_wv_h; Bl = s_wv_l; bn = (ct - 20) * 128; }

    float acc[2][4][4];
    gemm_mainloop(sm, Ah, Al, Bh, Bl, H, bm, bn, acc);

    const int tid = threadIdx.x, wid = tid >> 5, lane = tid & 31;
    const int wm = wid >> 2, wn = wid & 3;
    const int gid = lane >> 2, tig = lane & 3;

    #pragma unroll
    for (int mt = 0; mt < 2; mt++) {
        #pragma unroll
        for (int r = 0; r < 2; r++) {
            int grow = bm + wm * 32 + mt * 16 + gid + r * 8;   // bt index
            int t = grow & (T - 1);
            int b = grow >> 10;
            int p = pos[grow];
            #pragma unroll
            for (int nt = 0; nt < 4; nt++) {
                int col = bn + wn * 32 + nt * 8 + tig * 2;
                float x1 = acc[mt][nt][r * 2 + 0];
                float x2 = acc[mt][nt][r * 2 + 1];
                int h = col >> 6, d = col & 63, d2 = d >> 1;
                if (ct < 16) {
                    float c = cosp[p * 32 + d2], s = sinp[p * 32 + d2];
                    float r1 = x1 * c - x2 * s;
                    float r2 = x1 * s + x2 * c;
                    size_t ob = ((size_t)(b * NH + h) * T + t) * HD + d;
                    split_store2(qh, ql, ob, r1, r2);
                } else if (ct < 20) {
                    float c = cosp[p * 32 + d2], s = sinp[p * 32 + d2];
                    float r1 = x1 * c - x2 * s;
                    float r2 = x1 * s + x2 * c;
                    size_t ob = ((size_t)(b * NKV + h) * T + t) * HD + d;
                    *(float2*)(outk + ob) = make_float2(r1, r2);
                    split_store2(kh, kl, ob, r1, r2);
                } else {
                    size_t ob = ((size_t)(b * NKV + h) * T + t) * HD + d;
                    *(float2*)(outv + ob) = make_float2(x1, x2);
                    size_t vb = ((size_t)(b * NKV + h) * HD + d) * T + t;
                    bf16 h1b = __float2bfloat16(x1);
                    bf16 h2b = __float2bfloat16(x2);
                    vth[vb]     = h1b;
                    vtl[vb]     = __float2bfloat16(x1 - __bfloat162float(h1b));
                    vth[vb + T] = h2b;
                    vtl[vb + T] = __float2bfloat16(x2 - __bfloat162float(h2b));
                }
            }
        }
    }
}

// ---- fused gate/up + SwiGLU ----
__global__ void __launch_bounds__(256, 2)
gemm_gu_silu_kernel(const bf16* __restrict__ Ah, const bf16* __restrict__ Al,
                    bf16* __restrict__ gh, bf16* __restrict__ gl) {
    extern __shared__ float sm[];
    const uint32_t smem_base = smem_u32(sm);
    const int bn = blockIdx.x * 64;
    const int bm = blockIdx.y * 64;
    const int K  = H, KC = K >> 5;

    const int tid  = threadIdx.x;
    const int wid  = tid >> 5;
    const int lane = tid & 31;
    const int wsel = wid >> 2;
    const int wq   = wid & 3;
    const int wm   = wq >> 1;
    const int wn   = wq & 1;
    const int gid  = lane >> 2;
    const int tig  = lane & 3;
    const int lrow = tid >> 2;
    const int lch  = tid & 3;

    const int sub  = lane >> 3;
    const int r8   = lane & 7;
    const int arow = ((sub & 1) << 3) + r8;
    const int akof = (sub >> 1) << 4;
    const int brow = ((sub >> 1) << 3) + r8;
    const int bkof = (sub & 1) << 4;

    uint32_t aaddr[2][2], baddr[2][2];
    #pragma unroll
    for (int mt = 0; mt < 2; mt++) {
        uint32_t base = smem_base + (uint32_t)((wm * 32 + mt * 16 + arow) * RPAD) * 4 + akof;
        aaddr[mt][0] = base;
        aaddr[mt][1] = base + ATILE_U * 4;
    }
    #pragma unroll
    for (int np = 0; np < 2; np++) {
        uint32_t base = smem_base +
            (uint32_t)((2 + 2 * wsel) * ATILE_U + (wn * 32 + np * 16 + brow) * RPAD) * 4 + bkof;
        baddr[np][0] = base;
        baddr[np][1] = base + ATILE_U * 4;
    }

    const bf16* Bgh = s_wg_h; const bf16* Bgl = s_wg_l;
    const bf16* Buh = s_wu_h; const bf16* Bul = s_wu_l;

    float acc[2][4][4];
    #pragma unroll
    for (int i = 0; i < 2; i++)
        #pragma unroll
        for (int j = 0; j < 4; j++)
            #pragma unroll
            for (int k = 0; k < 4; k++) acc[i][j][k] = 0.f;

    auto issue_load = [&](int c, int buf) {
        const int k0 = c << 5;
        uint32_t st = smem_base + buf * (STAGE_U * 4);
        cp_async16(st + (0 * ATILE_U + lrow * RPAD + lch * 4) * 4,
                   Ah + (size_t)(bm + lrow) * K + k0 + lch * 8);
        cp_async16(st + (1 * ATILE_U + lrow * RPAD + lch * 4) * 4,
                   Al + (size_t)(bm + lrow) * K + k0 + lch * 8);
        cp_async16(st + (2 * ATILE_U + lrow * RPAD + lch * 4) * 4,
                   Bgh + (size_t)(bn + lrow) * K + k0 + lch * 8);
        cp_async16(st + (3 * ATILE_U + lrow * RPAD + lch * 4) * 4,
                   Bgl + (size_t)(bn + lrow) * K + k0 + lch * 8);
        cp_async16(st + (4 * ATILE_U + lrow * RPAD + lch * 4) * 4,
                   Buh + (size_t)(bn + lrow) * K + k0 + lch * 8);
        cp_async16(st + (5 * ATILE_U + lrow * RPAD + lch * 4) * 4,
                   Bul + (size_t)(bn + lrow) * K + k0 + lch * 8);
        CP_ASYNC_COMMIT();
    };

    issue_load(0, 0);

    for (int c = 0; c < KC; c++) {
        const int buf = c & 1;
        CP_ASYNC_WAIT0();
        __syncthreads();
        if (c + 1 < KC) issue_load(c + 1, buf ^ 1);

        const uint32_t boff = (uint32_t)buf * (STAGE_U * 4);

        #pragma unroll
        for (int ks = 0; ks < 2; ks++) {
            const uint32_t koff = boff + ks * 32;
            uint32_t ahf[2][4], alf[2][4], bhf[4][2], blf[4][2];
            #pragma unroll
            for (int mt = 0; mt < 2; mt++) {
                LDMX4(ahf[mt][0], ahf[mt][1], ahf[mt][2], ahf[mt][3], aaddr[mt][0] + koff);
                LDMX4(alf[mt][0], alf[mt][1], alf[mt][2], alf[mt][3], aaddr[mt][1] + koff);
            }
            #pragma unroll
            for (int np = 0; np < 2; np++) {
                LDMX4(bhf[2*np][0], bhf[2*np][1], bhf[2*np+1][0], bhf[2*np+1][1],
                      baddr[np][0] + koff);
                LDMX4(blf[2*np][0], blf[2*np][1], blf[2*np+1][0], blf[2*np+1][1],
                      baddr[np][1] + koff);
            }
            #pragma unroll
            for (int mt = 0; mt < 2; mt++)
                #pragma unroll
                for (int nt = 0; nt < 4; nt++) {
                    mma_bf16(acc[mt][nt][0], acc[mt][nt][1],
                             acc[mt][nt][2], acc[mt][nt][3],
                             ahf[mt][0], ahf[mt][1], ahf[mt][2], ahf[mt][3],
                             blf[nt][0], blf[nt][1]);
                    mma_bf16(acc[mt][nt][0], acc[mt][nt][1],
                             acc[mt][nt][2], acc[mt][nt][3],
                             alf[mt][0], alf[mt][1], alf[mt][2], alf[mt][3],
                             bhf[nt][0], bhf[nt][1]);
                    mma_bf16(acc[mt][nt][0], acc[mt][nt][1],
                             acc[mt][nt][2], acc[mt][nt][3],
                             ahf[mt][0], ahf[mt][1], ahf[mt][2], ahf[mt][3],
                             bhf[nt][0], bhf[nt][1]);
                }
        }
        __syncthreads();
    }

    float (*sx)[66] = (float (*)[66])sm;
    __syncthreads();
    if (wsel == 0) {
        #pragma unroll
        for (int mt = 0; mt < 2; mt++) {
            int lr = wm * 32 + mt * 16 + gid;
            #pragma unroll
            for (int nt = 0; nt < 4; nt++) {
                int lc = wn * 32 + nt * 8 + tig * 2;
                sx[lr][lc]     = acc[mt][nt][0];
                sx[lr][lc + 1] = acc[mt][nt][1];
                sx[lr + 8][lc]     = acc[mt][nt][2];
                sx[lr + 8][lc + 1] = acc[mt][nt][3];
            }
        }
    }
    __syncthreads();
    if (wsel == 1) {
        #pragma unroll
        for (int mt = 0; mt < 2; mt++) {
            int lr = wm * 32 + mt * 16 + gid;
            #pragma unroll
            for (int nt = 0; nt < 4; nt++) {
                int lc = wn * 32 + nt * 8 + tig * 2;
                float g0 = sx[lr][lc],     g1 = sx[lr][lc + 1];
                float g2 = sx[lr + 8][lc], g3 = sx[lr + 8][lc + 1];
                float r0 = g0 / (1.f + __expf(-g0)) * acc[mt][nt][0];
                float r1 = g1 / (1.f + __expf(-g1)) * acc[mt][nt][1];
                float r2 = g2 / (1.f + __expf(-g2)) * acc[mt][nt][2];
                float r3 = g3 / (1.f + __expf(-g3)) * acc[mt][nt][3];
                size_t o0 = (size_t)(bm + lr)     * IM + bn + lc;
                size_t o1 = (size_t)(bm + lr + 8) * IM + bn + lc;
                split_store2(gh, gl, o0, r0, r1);
                split_store2(gh, gl, o1, r2, r3);
            }
        }
    }
}

// ---------------- RMSNorm with split output ----------------
__global__ void rmsnorm_split_kernel(const float* __restrict__ x,
                                     const float* __restrict__ w,
                                     bf16* __restrict__ oh, bf16* __restrict__ ol) {
    int row = blockIdx.x;
    const float* xr = x + (size_t)row * H;
    float ss = 0.f;
    for (int i = threadIdx.x; i < H / 4; i += blockDim.x) {
        float4 v = ((const float4*)xr)[i];
        ss += v.x * v.x + v.y * v.y + v.z * v.z + v.w * v.w;
    }
    __shared__ float red[32];
    #pragma unroll
    for (int o = 16; o; o >>= 1) ss += __shfl_xor_sync(0xffffffffu, ss, o);
    if ((threadIdx.x & 31) == 0) red[threadIdx.x >> 5] = ss;
    __syncthreads();
    if (threadIdx.x < 32) {
        float v = (threadIdx.x < (blockDim.x >> 5)) ? red[threadIdx.x] : 0.f;
        #pragma unroll
        for (int o = 16; o; o >>= 1) v += __shfl_xor_sync(0xffffffffu, v, o);
        if (threadIdx.x == 0) red[0] = v;
    }
    __syncthreads();
    float r = rsqrtf(red[0] / (float)H + 1e-6f);
    for (int i = threadIdx.x; i < H / 4; i += blockDim.x) {
        float4 v = ((const float4*)xr)[i];
        float4 wv = ((const float4*)w)[i];
        split_store4(oh, ol, (size_t)row * H + 4 * i,
                     v.x * r * wv.x, v.y * r * wv.y, v.z * r * wv.z, v.w * r * wv.w);
    }
}

// ---------------- Flash attention (3xBF16 mma, 64 q rows/CTA, 4 warps) ------
#define AT_RPAD 36
#define AT_TILE_U (64 * AT_RPAD)
#define ATTN_DSMEM (6 * AT_TILE_U * 4)

__global__ void __launch_bounds__(128)
attn_kernel(const bf16* __restrict__ Qh_g, const bf16* __restrict__ Ql_g,
            const bf16* __restrict__ Kh_g, const bf16* __restrict__ Kl_g,
            const bf16* __restrict__ Vth_g, const bf16* __restrict__ Vtl_g,
            bf16* __restrict__ Oh, bf16* __restrict__ Ol) {
    extern __shared__ uint32_t smu[];
    const int qt = blockIdx.x, h = blockIdx.y, b = blockIdx.z;
    const int kvh = h >> 2;
    const int tid = threadIdx.x, wid = tid >> 5, lane = tid & 31;
    const int gid = lane >> 2, tig = lane & 3;
    const int sub = lane >> 3, r8 = lane & 7;
    const int arow = ((sub & 1) << 3) + r8;
    const int akof = (sub >> 1) << 4;
    const int brow = ((sub >> 1) << 3) + r8;
    const int bkof = (sub & 1) << 4;

    const uint32_t smem_base = smem_u32(smu);
    const uint32_t Qh_s = smem_base;
    const uint32_t Ql_s = Qh_s + AT_TILE_U * 4;
    const uint32_t Kh_s = Ql_s + AT_TILE_U * 4;
    const uint32_t Kl_s = Kh_s + AT_TILE_U * 4;
    const uint32_t Vh_s = Kl_s + AT_TILE_U * 4;
    const uint32_t Vl_s = Vh_s + AT_TILE_U * 4;

    {
        const bf16* qh = Qh_g + ((size_t)(b * NH + h) * T + qt * 64) * HD;
        const bf16* ql = Ql_g + ((size_t)(b * NH + h) * T + qt * 64) * HD;
        #pragma unroll
        for (int it = 0; it < 4; it++) {
            int idx = tid + it * 128;
            int row = idx >> 3, ch = idx & 7;
            cp_async16(Qh_s + (row * AT_RPAD + ch * 4) * 4, qh + (size_t)row * HD + ch * 8);
            cp_async16(Ql_s + (row * AT_RPAD + ch * 4) * 4, ql + (size_t)row * HD + ch * 8);
        }
        CP_ASYNC_COMMIT();
        CP_ASYNC_WAIT0();
        __syncthreads();
    }
    uint32_t qfh[4][4], qfl[4][4];
    {
        uint32_t qa = (uint32_t)((wid * 16 + arow) * AT_RPAD) * 4 + akof;
        #pragma unroll
        for (int ks = 0; ks < 4; ks++) {
            LDMX4(qfh[ks][0], qfh[ks][1], qfh[ks][2], qfh[ks][3], Qh_s + qa + ks * 32);
            LDMX4(qfl[ks][0], qfl[ks][1], qfl[ks][2], qfl[ks][3], Ql_s + qa + ks * 32);
        }
    }

    float oacc[8][4];
    #pragma unroll
    for (int i = 0; i < 8; i++)
        #pragma unroll
        for (int j = 0; j < 4; j++) oacc[i][j] = 0.f;
    float rm0 = -1e30f, rm1 = -1e30f, rs0 = 0.f, rs1 = 0.f;

    for (int kt = 0; kt <= qt; kt++) {
        __syncthreads();
        {
            const bf16* kh  = Kh_g  + ((size_t)(b * NKV + kvh) * T + kt * 64) * HD;
            const bf16* kl  = Kl_g  + ((size_t)(b * NKV + kvh) * T + kt * 64) * HD;
            const bf16* vth = Vth_g + (size_t)(b * NKV + kvh) * HD * T;
            const bf16* vtl = Vtl_g + (size_t)(b * NKV + kvh) * HD * T;
            #pragma unroll
            for (int it = 0; it < 4; it++) {
                int idx = tid + it * 128;
                int row = idx >> 3, ch = idx & 7;
                uint32_t soff = (row * AT_RPAD + ch * 4) * 4;
                cp_async16(Kh_s + soff, kh + (size_t)row * HD + ch * 8);
                cp_async16(Kl_s + soff, kl + (size_t)row * HD + ch * 8);
                cp_async16(Vh_s + soff, vth + (size_t)row * T + kt * 64 + ch * 8);
                cp_async16(Vl_s + soff, vtl + (size_t)row * T + kt * 64 + ch * 8);
            }
            CP_ASYNC_COMMIT();
            CP_ASYNC_WAIT0();
            __syncthreads();
        }

        float sacc[8][4];
        #pragma unroll
        for (int i = 0; i < 8; i++)
            #pragma unroll
            for (int j = 0; j < 4; j++) sacc[i][j] = 0.f;

        #pragma unroll
        for (int ks = 0; ks < 4; ks++) {
            uint32_t kfh[8][2], kfl[8][2];
            #pragma unroll
            for (int np = 0; np < 4; np++) {
                uint32_t ka = (uint32_t)((np * 16 + brow) * AT_RPAD) * 4 + bkof + ks * 32;
                LDMX4(kfh[2*np][0], kfh[2*np][1], kfh[2*np+1][0], kfh[2*np+1][1], Kh_s + ka);
                LDMX4(kfl[2*np][0], kfl[2*np][1], kfl[2*np+1][0], kfl[2*np+1][1], Kl_s + ka);
            }
            #pragma unroll
            for (int nt = 0; nt < 8; nt++) {
                mma_bf16(sacc[nt][0], sacc[nt][1], sacc[nt][2], sacc[nt][3],
                         qfh[ks][0], qfh[ks][1], qfh[ks][2], qfh[ks][3],
                         kfl[nt][0], kfl[nt][1]);
                mma_bf16(sacc[nt][0], sacc[nt][1], sacc[nt][2], sacc[nt][3],
                         qfl[ks][0], qfl[ks][1], qfl[ks][2], qfl[ks][3],
                         kfh[nt][0], kfh[nt][1]);
                mma_bf16(sacc[nt][0], sacc[nt][1], sacc[nt][2], sacc[nt][3],
                         qfh[ks][0], qfh[ks][1], qfh[ks][2], qfh[ks][3],
                         kfh[nt][0], kfh[nt][1]);
            }
        }

        const float scale = 0.125f;
        if (kt == qt) {
            #pragma unroll
            for (int nt = 0; nt < 8; nt++)
                #pragma unroll
                for (int c = 0; c < 4; c++) {
                    int col = 8 * nt + 2 * tig + (c & 1);
                    int row = wid * 16 + gid + ((c >> 1) << 3);
                    sacc[nt][c] = (col <= row) ? sacc[nt][c] * scale : -1e30f;
                }
        } else {
            #pragma unroll
            for (int nt = 0; nt < 8; nt++)
                #pragma unroll
                for (int c = 0; c < 4; c++) sacc[nt][c] *= scale;
        }

        float mx0 = -1e30f, mx1 = -1e30f;
        #pragma unroll
        for (int nt = 0; nt < 8; nt++) {
            mx0 = fmaxf(mx0, fmaxf(sacc[nt][0], sacc[nt][1]));
            mx1 = fmaxf(mx1, fmaxf(sacc[nt][2], sacc[nt][3]));
        }
        mx0 = fmaxf(mx0, __shfl_xor_sync(0xffffffffu, mx0, 1));
        mx0 = fmaxf(mx0, __shfl_xor_sync(0xffffffffu, mx0, 2));
        mx1 = fmaxf(mx1, __shfl_xor_sync(0xffffffffu, mx1, 1));
        mx1 = fmaxf(mx1, __shfl_xor_sync(0xffffffffu, mx1, 2));
        float nrm0 = fmaxf(rm0, mx0), nrm1 = fmaxf(rm1, mx1);
        float al0 = __expf(rm0 - nrm0), al1 = __expf(rm1 - nrm1);
        rm0 = nrm0; rm1 = nrm1;

        float p[8][4];
        float sum0 = 0.f, sum1 = 0.f;
        #pragma unroll
        for (int nt = 0; nt < 8; nt++) {
            p[nt][0] = __expf(sacc[nt][0] - nrm0); sum0 += p[nt][0];
            p[nt][1] = __expf(sacc[nt][1] - nrm0); sum0 += p[nt][1];
            p[nt][2] = __expf(sacc[nt][2] - nrm1); sum1 += p[nt][2];
            p[nt][3] = __expf(sacc[nt][3] - nrm1); sum1 += p[nt][3];
        }
        sum0 += __shfl_xor_sync(0xffffffffu, sum0, 1);
        sum0 += __shfl_xor_sync(0xffffffffu, sum0, 2);
        sum1 += __shfl_xor_sync(0xffffffffu, sum1, 1);
        sum1 += __shfl_xor_sync(0xffffffffu, sum1, 2);
        rs0 = rs0 * al0 + sum0;
        rs1 = rs1 * al1 + sum1;
        #pragma unroll
        for (int nt = 0; nt < 8; nt++) {
            oacc[nt][0] *= al0; oacc[nt][1] *= al0;
            oacc[nt][2] *= al1; oacc[nt][3] *= al1;
        }

        uint32_t ph[4][4], pl[4][4];
        #pragma unroll
        for (int ks = 0; ks < 4; ks++) {
            pack_split2(p[2*ks][0],   p[2*ks][1],   ph[ks][0], pl[ks][0]);
            pack_split2(p[2*ks][2],   p[2*ks][3],   ph[ks][1], pl[ks][1]);
            pack_split2(p[2*ks+1][0], p[2*ks+1][1], ph[ks][2], pl[ks][2]);
            pack_split2(p[2*ks+1][2], p[2*ks+1][3], ph[ks][3], pl[ks][3]);
        }

        #pragma unroll
        for (int ks = 0; ks < 4; ks++) {
            uint32_t vfh[8][2], vfl[8][2];
            #pragma unroll
            for (int np = 0; np < 4; np++) {
                uint32_t va = (uint32_t)((np * 16 + brow) * AT_RPAD) * 4 + bkof + ks * 32;
                LDMX4(vfh[2*np][0], vfh[2*np][1], vfh[2*np+1][0], vfh[2*np+1][1], Vh_s + va);
                LDMX4(vfl[2*np][0], vfl[2*np][1], vfl[2*np+1][0], vfl[2*np+1][1], Vl_s + va);
            }
            #pragma unroll
            for (int nt = 0; nt < 8; nt++) {
                mma_bf16(oacc[nt][0], oacc[nt][1], oacc[nt][2], oacc[nt][3],
                         ph[ks][0], ph[ks][1], ph[ks][2], ph[ks][3],
                         vfl[nt][0], vfl[nt][1]);
                mma_bf16(oacc[nt][0], oacc[nt][1], oacc[nt][2], oacc[nt][3],
                         pl[ks][0], pl[ks][1], pl[ks][2], pl[ks][3],
                         vfh[nt][0], vfh[nt][1]);
                mma_bf16(oacc[nt][0], oacc[nt][1], oacc[nt][2], oacc[nt][3],
                         ph[ks][0], ph[ks][1], ph[ks][2], ph[ks][3],
                         vfh[nt][0], vfh[nt][1]);
            }
        }
    }

    float inv0 = 1.f / rs0, inv1 = 1.f / rs1;
    int trow0 = qt * 64 + wid * 16 + gid;
    #pragma unroll
    for (int nt = 0; nt < 8; nt++) {
        int col = 8 * nt + 2 * tig;
        size_t o0 = ((size_t)(b * T + trow0))     * (NH * HD) + h * HD + col;
        size_t o1 = ((size_t)(b * T + trow0 + 8)) * (NH * HD) + h * HD + col;
        split_store2(Oh, Ol, o0, oacc[nt][0] * inv0, oacc[nt][1] * inv0);
        split_store2(Oh, Ol, o1, oacc[nt][2] * inv1, oacc[nt][3] * inv1);
    }
}

// ---------------- launch ----------------
extern "C" void kernel_launch(void* const* d_in, const int* in_sizes, int n_in,
                              void* d_out, int out_size) {
    const float* hs   = (const float*)d_in[0];
    const float* cosp = (const float*)d_in[1];
    const float* sinp = (const float*)d_in[2];
    const int*   pos  = (const int*)  d_in[3];
    const float* n1w  = (const float*)d_in[5];
    const float* wq   = (const float*)d_in[6];
    const float* wk   = (const float*)d_in[7];
    const float* wv   = (const float*)d_in[8];
    const float* wo   = (const float*)d_in[9];
    const float* n2w  = (const float*)d_in[10];
    const float* wg   = (const float*)d_in[11];
    const float* wu   = (const float*)d_in[12];
    const float* wd   = (const float*)d_in[13];

    float *h2;
    cudaGetSymbolAddress((void**)&h2, g_h2);

    bf16 *woh,*wol,*wdh,*wdl;
    bf16 *xnh,*xnl,*ath,*atl,*xn2h,*xn2l,*gh,*gl;
    bf16 *qh,*ql,*kh,*kl,*vth,*vtl;
    cudaGetSymbolAddress((void**)&woh, s_wo_h);  cudaGetSymbolAddress((void**)&wol, s_wo_l);
    cudaGetSymbolAddress((void**)&wdh, s_wd_h);  cudaGetSymbolAddress((void**)&wdl, s_wd_l);
    cudaGetSymbolAddress((void**)&xnh, s_xn_h);  cudaGetSymbolAddress((void**)&xnl, s_xn_l);
    cudaGetSymbolAddress((void**)&ath, s_at_h);  cudaGetSymbolAddress((void**)&atl, s_at_l);
    cudaGetSymbolAddress((void**)&xn2h, s_xn2_h);cudaGetSymbolAddress((void**)&xn2l, s_xn2_l);
    cudaGetSymbolAddress((void**)&gh,  s_g_h);   cudaGetSymbolAddress((void**)&gl,  s_g_l);
    cudaGetSymbolAddress((void**)&qh,  s_q_h);   cudaGetSymbolAddress((void**)&ql,  s_q_l);
    cudaGetSymbolAddress((void**)&kh,  s_k_h);   cudaGetSymbolAddress((void**)&kl,  s_k_l);
    cudaGetSymbolAddress((void**)&vth, s_vt_h);  cudaGetSymbolAddress((void**)&vtl, s_vt_l);

    float* out_x = (float*)d_out;
    float* out_k = out_x + (size_t)M * H;
    float* out_v = out_k + (size_t)B * NKV * T * HD;

    cudaFuncSetAttribute(gemm_mma_kernel,
                         cudaFuncAttributeMaxDynamicSharedMemorySize, GEMM_DSMEM);
    cudaFuncSetAttribute(gemm_qkv_rope_kernel,
                         cudaFuncAttributeMaxDynamicSharedMemorySize, GEMM_DSMEM);
    cudaFuncSetAttribute(gemm_gu_silu_kernel,
                         cudaFuncAttributeMaxDynamicSharedMemorySize, GEMM_DSMEM);
    cudaFuncSetAttribute(attn_kernel,
                         cudaFuncAttributeMaxDynamicSharedMemorySize, ATTN_DSMEM);

    // 0. split ALL weights in one launch
    split_all_kernel<<<SPLIT_BLOCKS, 256>>>(wq, wk, wv, wo, wg, wu, wd);
    // 1. RMSNorm 1
    rmsnorm_split_kernel<<<M, 256>>>(hs, n1w, xnh, xnl);
    // 2. fused Q/K/V projections + RoPE + KV-cache + bf16 splits
    gemm_qkv_rope_kernel<<<dim3(24, M / 64), 256, GEMM_DSMEM>>>(
        xnh, xnl, cosp, sinp, pos, out_k, out_v, qh, ql, kh, kl, vth, vtl);
    // 3. Attention (tensor-core, 3xBF16)
    attn_kernel<<<dim3(T / 64, NH, B), 128, ATTN_DSMEM>>>(qh, ql, kh, kl, vth, vtl, ath, atl);
    // 4. O-projection + residual
    gemm_mma_kernel<<<dim3(H / 128, M / 64), 256, GEMM_DSMEM>>>(ath, atl, woh, wol,
                                                                hs, h2, H, NH * HD);
    // 5. RMSNorm 2
    rmsnorm_split_kernel<<<M, 256>>>(h2, n2w, xn2h, xn2l);
    // 6. fused MLP gate/up + SwiGLU
    gemm_gu_silu_kernel<<<dim3(IM / 64, M / 64), 256, GEMM_DSMEM>>>(xn2h, xn2l, gh, gl);
    // 7. Down projection + residual -> x output
    gemm_mma_kernel<<<dim3(H / 128, M / 64), 256, GEMM_DSMEM>>>(gh, gl, wdh, wdl,
                                                                h2, out_x, H, IM);
}

// round 14
// speedup vs baseline: 1.0715x; 1.0436x over previous
#include <cuda_runtime.h>
#include <cuda_bf16.h>
#include <math.h>
#include <stdint.h>

#define B   2
#define T   1024
#define H   2048
#define NH  32
#define NKV 8
#define HD  64
#define IM  8192
#define M   (B*T)

typedef __nv_bfloat16  bf16;
typedef __nv_bfloat162 bf162;

// ---------------- scratch (device globals; no allocation) ----------------
__device__ __align__(16) float g_h2 [M * H];
// bf16 hi/lo split weights
__device__ __align__(16) bf16 s_wq_h[NH*HD*H],  s_wq_l[NH*HD*H];
__device__ __align__(16) bf16 s_wk_h[NKV*HD*H], s_wk_l[NKV*HD*H];
__device__ __align__(16) bf16 s_wv_h[NKV*HD*H], s_wv_l[NKV*HD*H];
__device__ __align__(16) bf16 s_wo_h[H*NH*HD],  s_wo_l[H*NH*HD];
__device__ __align__(16) bf16 s_wg_h[(size_t)IM*H], s_wg_l[(size_t)IM*H];
__device__ __align__(16) bf16 s_wu_h[(size_t)IM*H], s_wu_l[(size_t)IM*H];
__device__ __align__(16) bf16 s_wd_h[(size_t)H*IM], s_wd_l[(size_t)H*IM];
// bf16 hi/lo split activations
__device__ __align__(16) bf16 s_xn_h [M*H],        s_xn_l [M*H];
__device__ __align__(16) bf16 s_at_h [M*NH*HD],    s_at_l [M*NH*HD];
__device__ __align__(16) bf16 s_xn2_h[M*H],        s_xn2_l[M*H];
__device__ __align__(16) bf16 s_g_h  [(size_t)M*IM], s_g_l[(size_t)M*IM];
// bf16 hi/lo split q/k/v for attention (head-major; v transposed)
__device__ __align__(16) bf16 s_q_h [M*NH*HD],  s_q_l [M*NH*HD];
__device__ __align__(16) bf16 s_k_h [M*NKV*HD], s_k_l [M*NKV*HD];
__device__ __align__(16) bf16 s_vt_h[M*NKV*HD], s_vt_l[M*NKV*HD];

// ---------------- helpers ----------------
__device__ __forceinline__ uint32_t smem_u32(const void* p) {
    uint32_t a;
    asm("{ .reg .u64 t; cvta.to.shared.u64 t, %1; cvt.u32.u64 %0, t; }"
        : "=r"(a) : "l"(p));
    return a;
}
__device__ __forceinline__ void cp_async16(uint32_t dst, const void* src) {
    asm volatile("cp.async.cg.shared.global [%0], [%1], 16;"
                 :: "r"(dst), "l"(src));
}
#define CP_ASYNC_COMMIT() asm volatile("cp.async.commit_group;" ::: "memory")
#define CP_ASYNC_WAIT0()  asm volatile("cp.async.wait_group 0;" ::: "memory")

#define LDMX4(r0, r1, r2, r3, addr) \
    asm volatile("ldmatrix.sync.aligned.m8n8.x4.shared.b16 {%0,%1,%2,%3}, [%4];" \
        : "=r"(r0), "=r"(r1), "=r"(r2), "=r"(r3) : "r"(addr))

__device__ __forceinline__ void mma_bf16(float& c0, float& c1, float& c2, float& c3,
                                         uint32_t a0, uint32_t a1, uint32_t a2, uint32_t a3,
                                         uint32_t b0, uint32_t b1) {
    asm volatile(
        "mma.sync.aligned.m16n8k16.row.col.f32.bf16.bf16.f32 "
        "{%0,%1,%2,%3}, {%4,%5,%6,%7}, {%8,%9}, {%0,%1,%2,%3};"
        : "+f"(c0), "+f"(c1), "+f"(c2), "+f"(c3)
        : "r"(a0), "r"(a1), "r"(a2), "r"(a3), "r"(b0), "r"(b1));
}

// split-store helpers (fp32 -> hi/lo bf16)
__device__ __forceinline__ void split_store4(bf16* __restrict__ h, bf16* __restrict__ l,
                                             size_t idx, float x, float y, float z, float w) {
    bf162 h0 = __floats2bfloat162_rn(x, y);
    bf162 h1 = __floats2bfloat162_rn(z, w);
    float lx = x - __bfloat162float(__low2bfloat16(h0));
    float ly = y - __bfloat162float(__high2bfloat16(h0));
    float lz = z - __bfloat162float(__low2bfloat16(h1));
    float lw = w - __bfloat162float(__high2bfloat16(h1));
    *(bf162*)(h + idx)     = h0;
    *(bf162*)(h + idx + 2) = h1;
    *(bf162*)(l + idx)     = __floats2bfloat162_rn(lx, ly);
    *(bf162*)(l + idx + 2) = __floats2bfloat162_rn(lz, lw);
}
__device__ __forceinline__ void split_store2(bf16* __restrict__ h, bf16* __restrict__ l,
                                             size_t idx, float x, float y) {
    bf162 h0 = __floats2bfloat162_rn(x, y);
    float lx = x - __bfloat162float(__low2bfloat16(h0));
    float ly = y - __bfloat162float(__high2bfloat16(h0));
    *(bf162*)(h + idx) = h0;
    *(bf162*)(l + idx) = __floats2bfloat162_rn(lx, ly);
}
__device__ __forceinline__ void pack_split2(float x, float y, uint32_t& hi, uint32_t& lo) {
    bf162 h0 = __floats2bfloat162_rn(x, y);
    float lx = x - __bfloat162float(__low2bfloat16(h0));
    float ly = y - __bfloat162float(__high2bfloat16(h0));
    bf162 l0 = __floats2bfloat162_rn(lx, ly);
    hi = *(uint32_t*)&h0;
    lo = *(uint32_t*)&l0;
}

// ---------------- merged weight-split kernel ----------------
#define U_WQ  262144
#define U_WK  (U_WQ + 65536)
#define U_WV  (U_WK + 65536)
#define U_WO  (U_WV + 262144)
#define U_WG  (U_WO + 1048576)
#define U_WU  (U_WG + 1048576)
#define U_WD  (U_WU + 1048576)
#define SPLIT_BLOCKS (U_WD / 256)

__global__ void __launch_bounds__(256)
split_all_kernel(const float* __restrict__ wq, const float* __restrict__ wk,
                 const float* __restrict__ wv, const float* __restrict__ wo,
                 const float* __restrict__ wg, const float* __restrict__ wu,
                 const float* __restrict__ wd) {
    uint32_t u = blockIdx.x * 256 + threadIdx.x;
    const float* src; bf16 *h, *l; uint32_t off;
    if (u < U_WQ)      { src = wq; h = s_wq_h; l = s_wq_l; off = u; }
    else if (u < U_WK) { src = wk; h = s_wk_h; l = s_wk_l; off = u - U_WQ; }
    else if (u < U_WV) { src = wv; h = s_wv_h; l = s_wv_l; off = u - U_WK; }
    else if (u < U_WO) { src = wo; h = s_wo_h; l = s_wo_l; off = u - U_WV; }
    else if (u < U_WG) { src = wg; h = s_wg_h; l = s_wg_l; off = u - U_WO; }
    else if (u < U_WU) { src = wu; h = s_wu_h; l = s_wu_l; off = u - U_WG; }
    else               { src = wd; h = s_wd_h; l = s_wd_l; off = u - U_WU; }

    size_t e = (size_t)off * 16;
    float4 a0 = ((const float4*)(src + e))[0];
    float4 a1 = ((const float4*)(src + e))[1];
    float4 a2 = ((const float4*)(src + e))[2];
    float4 a3 = ((const float4*)(src + e))[3];
    uint32_t hh[8], ll[8];
    pack_split2(a0.x, a0.y, hh[0], ll[0]);
    pack_split2(a0.z, a0.w, hh[1], ll[1]);
    pack_split2(a1.x, a1.y, hh[2], ll[2]);
    pack_split2(a1.z, a1.w, hh[3], ll[3]);
    pack_split2(a2.x, a2.y, hh[4], ll[4]);
    pack_split2(a2.z, a2.w, hh[5], ll[5]);
    pack_split2(a3.x, a3.y, hh[6], ll[6]);
    pack_split2(a3.z, a3.w, hh[7], ll[7]);
    ((uint4*)(h + e))[0] = make_uint4(hh[0], hh[1], hh[2], hh[3]);
    ((uint4*)(h + e))[1] = make_uint4(hh[4], hh[5], hh[6], hh[7]);
    ((uint4*)(l + e))[0] = make_uint4(ll[0], ll[1], ll[2], ll[3]);
    ((uint4*)(l + e))[1] = make_uint4(ll[4], ll[5], ll[6], ll[7]);
}

// ---------------- 3xBF16 GEMM mainloop (ldmatrix, 2-stage cp.async) ---------
#define RPAD 20
#define ATILE_U (64 * RPAD)
#define BTILE_U (128 * RPAD)
#define STAGE_U (2 * ATILE_U + 2 * BTILE_U)
#define GEMM_DSMEM (2 * STAGE_U * 4)

__device__ __forceinline__ void gemm_mainloop(float* sm,
                                              const bf16* __restrict__ Ah, const bf16* __restrict__ Al,
                                              const bf16* __restrict__ Bh, const bf16* __restrict__ Bl,
                                              int K, int bm, int bn,
                                              float (&acc)[2][4][4]) {
    const uint32_t smem_base = smem_u32(sm);
    const int tid  = threadIdx.x;
    const int wid  = tid >> 5;
    const int lane = tid & 31;
    const int wm   = wid >> 2;
    const int wn   = wid & 3;
    const int KC   = K >> 5;
    const int lrow = tid >> 2;
    const int lch  = tid & 3;

    const int sub  = lane >> 3;
    const int r8   = lane & 7;
    const int arow = ((sub & 1) << 3) + r8;
    const int akof = (sub >> 1) << 4;
    const int brow = ((sub >> 1) << 3) + r8;
    const int bkof = (sub & 1) << 4;

    uint32_t aaddr[2][2], baddr[2][2];
    #pragma unroll
    for (int mt = 0; mt < 2; mt++) {
        uint32_t base = smem_base + (uint32_t)((wm * 32 + mt * 16 + arow) * RPAD) * 4 + akof;
        aaddr[mt][0] = base;
        aaddr[mt][1] = base + ATILE_U * 4;
    }
    #pragma unroll
    for (int np = 0; np < 2; np++) {
        uint32_t base = smem_base + (uint32_t)(2 * ATILE_U + (wn * 32 + np * 16 + brow) * RPAD) * 4 + bkof;
        baddr[np][0] = base;
        baddr[np][1] = base + BTILE_U * 4;
    }

    #pragma unroll
    for (int i = 0; i < 2; i++)
        #pragma unroll
        for (int j = 0; j < 4; j++)
            #pragma unroll
            for (int k = 0; k < 4; k++) acc[i][j][k] = 0.f;

    auto issue_load = [&](int c, int buf) {
        const int k0 = c << 5;
        uint32_t st = smem_base + buf * (STAGE_U * 4);
        cp_async16(st + (lrow * RPAD + lch * 4) * 4,
                   Ah + (size_t)(bm + lrow) * K + k0 + lch * 8);
        cp_async16(st + (ATILE_U + lrow * RPAD + lch * 4) * 4,
                   Al + (size_t)(bm + lrow) * K + k0 + lch * 8);
        #pragma unroll
        for (int it = 0; it < 2; it++) {
            int br = it * 64 + lrow;
            cp_async16(st + (2 * ATILE_U + br * RPAD + lch * 4) * 4,
                       Bh + (size_t)(bn + br) * K + k0 + lch * 8);
            cp_async16(st + (2 * ATILE_U + BTILE_U + br * RPAD + lch * 4) * 4,
                       Bl + (size_t)(bn + br) * K + k0 + lch * 8);
        }
        CP_ASYNC_COMMIT();
    };

    issue_load(0, 0);

    for (int c = 0; c < KC; c++) {
        const int buf = c & 1;
        CP_ASYNC_WAIT0();
        __syncthreads();
        if (c + 1 < KC) issue_load(c + 1, buf ^ 1);

        const uint32_t boff = (uint32_t)buf * (STAGE_U * 4);

        #pragma unroll
        for (int ks = 0; ks < 2; ks++) {
            const uint32_t koff = boff + ks * 32;
            uint32_t ahf[2][4], alf[2][4], bhf[4][2], blf[4][2];
            #pragma unroll
            for (int mt = 0; mt < 2; mt++) {
                LDMX4(ahf[mt][0], ahf[mt][1], ahf[mt][2], ahf[mt][3], aaddr[mt][0] + koff);
                LDMX4(alf[mt][0], alf[mt][1], alf[mt][2], alf[mt][3], aaddr[mt][1] + koff);
            }
            #pragma unroll
            for (int np = 0; np < 2; np++) {
                LDMX4(bhf[2*np][0], bhf[2*np][1], bhf[2*np+1][0], bhf[2*np+1][1],
                      baddr[np][0] + koff);
                LDMX4(blf[2*np][0], blf[2*np][1], blf[2*np+1][0], blf[2*np+1][1],
                      baddr[np][1] + koff);
            }
            #pragma unroll
            for (int mt = 0; mt < 2; mt++)
                #pragma unroll
                for (int nt = 0; nt < 4; nt++) {
                    mma_bf16(acc[mt][nt][0], acc[mt][nt][1],
                             acc[mt][nt][2], acc[mt][nt][3],
                             ahf[mt][0], ahf[mt][1], ahf[mt][2], ahf[mt][3],
                             blf[nt][0], blf[nt][1]);
                    mma_bf16(acc[mt][nt][0], acc[mt][nt][1],
                             acc[mt][nt][2], acc[mt][nt][3],
                             alf[mt][0], alf[mt][1], alf[mt][2], alf[mt][3],
                             bhf[nt][0], bhf[nt][1]);
                    mma_bf16(acc[mt][nt][0], acc[mt][nt][1],
                             acc[mt][nt][2], acc[mt][nt][3],
                             ahf[mt][0], ahf[mt][1], ahf[mt][2], ahf[mt][3],
                             bhf[nt][0], bhf[nt][1]);
                }
        }
        // trailing __syncthreads removed: buffer reuse is protected by the
        // post-wait barrier of iteration c+1 (load c+2 is issued after it).
    }
}

// ---- generic GEMM (o-proj, down-proj) ----
__global__ void __launch_bounds__(256, 2)
gemm_mma_kernel(const bf16* __restrict__ Ah, const bf16* __restrict__ Al,
                const bf16* __restrict__ Bh, const bf16* __restrict__ Bl,
                const float* __restrict__ res, float* __restrict__ C,
                int N, int K) {
    extern __shared__ float sm[];
    const int bm = blockIdx.y * 64;
    const int bn = blockIdx.x * 128;
    float acc[2][4][4];
    gemm_mainloop(sm, Ah, Al, Bh, Bl, K, bm, bn, acc);

    const int tid = threadIdx.x, wid = tid >> 5, lane = tid & 31;
    const int wm = wid >> 2, wn = wid & 3;
    const int gid = lane >> 2, tig = lane & 3;
    #pragma unroll
    for (int mt = 0; mt < 2; mt++) {
        int r0 = bm + wm * 32 + mt * 16 + gid;
        #pragma unroll
        for (int nt = 0; nt < 4; nt++) {
            int col = bn + wn * 32 + nt * 8 + tig * 2;
            size_t o0 = (size_t)r0 * N + col;
            size_t o1 = (size_t)(r0 + 8) * N + col;
            float2 v0 = make_float2(acc[mt][nt][0], acc[mt][nt][1]);
            float2 v1 = make_float2(acc[mt][nt][2], acc[mt][nt][3]);
            if (res) {
                float2 r0v = *(const float2*)(res + o0);
                float2 r1v = *(const float2*)(res + o1);
                v0.x += r0v.x; v0.y += r0v.y;
                v1.x += r1v.x; v1.y += r1v.y;
            }
            *(float2*)(C + o0) = v0;
            *(float2*)(C + o1) = v1;
        }
    }
}

// ---- fused QKV projection + RoPE + KV-cache + bf16 splits -----------------
__global__ void __launch_bounds__(256, 2)
gemm_qkv_rope_kernel(const bf16* __restrict__ Ah, const bf16* __restrict__ Al,
                     const float* __restrict__ cosp, const float* __restrict__ sinp,
                     const int* __restrict__ pos,
                     float* __restrict__ outk, float* __restrict__ outv,
                     bf16* __restrict__ qh, bf16* __restrict__ ql,
                     bf16* __restrict__ kh, bf16* __restrict__ kl,
                     bf16* __restrict__ vth, bf16* __restrict__ vtl) {
    extern __shared__ float sm[];
    const int ct = blockIdx.x;
    const int bm = blockIdx.y * 64;
    const bf16 *Bh, *Bl; int bn;
    if (ct < 16)      { Bh = s_wq_h; Bl = s_wq_l; bn = ct * 128; }
    else if (ct < 20) { Bh = s_wk_h; Bl = s_wk_l; bn = (ct - 16) * 128; }
    else              { Bh = s_wv_h; Bl = s_wv_l; bn = (ct - 20) * 128; }

    float acc[2][4][4];
    gemm_mainloop(sm, Ah, Al, Bh, Bl, H, bm, bn, acc);

    const int tid = threadIdx.x, wid = tid >> 5, lane = tid & 31;
    const int wm = wid >> 2, wn = wid & 3;
    const int gid = lane >> 2, tig = lane & 3;

    #pragma unroll
    for (int mt = 0; mt < 2; mt++) {
        #pragma unroll
        for (int r = 0; r < 2; r++) {
            int grow = bm + wm * 32 + mt * 16 + gid + r * 8;   // bt index
            int t = grow & (T - 1);
            int b = grow >> 10;
            int p = pos[grow];
            #pragma unroll
            for (int nt = 0; nt < 4; nt++) {
                int col = bn + wn * 32 + nt * 8 + tig * 2;
                float x1 = acc[mt][nt][r * 2 + 0];
                float x2 = acc[mt][nt][r * 2 + 1];
                int h = col >> 6, d = col & 63, d2 = d >> 1;
                if (ct < 16) {
                    float c = cosp[p * 32 + d2], s = sinp[p * 32 + d2];
                    float r1 = x1 * c - x2 * s;
                    float r2 = x1 * s + x2 * c;
                    size_t ob = ((size_t)(b * NH + h) * T + t) * HD + d;
                    split_store2(qh, ql, ob, r1, r2);
                } else if (ct < 20) {
                    float c = cosp[p * 32 + d2], s = sinp[p * 32 + d2];
                    float r1 = x1 * c - x2 * s;
                    float r2 = x1 * s + x2 * c;
                    size_t ob = ((size_t)(b * NKV + h) * T + t) * HD + d;
                    *(float2*)(outk + ob) = make_float2(r1, r2);
                    split_store2(kh, kl, ob, r1, r2);
                } else {
                    size_t ob = ((size_t)(b * NKV + h) * T + t) * HD + d;
                    *(float2*)(outv + ob) = make_float2(x1, x2);
                    size_t vb = ((size_t)(b * NKV + h) * HD + d) * T + t;
                    bf16 h1b = __float2bfloat16(x1);
                    bf16 h2b = __float2bfloat16(x2);
                    vth[vb]     = h1b;
                    vtl[vb]     = __float2bfloat16(x1 - __bfloat162float(h1b));
                    vth[vb + T] = h2b;
                    vtl[vb + T] = __float2bfloat16(x2 - __bfloat162float(h2b));
                }
            }
        }
    }
}

// ---- fused gate/up + SwiGLU; grid: x = M-block (fast, for B-stripe L2 reuse),
//      y = N64-block
__global__ void __launch_bounds__(256, 2)
gemm_gu_silu_kernel(const bf16* __restrict__ Ah, const bf16* __restrict__ Al,
                    bf16* __restrict__ gh, bf16* __restrict__ gl) {
    extern __shared__ float sm[];
    const uint32_t smem_base = smem_u32(sm);
    const int bm = blockIdx.x * 64;
    const int bn = blockIdx.y * 64;
    const int K  = H, KC = K >> 5;

    const int tid  = threadIdx.x;
    const int wid  = tid >> 5;
    const int lane = tid & 31;
    const int wsel = wid >> 2;
    const int wq   = wid & 3;
    const int wm   = wq >> 1;
    const int wn   = wq & 1;
    const int gid  = lane >> 2;
    const int tig  = lane & 3;
    const int lrow = tid >> 2;
    const int lch  = tid & 3;

    const int sub  = lane >> 3;
    const int r8   = lane & 7;
    const int arow = ((sub & 1) << 3) + r8;
    const int akof = (sub >> 1) << 4;
    const int brow = ((sub >> 1) << 3) + r8;
    const int bkof = (sub & 1) << 4;

    uint32_t aaddr[2][2], baddr[2][2];
    #pragma unroll
    for (int mt = 0; mt < 2; mt++) {
        uint32_t base = smem_base + (uint32_t)((wm * 32 + mt * 16 + arow) * RPAD) * 4 + akof;
        aaddr[mt][0] = base;
        aaddr[mt][1] = base + ATILE_U * 4;
    }
    #pragma unroll
    for (int np = 0; np < 2; np++) {
        uint32_t base = smem_base +
            (uint32_t)((2 + 2 * wsel) * ATILE_U + (wn * 32 + np * 16 + brow) * RPAD) * 4 + bkof;
        baddr[np][0] = base;
        baddr[np][1] = base + ATILE_U * 4;
    }

    const bf16* Bgh = s_wg_h; const bf16* Bgl = s_wg_l;
    const bf16* Buh = s_wu_h; const bf16* Bul = s_wu_l;

    float acc[2][4][4];
    #pragma unroll
    for (int i = 0; i < 2; i++)
        #pragma unroll
        for (int j = 0; j < 4; j++)
            #pragma unroll
            for (int k = 0; k < 4; k++) acc[i][j][k] = 0.f;

    auto issue_load = [&](int c, int buf) {
        const int k0 = c << 5;
        uint32_t st = smem_base + buf * (STAGE_U * 4);
        cp_async16(st + (0 * ATILE_U + lrow * RPAD + lch * 4) * 4,
                   Ah + (size_t)(bm + lrow) * K + k0 + lch * 8);
        cp_async16(st + (1 * ATILE_U + lrow * RPAD + lch * 4) * 4,
                   Al + (size_t)(bm + lrow) * K + k0 + lch * 8);
        cp_async16(st + (2 * ATILE_U + lrow * RPAD + lch * 4) * 4,
                   Bgh + (size_t)(bn + lrow) * K + k0 + lch * 8);
        cp_async16(st + (3 * ATILE_U + lrow * RPAD + lch * 4) * 4,
                   Bgl + (size_t)(bn + lrow) * K + k0 + lch * 8);
        cp_async16(st + (4 * ATILE_U + lrow * RPAD + lch * 4) * 4,
                   Buh + (size_t)(bn + lrow) * K + k0 + lch * 8);
        cp_async16(st + (5 * ATILE_U + lrow * RPAD + lch * 4) * 4,
                   Bul + (size_t)(bn + lrow) * K + k0 + lch * 8);
        CP_ASYNC_COMMIT();
    };

    issue_load(0, 0);

    for (int c = 0; c < KC; c++) {
        const int buf = c & 1;
        CP_ASYNC_WAIT0();
        __syncthreads();
        if (c + 1 < KC) issue_load(c + 1, buf ^ 1);

        const uint32_t boff = (uint32_t)buf * (STAGE_U * 4);

        #pragma unroll
        for (int ks = 0; ks < 2; ks++) {
            const uint32_t koff = boff + ks * 32;
            uint32_t ahf[2][4], alf[2][4], bhf[4][2], blf[4][2];
            #pragma unroll
            for (int mt = 0; mt < 2; mt++) {
                LDMX4(ahf[mt][0], ahf[mt][1], ahf[mt][2], ahf[mt][3], aaddr[mt][0] + koff);
                LDMX4(alf[mt][0], alf[mt][1], alf[mt][2], alf[mt][3], aaddr[mt][1] + koff);
            }
            #pragma unroll
            for (int np = 0; np < 2; np++) {
                LDMX4(bhf[2*np][0], bhf[2*np][1], bhf[2*np+1][0], bhf[2*np+1][1],
                      baddr[np][0] + koff);
                LDMX4(blf[2*np][0], blf[2*np][1], blf[2*np+1][0], blf[2*np+1][1],
                      baddr[np][1] + koff);
            }
            #pragma unroll
            for (int mt = 0; mt < 2; mt++)
                #pragma unroll
                for (int nt = 0; nt < 4; nt++) {
                    mma_bf16(acc[mt][nt][0], acc[mt][nt][1],
                             acc[mt][nt][2], acc[mt][nt][3],
                             ahf[mt][0], ahf[mt][1], ahf[mt][2], ahf[mt][3],
                             blf[nt][0], blf[nt][1]);
                    mma_bf16(acc[mt][nt][0], acc[mt][nt][1],
                             acc[mt][nt][2], acc[mt][nt][3],
                             alf[mt][0], alf[mt][1], alf[mt][2], alf[mt][3],
                             bhf[nt][0], bhf[nt][1]);
                    mma_bf16(acc[mt][nt][0], acc[mt][nt][1],
                             acc[mt][nt][2], acc[mt][nt][3],
                             ahf[mt][0], ahf[mt][1], ahf[mt][2], ahf[mt][3],
                             bhf[nt][0], bhf[nt][1]);
                }
        }
    }

    float (*sx)[66] = (float (*)[66])sm;
    __syncthreads();
    if (wsel == 0) {
        #pragma unroll
        for (int mt = 0; mt < 2; mt++) {
            int lr = wm * 32 + mt * 16 + gid;
            #pragma unroll
            for (int nt = 0; nt < 4; nt++) {
                int lc = wn * 32 + nt * 8 + tig * 2;
                sx[lr][lc]     = acc[mt][nt][0];
                sx[lr][lc + 1] = acc[mt][nt][1];
                sx[lr + 8][lc]     = acc[mt][nt][2];
                sx[lr + 8][lc + 1] = acc[mt][nt][3];
            }
        }
    }
    __syncthreads();
    if (wsel == 1) {
        #pragma unroll
        for (int mt = 0; mt < 2; mt++) {
            int lr = wm * 32 + mt * 16 + gid;
            #pragma unroll
            for (int nt = 0; nt < 4; nt++) {
                int lc = wn * 32 + nt * 8 + tig * 2;
                float g0 = sx[lr][lc],     g1 = sx[lr][lc + 1];
                float g2 = sx[lr + 8][lc], g3 = sx[lr + 8][lc + 1];
                float r0 = g0 / (1.f + __expf(-g0)) * acc[mt][nt][0];
                float r1 = g1 / (1.f + __expf(-g1)) * acc[mt][nt][1];
                float r2 = g2 / (1.f + __expf(-g2)) * acc[mt][nt][2];
                float r3 = g3 / (1.f + __expf(-g3)) * acc[mt][nt][3];
                size_t o0 = (size_t)(bm + lr)     * IM + bn + lc;
                size_t o1 = (size_t)(bm + lr + 8) * IM + bn + lc;
                split_store2(gh, gl, o0, r0, r1);
                split_store2(gh, gl, o1, r2, r3);
            }
        }
    }
}

// ---------------- RMSNorm with split output ----------------
__global__ void rmsnorm_split_kernel(const float* __restrict__ x,
                                     const float* __restrict__ w,
                                     bf16* __restrict__ oh, bf16* __restrict__ ol) {
    int row = blockIdx.x;
    const float* xr = x + (size_t)row * H;
    float ss = 0.f;
    for (int i = threadIdx.x; i < H / 4; i += blockDim.x) {
        float4 v = ((const float4*)xr)[i];
        ss += v.x * v.x + v.y * v.y + v.z * v.z + v.w * v.w;
    }
    __shared__ float red[32];
    #pragma unroll
    for (int o = 16; o; o >>= 1) ss += __shfl_xor_sync(0xffffffffu, ss, o);
    if ((threadIdx.x & 31) == 0) red[threadIdx.x >> 5] = ss;
    __syncthreads();
    if (threadIdx.x < 32) {
        float v = (threadIdx.x < (blockDim.x >> 5)) ? red[threadIdx.x] : 0.f;
        #pragma unroll
        for (int o = 16; o; o >>= 1) v += __shfl_xor_sync(0xffffffffu, v, o);
        if (threadIdx.x == 0) red[0] = v;
    }
    __syncthreads();
    float r = rsqrtf(red[0] / (float)H + 1e-6f);
    for (int i = threadIdx.x; i < H / 4; i += blockDim.x) {
        float4 v = ((const float4*)xr)[i];
        float4 wv = ((const float4*)w)[i];
        split_store4(oh, ol, (size_t)row * H + 4 * i,
                     v.x * r * wv.x, v.y * r * wv.y, v.z * r * wv.z, v.w * r * wv.w);
    }
}

// ---------------- Flash attention (3xBF16 mma, 64 q rows/CTA, 4 warps) ------
#define AT_RPAD 36
#define AT_TILE_U (64 * AT_RPAD)
#define ATTN_DSMEM (6 * AT_TILE_U * 4)

__global__ void __launch_bounds__(128)
attn_kernel(const bf16* __restrict__ Qh_g, const bf16* __restrict__ Ql_g,
            const bf16* __restrict__ Kh_g, const bf16* __restrict__ Kl_g,
            const bf16* __restrict__ Vth_g, const bf16* __restrict__ Vtl_g,
            bf16* __restrict__ Oh, bf16* __restrict__ Ol) {
    extern __shared__ uint32_t smu[];
    const int qt = (int)(gridDim.x - 1 - blockIdx.x);   // LPT: heavy tiles first
    const int h = blockIdx.y, b = blockIdx.z;
    const int kvh = h >> 2;
    const int tid = threadIdx.x, wid = tid >> 5, lane = tid & 31;
    const int gid = lane >> 2, tig = lane & 3;
    const int sub = lane >> 3, r8 = lane & 7;
    const int arow = ((sub & 1) << 3) + r8;
    const int akof = (sub >> 1) << 4;
    const int brow = ((sub >> 1) << 3) + r8;
    const int bkof = (sub & 1) << 4;

    const uint32_t smem_base = smem_u32(smu);
    const uint32_t Qh_s = smem_base;
    const uint32_t Ql_s = Qh_s + AT_TILE_U * 4;
    const uint32_t Kh_s = Ql_s + AT_TILE_U * 4;
    const uint32_t Kl_s = Kh_s + AT_TILE_U * 4;
    const uint32_t Vh_s = Kl_s + AT_TILE_U * 4;
    const uint32_t Vl_s = Vh_s + AT_TILE_U * 4;

    {
        const bf16* qh = Qh_g + ((size_t)(b * NH + h) * T + qt * 64) * HD;
        const bf16* ql = Ql_g + ((size_t)(b * NH + h) * T + qt * 64) * HD;
        #pragma unroll
        for (int it = 0; it < 4; it++) {
            int idx = tid + it * 128;
            int row = idx >> 3, ch = idx & 7;
            cp_async16(Qh_s + (row * AT_RPAD + ch * 4) * 4, qh + (size_t)row * HD + ch * 8);
            cp_async16(Ql_s + (row * AT_RPAD + ch * 4) * 4, ql + (size_t)row * HD + ch * 8);
        }
        CP_ASYNC_COMMIT();
        CP_ASYNC_WAIT0();
        __syncthreads();
    }
    uint32_t qfh[4][4], qfl[4][4];
    {
        uint32_t qa = (uint32_t)((wid * 16 + arow) * AT_RPAD) * 4 + akof;
        #pragma unroll
        for (int ks = 0; ks < 4; ks++) {
            LDMX4(qfh[ks][0], qfh[ks][1], qfh[ks][2], qfh[ks][3], Qh_s + qa + ks * 32);
            LDMX4(qfl[ks][0], qfl[ks][1], qfl[ks][2], qfl[ks][3], Ql_s + qa + ks * 32);
        }
    }

    float oacc[8][4];
    #pragma unroll
    for (int i = 0; i < 8; i++)
        #pragma unroll
        for (int j = 0; j < 4; j++) oacc[i][j] = 0.f;
    float rm0 = -1e30f, rm1 = -1e30f, rs0 = 0.f, rs1 = 0.f;

    for (int kt = 0; kt <= qt; kt++) {
        __syncthreads();
        {
            const bf16* kh  = Kh_g  + ((size_t)(b * NKV + kvh) * T + kt * 64) * HD;
            const bf16* kl  = Kl_g  + ((size_t)(b * NKV + kvh) * T + kt * 64) * HD;
            const bf16* vth = Vth_g + (size_t)(b * NKV + kvh) * HD * T;
            const bf16* vtl = Vtl_g + (size_t)(b * NKV + kvh) * HD * T;
            #pragma unroll
            for (int it = 0; it < 4; it++) {
                int idx = tid + it * 128;
                int row = idx >> 3, ch = idx & 7;
                uint32_t soff = (row * AT_RPAD + ch * 4) * 4;
                cp_async16(Kh_s + soff, kh + (size_t)row * HD + ch * 8);
                cp_async16(Kl_s + soff, kl + (size_t)row * HD + ch * 8);
                cp_async16(Vh_s + soff, vth + (size_t)row * T + kt * 64 + ch * 8);
                cp_async16(Vl_s + soff, vtl + (size_t)row * T + kt * 64 + ch * 8);
            }
            CP_ASYNC_COMMIT();
            CP_ASYNC_WAIT0();
            __syncthreads();
        }

        float sacc[8][4];
        #pragma unroll
        for (int i = 0; i < 8; i++)
            #pragma unroll
            for (int j = 0; j < 4; j++) sacc[i][j] = 0.f;

        #pragma unroll
        for (int ks = 0; ks < 4; ks++) {
            uint32_t kfh[8][2], kfl[8][2];
            #pragma unroll
            for (int np = 0; np < 4; np++) {
                uint32_t ka = (uint32_t)((np * 16 + brow) * AT_RPAD) * 4 + bkof + ks * 32;
                LDMX4(kfh[2*np][0], kfh[2*np][1], kfh[2*np+1][0], kfh[2*np+1][1], Kh_s + ka);
                LDMX4(kfl[2*np][0], kfl[2*np][1], kfl[2*np+1][0], kfl[2*np+1][1], Kl_s + ka);
            }
            #pragma unroll
            for (int nt = 0; nt < 8; nt++) {
                mma_bf16(sacc[nt][0], sacc[nt][1], sacc[nt][2], sacc[nt][3],
                         qfh[ks][0], qfh[ks][1], qfh[ks][2], qfh[ks][3],
                         kfl[nt][0], kfl[nt][1]);
                mma_bf16(sacc[nt][0], sacc[nt][1], sacc[nt][2], sacc[nt][3],
                         qfl[ks][0], qfl[ks][1], qfl[ks][2], qfl[ks][3],
                         kfh[nt][0], kfh[nt][1]);
                mma_bf16(sacc[nt][0], sacc[nt][1], sacc[nt][2], sacc[nt][3],
                         qfh[ks][0], qfh[ks][1], qfh[ks][2], qfh[ks][3],
                         kfh[nt][0], kfh[nt][1]);
            }
        }

        const float scale = 0.125f;
        if (kt == qt) {
            #pragma unroll
            for (int nt = 0; nt < 8; nt++)
                #pragma unroll
                for (int c = 0; c < 4; c++) {
                    int col = 8 * nt + 2 * tig + (c & 1);
                    int row = wid * 16 + gid + ((c >> 1) << 3);
                    sacc[nt][c] = (col <= row) ? sacc[nt][c] * scale : -1e30f;
                }
        } else {
            #pragma unroll
            for (int nt = 0; nt < 8; nt++)
                #pragma unroll
                for (int c = 0; c < 4; c++) sacc[nt][c] *= scale;
        }

        float mx0 = -1e30f, mx1 = -1e30f;
        #pragma unroll
        for (int nt = 0; nt < 8; nt++) {
            mx0 = fmaxf(mx0, fmaxf(sacc[nt][0], sacc[nt][1]));
            mx1 = fmaxf(mx1, fmaxf(sacc[nt][2], sacc[nt][3]));
        }
        mx0 = fmaxf(mx0, __shfl_xor_sync(0xffffffffu, mx0, 1));
        mx0 = fmaxf(mx0, __shfl_xor_sync(0xffffffffu, mx0, 2));
        mx1 = fmaxf(mx1, __shfl_xor_sync(0xffffffffu, mx1, 1));
        mx1 = fmaxf(mx1, __shfl_xor_sync(0xffffffffu, mx1, 2));
        float nrm0 = fmaxf(rm0, mx0), nrm1 = fmaxf(rm1, mx1);
        float al0 = __expf(rm0 - nrm0), al1 = __expf(rm1 - nrm1);
        rm0 = nrm0; rm1 = nrm1;

        float p[8][4];
        float sum0 = 0.f, sum1 = 0.f;
        #pragma unroll
        for (int nt = 0; nt < 8; nt++) {
            p[nt][0] = __expf(sacc[nt][0] - nrm0); sum0 += p[nt][0];
            p[nt][1] = __expf(sacc[nt][1] - nrm0); sum0 += p[nt][1];
            p[nt][2] = __expf(sacc[nt][2] - nrm1); sum1 += p[nt][2];
            p[nt][3] = __expf(sacc[nt][3] - nrm1); sum1 += p[nt][3];
        }
        sum0 += __shfl_xor_sync(0xffffffffu, sum0, 1);
        sum0 += __shfl_xor_sync(0xffffffffu, sum0, 2);
        sum1 += __shfl_xor_sync(0xffffffffu, sum1, 1);
        sum1 += __shfl_xor_sync(0xffffffffu, sum1, 2);
        rs0 = rs0 * al0 + sum0;
        rs1 = rs1 * al1 + sum1;
        #pragma unroll
        for (int nt = 0; nt < 8; nt++) {
            oacc[nt][0] *= al0; oacc[nt][1] *= al0;
            oacc[nt][2] *= al1; oacc[nt][3] *= al1;
        }

        uint32_t ph[4][4], pl[4][4];
        #pragma unroll
        for (int ks = 0; ks < 4; ks++) {
            pack_split2(p[2*ks][0],   p[2*ks][1],   ph[ks][0], pl[ks][0]);
            pack_split2(p[2*ks][2],   p[2*ks][3],   ph[ks][1], pl[ks][1]);
            pack_split2(p[2*ks+1][0], p[2*ks+1][1], ph[ks][2], pl[ks][2]);
            pack_split2(p[2*ks+1][2], p[2*ks+1][3], ph[ks][3], pl[ks][3]);
        }

        #pragma unroll
        for (int ks = 0; ks < 4; ks++) {
            uint32_t vfh[8][2], vfl[8][2];
            #pragma unroll
            for (int np = 0; np < 4; np++) {
                uint32_t va = (uint32_t)((np * 16 + brow) * AT_RPAD) * 4 + bkof + ks * 32;
                LDMX4(vfh[2*np][0], vfh[2*np][1], vfh[2*np+1][0], vfh[2*np+1][1], Vh_s + va);
                LDMX4(vfl[2*np][0], vfl[2*np][1], vfl[2*np+1][0], vfl[2*np+1][1], Vl_s + va);
            }
            #pragma unroll
            for (int nt = 0; nt < 8; nt++) {
                mma_bf16(oacc[nt][0], oacc[nt][1], oacc[nt][2], oacc[nt][3],
                         ph[ks][0], ph[ks][1], ph[ks][2], ph[ks][3],
                         vfl[nt][0], vfl[nt][1]);
                mma_bf16(oacc[nt][0], oacc[nt][1], oacc[nt][2], oacc[nt][3],
                         pl[ks][0], pl[ks][1], pl[ks][2], pl[ks][3],
                         vfh[nt][0], vfh[nt][1]);
                mma_bf16(oacc[nt][0], oacc[nt][1], oacc[nt][2], oacc[nt][3],
                         ph[ks][0], ph[ks][1], ph[ks][2], ph[ks][3],
                         vfh[nt][0], vfh[nt][1]);
            }
        }
    }

    float inv0 = 1.f / rs0, inv1 = 1.f / rs1;
    int trow0 = qt * 64 + wid * 16 + gid;
    #pragma unroll
    for (int nt = 0; nt < 8; nt++) {
        int col = 8 * nt + 2 * tig;
        size_t o0 = ((size_t)(b * T + trow0))     * (NH * HD) + h * HD + col;
        size_t o1 = ((size_t)(b * T + trow0 + 8)) * (NH * HD) + h * HD + col;
        split_store2(Oh, Ol, o0, oacc[nt][0] * inv0, oacc[nt][1] * inv0);
        split_store2(Oh, Ol, o1, oacc[nt][2] * inv1, oacc[nt][3] * inv1);
    }
}

// ---------------- launch ----------------
extern "C" void kernel_launch(void* const* d_in, const int* in_sizes, int n_in,
                              void* d_out, int out_size) {
    const float* hs   = (const float*)d_in[0];
    const float* cosp = (const float*)d_in[1];
    const float* sinp = (const float*)d_in[2];
    const int*   pos  = (const int*)  d_in[3];
    const float* n1w  = (const float*)d_in[5];
    const float* wq   = (const float*)d_in[6];
    const float* wk   = (const float*)d_in[7];
    const float* wv   = (const float*)d_in[8];
    const float* wo   = (const float*)d_in[9];
    const float* n2w  = (const float*)d_in[10];
    const float* wg   = (const float*)d_in[11];
    const float* wu   = (const float*)d_in[12];
    const float* wd   = (const float*)d_in[13];

    float *h2;
    cudaGetSymbolAddress((void**)&h2, g_h2);

    bf16 *woh,*wol,*wdh,*wdl;
    bf16 *xnh,*xnl,*ath,*atl,*xn2h,*xn2l,*gh,*gl;
    bf16 *qh,*ql,*kh,*kl,*vth,*vtl;
    cudaGetSymbolAddress((void**)&woh, s_wo_h);  cudaGetSymbolAddress((void**)&wol, s_wo_l);
    cudaGetSymbolAddress((void**)&wdh, s_wd_h);  cudaGetSymbolAddress((void**)&wdl, s_wd_l);
    cudaGetSymbolAddress((void**)&xnh, s_xn_h);  cudaGetSymbolAddress((void**)&xnl, s_xn_l);
    cudaGetSymbolAddress((void**)&ath, s_at_h);  cudaGetSymbolAddress((void**)&atl, s_at_l);
    cudaGetSymbolAddress((void**)&xn2h, s_xn2_h);cudaGetSymbolAddress((void**)&xn2l, s_xn2_l);
    cudaGetSymbolAddress((void**)&gh,  s_g_h);   cudaGetSymbolAddress((void**)&gl,  s_g_l);
    cudaGetSymbolAddress((void**)&qh,  s_q_h);   cudaGetSymbolAddress((void**)&ql,  s_q_l);
    cudaGetSymbolAddress((void**)&kh,  s_k_h);   cudaGetSymbolAddress((void**)&kl,  s_k_l);
    cudaGetSymbolAddress((void**)&vth, s_vt_h);  cudaGetSymbolAddress((void**)&vtl, s_vt_l);

    float* out_x = (float*)d_out;
    float* out_k = out_x + (size_t)M * H;
    float* out_v = out_k + (size_t)B * NKV * T * HD;

    cudaFuncSetAttribute(gemm_mma_kernel,
                         cudaFuncAttributeMaxDynamicSharedMemorySize, GEMM_DSMEM);
    cudaFuncSetAttribute(gemm_qkv_rope_kernel,
                         cudaFuncAttributeMaxDynamicSharedMemorySize, GEMM_DSMEM);
    cudaFuncSetAttribute(gemm_gu_silu_kernel,
                         cudaFuncAttributeMaxDynamicSharedMemorySize, GEMM_DSMEM);
    cudaFuncSetAttribute(attn_kernel,
                         cudaFuncAttributeMaxDynamicSharedMemorySize, ATTN_DSMEM);

    // 0. split ALL weights in one launch
    split_all_kernel<<<SPLIT_BLOCKS, 256>>>(wq, wk, wv, wo, wg, wu, wd);
    // 1. RMSNorm 1
    rmsnorm_split_kernel<<<M, 256>>>(hs, n1w, xnh, xnl);
    // 2. fused Q/K/V projections + RoPE + KV-cache + bf16 splits
    gemm_qkv_rope_kernel<<<dim3(24, M / 64), 256, GEMM_DSMEM>>>(
        xnh, xnl, cosp, sinp, pos, out_k, out_v, qh, ql, kh, kl, vth, vtl);
    // 3. Attention (tensor-core, 3xBF16; LPT order)
    attn_kernel<<<dim3(T / 64, NH, B), 128, ATTN_DSMEM>>>(qh, ql, kh, kl, vth, vtl, ath, atl);
    // 4. O-projection + residual
    gemm_mma_kernel<<<dim3(H / 128, M / 64), 256, GEMM_DSMEM>>>(ath, atl, woh, wol,
                                                                hs, h2, H, NH * HD);
    // 5. RMSNorm 2
    rmsnorm_split_kernel<<<M, 256>>>(h2, n2w, xn2h, xn2l);
    // 6. fused MLP gate/up + SwiGLU (M-block fast for B-stripe L2 reuse)
    gemm_gu_silu_kernel<<<dim3(M / 64, IM / 64), 256, GEMM_DSMEM>>>(xn2h, xn2l, gh, gl);
    // 7. Down projection + residual -> x output
    gemm_mma_kernel<<<dim3(H / 128, M / 64), 256, GEMM_DSMEM>>>(gh, gl, wdh, wdl,
                                                                h2, out_x, H, IM);
}

// round 16
// speedup vs baseline: 1.1415x; 1.0653x over previous
#include <cuda_runtime.h>
#include <cuda_bf16.h>
#include <math.h>
#include <stdint.h>

#define B   2
#define T   1024
#define H   2048
#define NH  32
#define NKV 8
#define HD  64
#define IM  8192
#define M   (B*T)

typedef __nv_bfloat16  bf16;
typedef __nv_bfloat162 bf162;

// ---------------- scratch (device globals; no allocation) ----------------
__device__ __align__(16) float g_h2 [M * H];
// bf16 hi/lo split weights
__device__ __align__(16) bf16 s_wq_h[NH*HD*H],  s_wq_l[NH*HD*H];
__device__ __align__(16) bf16 s_wk_h[NKV*HD*H], s_wk_l[NKV*HD*H];
__device__ __align__(16) bf16 s_wv_h[NKV*HD*H], s_wv_l[NKV*HD*H];
__device__ __align__(16) bf16 s_wo_h[H*NH*HD],  s_wo_l[H*NH*HD];
__device__ __align__(16) bf16 s_wg_h[(size_t)IM*H], s_wg_l[(size_t)IM*H];
__device__ __align__(16) bf16 s_wu_h[(size_t)IM*H], s_wu_l[(size_t)IM*H];
__device__ __align__(16) bf16 s_wd_h[(size_t)H*IM], s_wd_l[(size_t)H*IM];
// bf16 hi/lo split activations
__device__ __align__(16) bf16 s_xn_h [M*H],        s_xn_l [M*H];
__device__ __align__(16) bf16 s_at_h [M*NH*HD],    s_at_l [M*NH*HD];
__device__ __align__(16) bf16 s_xn2_h[M*H],        s_xn2_l[M*H];
__device__ __align__(16) bf16 s_g_h  [(size_t)M*IM], s_g_l[(size_t)M*IM];
// bf16 hi/lo split q/k/v for attention (head-major; v transposed)
__device__ __align__(16) bf16 s_q_h [M*NH*HD],  s_q_l [M*NH*HD];
__device__ __align__(16) bf16 s_k_h [M*NKV*HD], s_k_l [M*NKV*HD];
__device__ __align__(16) bf16 s_vt_h[M*NKV*HD], s_vt_l[M*NKV*HD];

// ---------------- helpers ----------------
__device__ __forceinline__ uint32_t smem_u32(const void* p) {
    uint32_t a;
    asm("{ .reg .u64 t; cvta.to.shared.u64 t, %1; cvt.u32.u64 %0, t; }"
        : "=r"(a) : "l"(p));
    return a;
}
__device__ __forceinline__ void cp_async16(uint32_t dst, const void* src) {
    asm volatile("cp.async.cg.shared.global [%0], [%1], 16;"
                 :: "r"(dst), "l"(src));
}
#define CP_ASYNC_COMMIT() asm volatile("cp.async.commit_group;" ::: "memory")
#define CP_ASYNC_WAIT0()  asm volatile("cp.async.wait_group 0;" ::: "memory")

#define LDMX4(r0, r1, r2, r3, addr) \
    asm volatile("ldmatrix.sync.aligned.m8n8.x4.shared.b16 {%0,%1,%2,%3}, [%4];" \
        : "=r"(r0), "=r"(r1), "=r"(r2), "=r"(r3) : "r"(addr))

__device__ __forceinline__ void mma_bf16(float& c0, float& c1, float& c2, float& c3,
                                         uint32_t a0, uint32_t a1, uint32_t a2, uint32_t a3,
                                         uint32_t b0, uint32_t b1) {
    asm volatile(
        "mma.sync.aligned.m16n8k16.row.col.f32.bf16.bf16.f32 "
        "{%0,%1,%2,%3}, {%4,%5,%6,%7}, {%8,%9}, {%0,%1,%2,%3};"
        : "+f"(c0), "+f"(c1), "+f"(c2), "+f"(c3)
        : "r"(a0), "r"(a1), "r"(a2), "r"(a3), "r"(b0), "r"(b1));
}

// split-store helpers (fp32 -> hi/lo bf16)
__device__ __forceinline__ void split_store4(bf16* __restrict__ h, bf16* __restrict__ l,
                                             size_t idx, float x, float y, float z, float w) {
    bf162 h0 = __floats2bfloat162_rn(x, y);
    bf162 h1 = __floats2bfloat162_rn(z, w);
    float lx = x - __bfloat162float(__low2bfloat16(h0));
    float ly = y - __bfloat162float(__high2bfloat16(h0));
    float lz = z - __bfloat162float(__low2bfloat16(h1));
    float lw = w - __bfloat162float(__high2bfloat16(h1));
    *(bf162*)(h + idx)     = h0;
    *(bf162*)(h + idx + 2) = h1;
    *(bf162*)(l + idx)     = __floats2bfloat162_rn(lx, ly);
    *(bf162*)(l + idx + 2) = __floats2bfloat162_rn(lz, lw);
}
__device__ __forceinline__ void split_store2(bf16* __restrict__ h, bf16* __restrict__ l,
                                             size_t idx, float x, float y) {
    bf162 h0 = __floats2bfloat162_rn(x, y);
    float lx = x - __bfloat162float(__low2bfloat16(h0));
    float ly = y - __bfloat162float(__high2bfloat16(h0));
    *(bf162*)(h + idx) = h0;
    *(bf162*)(l + idx) = __floats2bfloat162_rn(lx, ly);
}
__device__ __forceinline__ void pack_split2(float x, float y, uint32_t& hi, uint32_t& lo) {
    bf162 h0 = __floats2bfloat162_rn(x, y);
    float lx = x - __bfloat162float(__low2bfloat16(h0));
    float ly = y - __bfloat162float(__high2bfloat16(h0));
    bf162 l0 = __floats2bfloat162_rn(lx, ly);
    hi = *(uint32_t*)&h0;
    lo = *(uint32_t*)&l0;
}

// ---------------- merged weight-split kernel (32 elems/thread) --------------
// Unit = 32 fp32 elements. CORRECTED cumulative table:
//   wq 4194304/32 = 131072 | wk,wv 1048576/32 = 32768 | wo 131072
//   wg,wu,wd 16777216/32 = 524288      total = 1900544 units
#define U_WQ  131072
#define U_WK  (U_WQ + 32768)        // 163840
#define U_WV  (U_WK + 32768)        // 196608
#define U_WO  (U_WV + 131072)       // 327680
#define U_WG  (U_WO + 524288)       // 851968
#define U_WU  (U_WG + 524288)       // 1376256
#define U_WD  (U_WU + 524288)       // 1900544
#define SPLIT_BLOCKS (U_WD / 256)   // 7424

__global__ void __launch_bounds__(256)
split_all_kernel(const float* __restrict__ wq, const float* __restrict__ wk,
                 const float* __restrict__ wv, const float* __restrict__ wo,
                 const float* __restrict__ wg, const float* __restrict__ wu,
                 const float* __restrict__ wd) {
    uint32_t u = blockIdx.x * 256 + threadIdx.x;
    const float* src; bf16 *h, *l; uint32_t off;
    if (u < U_WQ)      { src = wq; h = s_wq_h; l = s_wq_l; off = u; }
    else if (u < U_WK) { src = wk; h = s_wk_h; l = s_wk_l; off = u - U_WQ; }
    else if (u < U_WV) { src = wv; h = s_wv_h; l = s_wv_l; off = u - U_WK; }
    else if (u < U_WO) { src = wo; h = s_wo_h; l = s_wo_l; off = u - U_WV; }
    else if (u < U_WG) { src = wg; h = s_wg_h; l = s_wg_l; off = u - U_WO; }
    else if (u < U_WU) { src = wu; h = s_wu_h; l = s_wu_l; off = u - U_WG; }
    else               { src = wd; h = s_wd_h; l = s_wd_l; off = u - U_WU; }

    size_t e = (size_t)off * 32;
    float4 a[8];
    #pragma unroll
    for (int i = 0; i < 8; i++) a[i] = ((const float4*)(src + e))[i];   // MLP=8
    #pragma unroll
    for (int i = 0; i < 4; i++) {
        uint32_t h0, h1, h2, h3, l0, l1, l2, l3;
        pack_split2(a[2*i].x,   a[2*i].y,   h0, l0);
        pack_split2(a[2*i].z,   a[2*i].w,   h1, l1);
        pack_split2(a[2*i+1].x, a[2*i+1].y, h2, l2);
        pack_split2(a[2*i+1].z, a[2*i+1].w, h3, l3);
        ((uint4*)(h + e))[i] = make_uint4(h0, h1, h2, h3);
        ((uint4*)(l + e))[i] = make_uint4(l0, l1, l2, l3);
    }
}

// ---------------- 3xBF16 GEMM mainloop (K-chunk 64, 2-stage cp.async) -------
#define RPAD 36                                   // uints per 64-bf16 row (32 + 4 pad)
#define ATILE_U (64 * RPAD)                       // 2304
#define BTILE_U (128 * RPAD)                      // 4608
#define STAGE_U (2 * ATILE_U + 2 * BTILE_U)       // 13824 uints = 55296 B
#define GEMM_DSMEM (2 * STAGE_U * 4)              // 110592 B (2 CTAs = 221 KB/SM)

__device__ __forceinline__ void gemm_mainloop(float* sm,
                                              const bf16* __restrict__ Ah, const bf16* __restrict__ Al,
                                              const bf16* __restrict__ Bh, const bf16* __restrict__ Bl,
                                              int K, int bm, int bn,
                                              float (&acc)[2][4][4]) {
    const uint32_t smem_base = smem_u32(sm);
    const int tid  = threadIdx.x;
    const int wid  = tid >> 5;
    const int lane = tid & 31;
    const int wm   = wid >> 2;
    const int wn   = wid & 3;
    const int KC   = K >> 6;                      // chunks of 64

    const int sub  = lane >> 3;
    const int r8   = lane & 7;
    const int arow = ((sub & 1) << 3) + r8;
    const int akof = (sub >> 1) << 4;
    const int brow = ((sub >> 1) << 3) + r8;
    const int bkof = (sub & 1) << 4;

    uint32_t aaddr[2][2], baddr[2][2];
    #pragma unroll
    for (int mt = 0; mt < 2; mt++) {
        uint32_t base = smem_base + (uint32_t)((wm * 32 + mt * 16 + arow) * RPAD) * 4 + akof;
        aaddr[mt][0] = base;
        aaddr[mt][1] = base + ATILE_U * 4;
    }
    #pragma unroll
    for (int np = 0; np < 2; np++) {
        uint32_t base = smem_base + (uint32_t)(2 * ATILE_U + (wn * 32 + np * 16 + brow) * RPAD) * 4 + bkof;
        baddr[np][0] = base;
        baddr[np][1] = base + BTILE_U * 4;
    }

    #pragma unroll
    for (int i = 0; i < 2; i++)
        #pragma unroll
        for (int j = 0; j < 4; j++)
            #pragma unroll
            for (int k = 0; k < 4; k++) acc[i][j][k] = 0.f;

    auto issue_load = [&](int c, int buf) {
        const int k0 = c << 6;
        uint32_t st = smem_base + buf * (STAGE_U * 4);
        // A hi/lo: 64 rows x 64 bf16 (512 16B chunks each -> 2/thread)
        #pragma unroll
        for (int it = 0; it < 2; it++) {
            int idx = tid + it * 256;
            int row = idx >> 3, ch = idx & 7;
            cp_async16(st + (row * RPAD + ch * 4) * 4,
                       Ah + (size_t)(bm + row) * K + k0 + ch * 8);
            cp_async16(st + (ATILE_U + row * RPAD + ch * 4) * 4,
                       Al + (size_t)(bm + row) * K + k0 + ch * 8);
        }
        // B hi/lo: 128 rows (1024 chunks each -> 4/thread)
        #pragma unroll
        for (int it = 0; it < 4; it++) {
            int idx = tid + it * 256;
            int row = idx >> 3, ch = idx & 7;
            cp_async16(st + (2 * ATILE_U + row * RPAD + ch * 4) * 4,
                       Bh + (size_t)(bn + row) * K + k0 + ch * 8);
            cp_async16(st + (2 * ATILE_U + BTILE_U + row * RPAD + ch * 4) * 4,
                       Bl + (size_t)(bn + row) * K + k0 + ch * 8);
        }
        CP_ASYNC_COMMIT();
    };

    issue_load(0, 0);

    for (int c = 0; c < KC; c++) {
        const int buf = c & 1;
        CP_ASYNC_WAIT0();
        __syncthreads();
        if (c + 1 < KC) issue_load(c + 1, buf ^ 1);

        const uint32_t boff = (uint32_t)buf * (STAGE_U * 4);

        #pragma unroll
        for (int ks = 0; ks < 4; ks++) {
            const uint32_t koff = boff + ks * 32;
            uint32_t ahf[2][4], alf[2][4], bhf[4][2], blf[4][2];
            #pragma unroll
            for (int mt = 0; mt < 2; mt++) {
                LDMX4(ahf[mt][0], ahf[mt][1], ahf[mt][2], ahf[mt][3], aaddr[mt][0] + koff);
                LDMX4(alf[mt][0], alf[mt][1], alf[mt][2], alf[mt][3], aaddr[mt][1] + koff);
            }
            #pragma unroll
            for (int np = 0; np < 2; np++) {
                LDMX4(bhf[2*np][0], bhf[2*np][1], bhf[2*np+1][0], bhf[2*np+1][1],
                      baddr[np][0] + koff);
                LDMX4(blf[2*np][0], blf[2*np][1], blf[2*np+1][0], blf[2*np+1][1],
                      baddr[np][1] + koff);
            }
            #pragma unroll
            for (int mt = 0; mt < 2; mt++)
                #pragma unroll
                for (int nt = 0; nt < 4; nt++) {
                    mma_bf16(acc[mt][nt][0], acc[mt][nt][1],
                             acc[mt][nt][2], acc[mt][nt][3],
                             ahf[mt][0], ahf[mt][1], ahf[mt][2], ahf[mt][3],
                             blf[nt][0], blf[nt][1]);
                    mma_bf16(acc[mt][nt][0], acc[mt][nt][1],
                             acc[mt][nt][2], acc[mt][nt][3],
                             alf[mt][0], alf[mt][1], alf[mt][2], alf[mt][3],
                             bhf[nt][0], bhf[nt][1]);
                    mma_bf16(acc[mt][nt][0], acc[mt][nt][1],
                             acc[mt][nt][2], acc[mt][nt][3],
                             ahf[mt][0], ahf[mt][1], ahf[mt][2], ahf[mt][3],
                             bhf[nt][0], bhf[nt][1]);
                }
        }
        // buffer reuse protected by the post-wait barrier of iteration c+1
    }
}

// ---- generic GEMM (o-proj, down-proj) ----
__global__ void __launch_bounds__(256, 2)
gemm_mma_kernel(const bf16* __restrict__ Ah, const bf16* __restrict__ Al,
                const bf16* __restrict__ Bh, const bf16* __restrict__ Bl,
                const float* __restrict__ res, float* __restrict__ C,
                int N, int K) {
    extern __shared__ float sm[];
    const int bm = blockIdx.y * 64;
    const int bn = blockIdx.x * 128;
    float acc[2][4][4];
    gemm_mainloop(sm, Ah, Al, Bh, Bl, K, bm, bn, acc);

    const int tid = threadIdx.x, wid = tid >> 5, lane = tid & 31;
    const int wm = wid >> 2, wn = wid & 3;
    const int gid = lane >> 2, tig = lane & 3;
    #pragma unroll
    for (int mt = 0; mt < 2; mt++) {
        int r0 = bm + wm * 32 + mt * 16 + gid;
        #pragma unroll
        for (int nt = 0; nt < 4; nt++) {
            int col = bn + wn * 32 + nt * 8 + tig * 2;
            size_t o0 = (size_t)r0 * N + col;
            size_t o1 = (size_t)(r0 + 8) * N + col;
            float2 v0 = make_float2(acc[mt][nt][0], acc[mt][nt][1]);
            float2 v1 = make_float2(acc[mt][nt][2], acc[mt][nt][3]);
            if (res) {
                float2 r0v = *(const float2*)(res + o0);
                float2 r1v = *(const float2*)(res + o1);
                v0.x += r0v.x; v0.y += r0v.y;
                v1.x += r1v.x; v1.y += r1v.y;
            }
            *(float2*)(C + o0) = v0;
            *(float2*)(C + o1) = v1;
        }
    }
}

// ---- fused QKV projection + RoPE + KV-cache + bf16 splits -----------------
__global__ void __launch_bounds__(256, 2)
gemm_qkv_rope_kernel(const bf16* __restrict__ Ah, const bf16* __restrict__ Al,
                     const float* __restrict__ cosp, const float* __restrict__ sinp,
                     const int* __restrict__ pos,
                     float* __restrict__ outk, float* __restrict__ outv,
                     bf16* __restrict__ qh, bf16* __restrict__ ql,
                     bf16* __restrict__ kh, bf16* __restrict__ kl,
                     bf16* __restrict__ vth, bf16* __restrict__ vtl) {
    extern __shared__ float sm[];
    const int ct = blockIdx.x;
    const int bm = blockIdx.y * 64;
    const bf16 *Bh, *Bl; int bn;
    if (ct < 16)      { Bh = s_wq_h; Bl = s_wq_l; bn = ct * 128; }
    else if (ct < 20) { Bh = s_wk_h; Bl = s_wk_l; bn = (ct - 16) * 128; }
    else              { Bh = s_wv_h; Bl = s_wv_l; bn = (ct - 20) * 128; }

    float acc[2][4][4];
    gemm_mainloop(sm, Ah, Al, Bh, Bl, H, bm, bn, acc);

    const int tid = threadIdx.x, wid = tid >> 5, lane = tid & 31;
    const int wm = wid >> 2, wn = wid & 3;
    const int gid = lane >> 2, tig = lane & 3;

    #pragma unroll
    for (int mt = 0; mt < 2; mt++) {
        #pragma unroll
        for (int r = 0; r < 2; r++) {
            int grow = bm + wm * 32 + mt * 16 + gid + r * 8;   // bt index
            int t = grow & (T - 1);
            int b = grow >> 10;
            int p = pos[grow];
            #pragma unroll
            for (int nt = 0; nt < 4; nt++) {
                int col = bn + wn * 32 + nt * 8 + tig * 2;
                float x1 = acc[mt][nt][r * 2 + 0];
                float x2 = acc[mt][nt][r * 2 + 1];
                int h = col >> 6, d = col & 63, d2 = d >> 1;
                if (ct < 16) {
                    float c = cosp[p * 32 + d2], s = sinp[p * 32 + d2];
                    float r1 = x1 * c - x2 * s;
                    float r2 = x1 * s + x2 * c;
                    size_t ob = ((size_t)(b * NH + h) * T + t) * HD + d;
                    split_store2(qh, ql, ob, r1, r2);
                } else if (ct < 20) {
                    float c = cosp[p * 32 + d2], s = sinp[p * 32 + d2];
                    float r1 = x1 * c - x2 * s;
                    float r2 = x1 * s + x2 * c;
                    size_t ob = ((size_t)(b * NKV + h) * T + t) * HD + d;
                    *(float2*)(outk + ob) = make_float2(r1, r2);
                    split_store2(kh, kl, ob, r1, r2);
                } else {
                    size_t ob = ((size_t)(b * NKV + h) * T + t) * HD + d;
                    *(float2*)(outv + ob) = make_float2(x1, x2);
                    size_t vb = ((size_t)(b * NKV + h) * HD + d) * T + t;
                    bf16 h1b = __float2bfloat16(x1);
                    bf16 h2b = __float2bfloat16(x2);
                    vth[vb]     = h1b;
                    vtl[vb]     = __float2bfloat16(x1 - __bfloat162float(h1b));
                    vth[vb + T] = h2b;
                    vtl[vb + T] = __float2bfloat16(x2 - __bfloat162float(h2b));
                }
            }
        }
    }
}

// ---- fused gate/up + SwiGLU; grid: x = M-block (fast), y = N64-block -------
__global__ void __launch_bounds__(256, 2)
gemm_gu_silu_kernel(const bf16* __restrict__ Ah, const bf16* __restrict__ Al,
                    bf16* __restrict__ gh, bf16* __restrict__ gl) {
    extern __shared__ float sm[];
    const uint32_t smem_base = smem_u32(sm);
    const int bm = blockIdx.x * 64;
    const int bn = blockIdx.y * 64;
    const int K  = H, KC = K >> 6;

    const int tid  = threadIdx.x;
    const int wid  = tid >> 5;
    const int lane = tid & 31;
    const int wsel = wid >> 2;           // 0 = gate, 1 = up
    const int wq   = wid & 3;
    const int wm   = wq >> 1;
    const int wn   = wq & 1;
    const int gid  = lane >> 2;
    const int tig  = lane & 3;

    const int sub  = lane >> 3;
    const int r8   = lane & 7;
    const int arow = ((sub & 1) << 3) + r8;
    const int akof = (sub >> 1) << 4;
    const int brow = ((sub >> 1) << 3) + r8;
    const int bkof = (sub & 1) << 4;

    // stage layout: 6 tiles of ATILE_U uints: A_h, A_l, Bg_h, Bg_l, Bu_h, Bu_l
    uint32_t aaddr[2][2], baddr[2][2];
    #pragma unroll
    for (int mt = 0; mt < 2; mt++) {
        uint32_t base = smem_base + (uint32_t)((wm * 32 + mt * 16 + arow) * RPAD) * 4 + akof;
        aaddr[mt][0] = base;
        aaddr[mt][1] = base + ATILE_U * 4;
    }
    #pragma unroll
    for (int np = 0; np < 2; np++) {
        uint32_t base = smem_base +
            (uint32_t)((2 + 2 * wsel) * ATILE_U + (wn * 32 + np * 16 + brow) * RPAD) * 4 + bkof;
        baddr[np][0] = base;
        baddr[np][1] = base + ATILE_U * 4;
    }

    const bf16* Bgh = s_wg_h; const bf16* Bgl = s_wg_l;
    const bf16* Buh = s_wu_h; const bf16* Bul = s_wu_l;

    float acc[2][4][4];
    #pragma unroll
    for (int i = 0; i < 2; i++)
        #pragma unroll
        for (int j = 0; j < 4; j++)
            #pragma unroll
            for (int k = 0; k < 4; k++) acc[i][j][k] = 0.f;

    auto issue_load = [&](int c, int buf) {
        const int k0 = c << 6;
        uint32_t st = smem_base + buf * (STAGE_U * 4);
        #pragma unroll
        for (int it = 0; it < 2; it++) {
            int idx = tid + it * 256;
            int row = idx >> 3, ch = idx & 7;
            uint32_t soff = (row * RPAD + ch * 4) * 4;
            size_t goff = (size_t)row * K + k0 + ch * 8;
            cp_async16(st + 0 * ATILE_U * 4 + soff, Ah  + (size_t)bm * K + goff);
            cp_async16(st + 1 * ATILE_U * 4 + soff, Al  + (size_t)bm * K + goff);
            cp_async16(st + 2 * ATILE_U * 4 + soff, Bgh + (size_t)bn * K + goff);
            cp_async16(st + 3 * ATILE_U * 4 + soff, Bgl + (size_t)bn * K + goff);
            cp_async16(st + 4 * ATILE_U * 4 + soff, Buh + (size_t)bn * K + goff);
            cp_async16(st + 5 * ATILE_U * 4 + soff, Bul + (size_t)bn * K + goff);
        }
        CP_ASYNC_COMMIT();
    };

    issue_load(0, 0);

    for (int c = 0; c < KC; c++) {
        const int buf = c & 1;
        CP_ASYNC_WAIT0();
        __syncthreads();
        if (c + 1 < KC) issue_load(c + 1, buf ^ 1);

        const uint32_t boff = (uint32_t)buf * (STAGE_U * 4);

        #pragma unroll
        for (int ks = 0; ks < 4; ks++) {
            const uint32_t koff = boff + ks * 32;
            uint32_t ahf[2][4], alf[2][4], bhf[4][2], blf[4][2];
            #pragma unroll
            for (int mt = 0; mt < 2; mt++) {
                LDMX4(ahf[mt][0], ahf[mt][1], ahf[mt][2], ahf[mt][3], aaddr[mt][0] + koff);
                LDMX4(alf[mt][0], alf[mt][1], alf[mt][2], alf[mt][3], aaddr[mt][1] + koff);
            }
            #pragma unroll
            for (int np = 0; np < 2; np++) {
                LDMX4(bhf[2*np][0], bhf[2*np][1], bhf[2*np+1][0], bhf[2*np+1][1],
                      baddr[np][0] + koff);
                LDMX4(blf[2*np][0], blf[2*np][1], blf[2*np+1][0], blf[2*np+1][1],
                      baddr[np][1] + koff);
            }
            #pragma unroll
            for (int mt = 0; mt < 2; mt++)
                #pragma unroll
                for (int nt = 0; nt < 4; nt++) {
                    mma_bf16(acc[mt][nt][0], acc[mt][nt][1],
                             acc[mt][nt][2], acc[mt][nt][3],
                             ahf[mt][0], ahf[mt][1], ahf[mt][2], ahf[mt][3],
                             blf[nt][0], blf[nt][1]);
                    mma_bf16(acc[mt][nt][0], acc[mt][nt][1],
                             acc[mt][nt][2], acc[mt][nt][3],
                             alf[mt][0], alf[mt][1], alf[mt][2], alf[mt][3],
                             bhf[nt][0], bhf[nt][1]);
                    mma_bf16(acc[mt][nt][0], acc[mt][nt][1],
                             acc[mt][nt][2], acc[mt][nt][3],
                             ahf[mt][0], ahf[mt][1], ahf[mt][2], ahf[mt][3],
                             bhf[nt][0], bhf[nt][1]);
                }
        }
    }

    // ---- epilogue: exchange gate accs via smem, apply silu*up, split-store --
    float (*sx)[66] = (float (*)[66])sm;
    __syncthreads();
    if (wsel == 0) {
        #pragma unroll
        for (int mt = 0; mt < 2; mt++) {
            int lr = wm * 32 + mt * 16 + gid;
            #pragma unroll
            for (int nt = 0; nt < 4; nt++) {
                int lc = wn * 32 + nt * 8 + tig * 2;
                sx[lr][lc]     = acc[mt][nt][0];
                sx[lr][lc + 1] = acc[mt][nt][1];
                sx[lr + 8][lc]     = acc[mt][nt][2];
                sx[lr + 8][lc + 1] = acc[mt][nt][3];
            }
        }
    }
    __syncthreads();
    if (wsel == 1) {
        #pragma unroll
        for (int mt = 0; mt < 2; mt++) {
            int lr = wm * 32 + mt * 16 + gid;
            #pragma unroll
            for (int nt = 0; nt < 4; nt++) {
                int lc = wn * 32 + nt * 8 + tig * 2;
                float g0 = sx[lr][lc],     g1 = sx[lr][lc + 1];
                float g2 = sx[lr + 8][lc], g3 = sx[lr + 8][lc + 1];
                float r0 = g0 / (1.f + __expf(-g0)) * acc[mt][nt][0];
                float r1 = g1 / (1.f + __expf(-g1)) * acc[mt][nt][1];
                float r2 = g2 / (1.f + __expf(-g2)) * acc[mt][nt][2];
                float r3 = g3 / (1.f + __expf(-g3)) * acc[mt][nt][3];
                size_t o0 = (size_t)(bm + lr)     * IM + bn + lc;
                size_t o1 = (size_t)(bm + lr + 8) * IM + bn + lc;
                split_store2(gh, gl, o0, r0, r1);
                split_store2(gh, gl, o1, r2, r3);
            }
        }
    }
}

// ---------------- RMSNorm with split output ----------------
__global__ void rmsnorm_split_kernel(const float* __restrict__ x,
                                     const float* __restrict__ w,
                                     bf16* __restrict__ oh, bf16* __restrict__ ol) {
    int row = blockIdx.x;
    const float* xr = x + (size_t)row * H;
    float ss = 0.f;
    for (int i = threadIdx.x; i < H / 4; i += blockDim.x) {
        float4 v = ((const float4*)xr)[i];
        ss += v.x * v.x + v.y * v.y + v.z * v.z + v.w * v.w;
    }
    __shared__ float red[32];
    #pragma unroll
    for (int o = 16; o; o >>= 1) ss += __shfl_xor_sync(0xffffffffu, ss, o);
    if ((threadIdx.x & 31) == 0) red[threadIdx.x >> 5] = ss;
    __syncthreads();
    if (threadIdx.x < 32) {
        float v = (threadIdx.x < (blockDim.x >> 5)) ? red[threadIdx.x] : 0.f;
        #pragma unroll
        for (int o = 16; o; o >>= 1) v += __shfl_xor_sync(0xffffffffu, v, o);
        if (threadIdx.x == 0) red[0] = v;
    }
    __syncthreads();
    float r = rsqrtf(red[0] / (float)H + 1e-6f);
    for (int i = threadIdx.x; i < H / 4; i += blockDim.x) {
        float4 v = ((const float4*)xr)[i];
        float4 wv = ((const float4*)w)[i];
        split_store4(oh, ol, (size_t)row * H + 4 * i,
                     v.x * r * wv.x, v.y * r * wv.y, v.z * r * wv.z, v.w * r * wv.w);
    }
}

// ---------------- Flash attention (3xBF16 mma, 64 q rows/CTA, 4 warps) ------
#define AT_RPAD 36
#define AT_TILE_U (64 * AT_RPAD)
#define ATTN_DSMEM (6 * AT_TILE_U * 4)

__global__ void __launch_bounds__(128)
attn_kernel(const bf16* __restrict__ Qh_g, const bf16* __restrict__ Ql_g,
            const bf16* __restrict__ Kh_g, const bf16* __restrict__ Kl_g,
            const bf16* __restrict__ Vth_g, const bf16* __restrict__ Vtl_g,
            bf16* __restrict__ Oh, bf16* __restrict__ Ol) {
    extern __shared__ uint32_t smu[];
    const int qt = (int)(gridDim.x - 1 - blockIdx.x);   // LPT: heavy tiles first
    const int h = blockIdx.y, b = blockIdx.z;
    const int kvh = h >> 2;
    const int tid = threadIdx.x, wid = tid >> 5, lane = tid & 31;
    const int gid = lane >> 2, tig = lane & 3;
    const int sub = lane >> 3, r8 = lane & 7;
    const int arow = ((sub & 1) << 3) + r8;
    const int akof = (sub >> 1) << 4;
    const int brow = ((sub >> 1) << 3) + r8;
    const int bkof = (sub & 1) << 4;

    const uint32_t smem_base = smem_u32(smu);
    const uint32_t Qh_s = smem_base;
    const uint32_t Ql_s = Qh_s + AT_TILE_U * 4;
    const uint32_t Kh_s = Ql_s + AT_TILE_U * 4;
    const uint32_t Kl_s = Kh_s + AT_TILE_U * 4;
    const uint32_t Vh_s = Kl_s + AT_TILE_U * 4;
    const uint32_t Vl_s = Vh_s + AT_TILE_U * 4;

    {
        const bf16* qh = Qh_g + ((size_t)(b * NH + h) * T + qt * 64) * HD;
        const bf16* ql = Ql_g + ((size_t)(b * NH + h) * T + qt * 64) * HD;
        #pragma unroll
        for (int it = 0; it < 4; it++) {
            int idx = tid + it * 128;
            int row = idx >> 3, ch = idx & 7;
            cp_async16(Qh_s + (row * AT_RPAD + ch * 4) * 4, qh + (size_t)row * HD + ch * 8);
            cp_async16(Ql_s + (row * AT_RPAD + ch * 4) * 4, ql + (size_t)row * HD + ch * 8);
        }
        CP_ASYNC_COMMIT();
        CP_ASYNC_WAIT0();
        __syncthreads();
    }
    uint32_t qfh[4][4], qfl[4][4];
    {
        uint32_t qa = (uint32_t)((wid * 16 + arow) * AT_RPAD) * 4 + akof;
        #pragma unroll
        for (int ks = 0; ks < 4; ks++) {
            LDMX4(qfh[ks][0], qfh[ks][1], qfh[ks][2], qfh[ks][3], Qh_s + qa + ks * 32);
            LDMX4(qfl[ks][0], qfl[ks][1], qfl[ks][2], qfl[ks][3], Ql_s + qa + ks * 32);
        }
    }

    float oacc[8][4];
    #pragma unroll
    for (int i = 0; i < 8; i++)
        #pragma unroll
        for (int j = 0; j < 4; j++) oacc[i][j] = 0.f;
    float rm0 = -1e30f, rm1 = -1e30f, rs0 = 0.f, rs1 = 0.f;

    for (int kt = 0; kt <= qt; kt++) {
        __syncthreads();
        {
            const bf16* kh  = Kh_g  + ((size_t)(b * NKV + kvh) * T + kt * 64) * HD;
            const bf16* kl  = Kl_g  + ((size_t)(b * NKV + kvh) * T + kt * 64) * HD;
            const bf16* vth = Vth_g + (size_t)(b * NKV + kvh) * HD * T;
            const bf16* vtl = Vtl_g + (size_t)(b * NKV + kvh) * HD * T;
            #pragma unroll
            for (int it = 0; it < 4; it++) {
                int idx = tid + it * 128;
                int row = idx >> 3, ch = idx & 7;
                uint32_t soff = (row * AT_RPAD + ch * 4) * 4;
                cp_async16(Kh_s + soff, kh + (size_t)row * HD + ch * 8);
                cp_async16(Kl_s + soff, kl + (size_t)row * HD + ch * 8);
                cp_async16(Vh_s + soff, vth + (size_t)row * T + kt * 64 + ch * 8);
                cp_async16(Vl_s + soff, vtl + (size_t)row * T + kt * 64 + ch * 8);
            }
            CP_ASYNC_COMMIT();
            CP_ASYNC_WAIT0();
            __syncthreads();
        }

        float sacc[8][4];
        #pragma unroll
        for (int i = 0; i < 8; i++)
            #pragma unroll
            for (int j = 0; j < 4; j++) sacc[i][j] = 0.f;

        #pragma unroll
        for (int ks = 0; ks < 4; ks++) {
            uint32_t kfh[8][2], kfl[8][2];
            #pragma unroll
            for (int np = 0; np < 4; np++) {
                uint32_t ka = (uint32_t)((np * 16 + brow) * AT_RPAD) * 4 + bkof + ks * 32;
                LDMX4(kfh[2*np][0], kfh[2*np][1], kfh[2*np+1][0], kfh[2*np+1][1], Kh_s + ka);
                LDMX4(kfl[2*np][0], kfl[2*np][1], kfl[2*np+1][0], kfl[2*np+1][1], Kl_s + ka);
            }
            #pragma unroll
            for (int nt = 0; nt < 8; nt++) {
                mma_bf16(sacc[nt][0], sacc[nt][1], sacc[nt][2], sacc[nt][3],
                         qfh[ks][0], qfh[ks][1], qfh[ks][2], qfh[ks][3],
                         kfl[nt][0], kfl[nt][1]);
                mma_bf16(sacc[nt][0], sacc[nt][1], sacc[nt][2], sacc[nt][3],
                         qfl[ks][0], qfl[ks][1], qfl[ks][2], qfl[ks][3],
                         kfh[nt][0], kfh[nt][1]);
                mma_bf16(sacc[nt][0], sacc[nt][1], sacc[nt][2], sacc[nt][3],
                         qfh[ks][0], qfh[ks][1], qfh[ks][2], qfh[ks][3],
                         kfh[nt][0], kfh[nt][1]);
            }
        }

        const float scale = 0.125f;
        if (kt == qt) {
            #pragma unroll
            for (int nt = 0; nt < 8; nt++)
                #pragma unroll
                for (int c = 0; c < 4; c++) {
                    int col = 8 * nt + 2 * tig + (c & 1);
                    int row = wid * 16 + gid + ((c >> 1) << 3);
                    sacc[nt][c] = (col <= row) ? sacc[nt][c] * scale : -1e30f;
                }
        } else {
            #pragma unroll
            for (int nt = 0; nt < 8; nt++)
                #pragma unroll
                for (int c = 0; c < 4; c++) sacc[nt][c] *= scale;
        }

        float mx0 = -1e30f, mx1 = -1e30f;
        #pragma unroll
        for (int nt = 0; nt < 8; nt++) {
            mx0 = fmaxf(mx0, fmaxf(sacc[nt][0], sacc[nt][1]));
            mx1 = fmaxf(mx1, fmaxf(sacc[nt][2], sacc[nt][3]));
        }
        mx0 = fmaxf(mx0, __shfl_xor_sync(0xffffffffu, mx0, 1));
        mx0 = fmaxf(mx0, __shfl_xor_sync(0xffffffffu, mx0, 2));
        mx1 = fmaxf(mx1, __shfl_xor_sync(0xffffffffu, mx1, 1));
        mx1 = fmaxf(mx1, __shfl_xor_sync(0xffffffffu, mx1, 2));
        float nrm0 = fmaxf(rm0, mx0), nrm1 = fmaxf(rm1, mx1);
        float al0 = __expf(rm0 - nrm0), al1 = __expf(rm1 - nrm1);
        rm0 = nrm0; rm1 = nrm1;

        float p[8][4];
        float sum0 = 0.f, sum1 = 0.f;
        #pragma unroll
        for (int nt = 0; nt < 8; nt++) {
            p[nt][0] = __expf(sacc[nt][0] - nrm0); sum0 += p[nt][0];
            p[nt][1] = __expf(sacc[nt][1] - nrm0); sum0 += p[nt][1];
            p[nt][2] = __expf(sacc[nt][2] - nrm1); sum1 += p[nt][2];
            p[nt][3] = __expf(sacc[nt][3] - nrm1); sum1 += p[nt][3];
        }
        sum0 += __shfl_xor_sync(0xffffffffu, sum0, 1);
        sum0 += __shfl_xor_sync(0xffffffffu, sum0, 2);
        sum1 += __shfl_xor_sync(0xffffffffu, sum1, 1);
        sum1 += __shfl_xor_sync(0xffffffffu, sum1, 2);
        rs0 = rs0 * al0 + sum0;
        rs1 = rs1 * al1 + sum1;
        #pragma unroll
        for (int nt = 0; nt < 8; nt++) {
            oacc[nt][0] *= al0; oacc[nt][1] *= al0;
            oacc[nt][2] *= al1; oacc[nt][3] *= al1;
        }

        uint32_t ph[4][4], pl[4][4];
        #pragma unroll
        for (int ks = 0; ks < 4; ks++) {
            pack_split2(p[2*ks][0],   p[2*ks][1],   ph[ks][0], pl[ks][0]);
            pack_split2(p[2*ks][2],   p[2*ks][3],   ph[ks][1], pl[ks][1]);
            pack_split2(p[2*ks+1][0], p[2*ks+1][1], ph[ks][2], pl[ks][2]);
            pack_split2(p[2*ks+1][2], p[2*ks+1][3], ph[ks][3], pl[ks][3]);
        }

        #pragma unroll
        for (int ks = 0; ks < 4; ks++) {
            uint32_t vfh[8][2], vfl[8][2];
            #pragma unroll
            for (int np = 0; np < 4; np++) {
                uint32_t va = (uint32_t)((np * 16 + brow) * AT_RPAD) * 4 + bkof + ks * 32;
                LDMX4(vfh[2*np][0], vfh[2*np][1], vfh[2*np+1][0], vfh[2*np+1][1], Vh_s + va);
                LDMX4(vfl[2*np][0], vfl[2*np][1], vfl[2*np+1][0], vfl[2*np+1][1], Vl_s + va);
            }
            #pragma unroll
            for (int nt = 0; nt < 8; nt++) {
                mma_bf16(oacc[nt][0], oacc[nt][1], oacc[nt][2], oacc[nt][3],
                         ph[ks][0], ph[ks][1], ph[ks][2], ph[ks][3],
                         vfl[nt][0], vfl[nt][1]);
                mma_bf16(oacc[nt][0], oacc[nt][1], oacc[nt][2], oacc[nt][3],
                         pl[ks][0], pl[ks][1], pl[ks][2], pl[ks][3],
                         vfh[nt][0], vfh[nt][1]);
                mma_bf16(oacc[nt][0], oacc[nt][1], oacc[nt][2], oacc[nt][3],
                         ph[ks][0], ph[ks][1], ph[ks][2], ph[ks][3],
                         vfh[nt][0], vfh[nt][1]);
            }
        }
    }

    float inv0 = 1.f / rs0, inv1 = 1.f / rs1;
    int trow0 = qt * 64 + wid * 16 + gid;
    #pragma unroll
    for (int nt = 0; nt < 8; nt++) {
        int col = 8 * nt + 2 * tig;
        size_t o0 = ((size_t)(b * T + trow0))     * (NH * HD) + h * HD + col;
        size_t o1 = ((size_t)(b * T + trow0 + 8)) * (NH * HD) + h * HD + col;
        split_store2(Oh, Ol, o0, oacc[nt][0] * inv0, oacc[nt][1] * inv0);
        split_store2(Oh, Ol, o1, oacc[nt][2] * inv1, oacc[nt][3] * inv1);
    }
}

// ---------------- launch ----------------
extern "C" void kernel_launch(void* const* d_in, const int* in_sizes, int n_in,
                              void* d_out, int out_size) {
    const float* hs   = (const float*)d_in[0];
    const float* cosp = (const float*)d_in[1];
    const float* sinp = (const float*)d_in[2];
    const int*   pos  = (const int*)  d_in[3];
    const float* n1w  = (const float*)d_in[5];
    const float* wq   = (const float*)d_in[6];
    const float* wk   = (const float*)d_in[7];
    const float* wv   = (const float*)d_in[8];
    const float* wo   = (const float*)d_in[9];
    const float* n2w  = (const float*)d_in[10];
    const float* wg   = (const float*)d_in[11];
    const float* wu   = (const float*)d_in[12];
    const float* wd   = (const float*)d_in[13];

    float *h2;
    cudaGetSymbolAddress((void**)&h2, g_h2);

    bf16 *woh,*wol,*wdh,*wdl;
    bf16 *xnh,*xnl,*ath,*atl,*xn2h,*xn2l,*gh,*gl;
    bf16 *qh,*ql,*kh,*kl,*vth,*vtl;
    cudaGetSymbolAddress((void**)&woh, s_wo_h);  cudaGetSymbolAddress((void**)&wol, s_wo_l);
    cudaGetSymbolAddress((void**)&wdh, s_wd_h);  cudaGetSymbolAddress((void**)&wdl, s_wd_l);
    cudaGetSymbolAddress((void**)&xnh, s_xn_h);  cudaGetSymbolAddress((void**)&xnl, s_xn_l);
    cudaGetSymbolAddress((void**)&ath, s_at_h);  cudaGetSymbolAddress((void**)&atl, s_at_l);
    cudaGetSymbolAddress((void**)&xn2h, s_xn2_h);cudaGetSymbolAddress((void**)&xn2l, s_xn2_l);
    cudaGetSymbolAddress((void**)&gh,  s_g_h);   cudaGetSymbolAddress((void**)&gl,  s_g_l);
    cudaGetSymbolAddress((void**)&qh,  s_q_h);   cudaGetSymbolAddress((void**)&ql,  s_q_l);
    cudaGetSymbolAddress((void**)&kh,  s_k_h);   cudaGetSymbolAddress((void**)&kl,  s_k_l);
    cudaGetSymbolAddress((void**)&vth, s_vt_h);  cudaGetSymbolAddress((void**)&vtl, s_vt_l);

    float* out_x = (float*)d_out;
    float* out_k = out_x + (size_t)M * H;
    float* out_v = out_k + (size_t)B * NKV * T * HD;

    cudaFuncSetAttribute(gemm_mma_kernel,
                         cudaFuncAttributeMaxDynamicSharedMemorySize, GEMM_DSMEM);
    cudaFuncSetAttribute(gemm_qkv_rope_kernel,
                         cudaFuncAttributeMaxDynamicSharedMemorySize, GEMM_DSMEM);
    cudaFuncSetAttribute(gemm_gu_silu_kernel,
                         cudaFuncAttributeMaxDynamicSharedMemorySize, GEMM_DSMEM);
    cudaFuncSetAttribute(attn_kernel,
                         cudaFuncAttributeMaxDynamicSharedMemorySize, ATTN_DSMEM);

    // 0. split ALL weights in one launch (32 elems/thread, MLP=8)
    split_all_kernel<<<SPLIT_BLOCKS, 256>>>(wq, wk, wv, wo, wg, wu, wd);
    // 1. RMSNorm 1
    rmsnorm_split_kernel<<<M, 256>>>(hs, n1w, xnh, xnl);
    // 2. fused Q/K/V projections + RoPE + KV-cache + bf16 splits
    gemm_qkv_rope_kernel<<<dim3(24, M / 64), 256, GEMM_DSMEM>>>(
        xnh, xnl, cosp, sinp, pos, out_k, out_v, qh, ql, kh, kl, vth, vtl);
    // 3. Attention (tensor-core, 3xBF16; LPT order)
    attn_kernel<<<dim3(T / 64, NH, B), 128, ATTN_DSMEM>>>(qh, ql, kh, kl, vth, vtl, ath, atl);
    // 4. O-projection + residual
    gemm_mma_kernel<<<dim3(H / 128, M / 64), 256, GEMM_DSMEM>>>(ath, atl, woh, wol,
                                                                hs, h2, H, NH * HD);
    // 5. RMSNorm 2
    rmsnorm_split_kernel<<<M, 256>>>(h2, n2w, xn2h, xn2l);
    // 6. fused MLP gate/up + SwiGLU (M-block fast)
    gemm_gu_silu_kernel<<<dim3(M / 64, IM / 64), 256, GEMM_DSMEM>>>(xn2h, xn2l, gh, gl);
    // 7. Down projection + residual -> x output
    gemm_mma_kernel<<<dim3(H / 128, M / 64), 256, GEMM_DSMEM>>>(gh, gl, wdh, wdl,
                                                                h2, out_x, H, IM);
}